// round 5
// baseline (speedup 1.0000x reference)
#include <cuda_runtime.h>
#include <cuda_bf16.h>
#include <math.h>

// ---------------------------------------------------------------------------
#define kD   256
#define kB   4
#define kS   8192
#define kNE  2048
#define kNC  512
#define kWIN 4
#define kM   (kB * kS)

#define S_SC       0.25f
#define SC_B       0.2f
#define SC_X       0.075f
#define EPSL       1e-5f
#define INV_SQRT_D 0.0625f
#define CAP        2048

#define OFF_SSTATE ((size_t)0)
#define OFF_SVAL   ((size_t)kB * kS * kD)
#define OFF_NCS    ((size_t)2 * kB * kS * kD)
#define OFF_NCV    (OFF_NCS + (size_t)kB * kNC * kD)

// ---------------------------------------------------------------------------
__device__ float g_scmat[(size_t)kB * kNC * kNC];
__device__ int   g_entR[(size_t)kB * kNC * CAP];
__device__ float g_entW[(size_t)kB * kNC * CAP];
__device__ int   g_cnt[kB * kNC];
__device__ float g_esum[kD];
__device__ int   g_is[4]; __device__ float g_ws[4];
__device__ int   g_ic[4]; __device__ float g_wc[4];
__device__ float g_ncs[(size_t)kB * kNC * kD];
__device__ float g_ncv[(size_t)kB * kNC * kD];

__device__ __nv_bfloat16 g_shi[(size_t)kM * kD];
__device__ __nv_bfloat16 g_slo[(size_t)kM * kD];
__device__ __nv_bfloat16 g_wth[(size_t)kNC * kD];
__device__ __nv_bfloat16 g_wtl[(size_t)kNC * kD];
__device__ float g_candV[(size_t)kM * 32];          // 8 slabs x 4 candidates
__device__ int   g_candI[(size_t)kM * 32];

__device__ __forceinline__ bool bet(float v, int i, float bv, int bi) {
    return (v > bv) || (v == bv && i < bi);
}

__device__ __forceinline__ float warpsum(float v) {
    #pragma unroll
    for (int off = 16; off > 0; off >>= 1) v += __shfl_xor_sync(0xffffffffu, v, off);
    return v;
}

__device__ __forceinline__ void ins4(float v, int i, float* tv, int* ti) {
    if (bet(v, i, tv[3], ti[3])) {
        tv[3] = v; ti[3] = i;
        #pragma unroll
        for (int q = 3; q > 0; q--) {
            if (bet(tv[q], ti[q], tv[q - 1], ti[q - 1])) {
                float fv = tv[q]; tv[q] = tv[q - 1]; tv[q - 1] = fv;
                int   fi = ti[q]; ti[q] = ti[q - 1]; ti[q - 1] = fi;
            } else break;
        }
    }
}

__device__ __forceinline__ void mma16816(float* c, const unsigned* a, const unsigned* b) {
    asm volatile(
        "mma.sync.aligned.m16n8k16.row.col.f32.bf16.bf16.f32 "
        "{%0,%1,%2,%3}, {%4,%5,%6,%7}, {%8,%9}, {%0,%1,%2,%3};"
        : "+f"(c[0]), "+f"(c[1]), "+f"(c[2]), "+f"(c[3])
        : "r"(a[0]), "r"(a[1]), "r"(a[2]), "r"(a[3]), "r"(b[0]), "r"(b[1]));
}

__device__ __forceinline__ void ldsm4(unsigned* r, const void* p) {
    unsigned a = (unsigned)__cvta_generic_to_shared(p);
    asm volatile("ldmatrix.sync.aligned.m8n8.x4.shared.b16 {%0,%1,%2,%3}, [%4];"
        : "=r"(r[0]), "=r"(r[1]), "=r"(r[2]), "=r"(r[3]) : "r"(a));
}

__device__ __forceinline__ void cpasync16(void* dst, const void* src) {
    unsigned sd = (unsigned)__cvta_generic_to_shared(dst);
    asm volatile("cp.async.cg.shared.global [%0], [%1], 16;" :: "r"(sd), "l"(src));
}

// ---------------------------------------------------------------------------
// K0: prep
// ---------------------------------------------------------------------------
__global__ __launch_bounds__(256) void k0_prep(
    const float* __restrict__ b_expand, const float* __restrict__ b_b2s,
    const float* __restrict__ b_comp,   const float* __restrict__ ln_b_c,
    const float* __restrict__ ln_g_e,   const float* __restrict__ ln_b_e)
{
    __shared__ float sv[256];  __shared__ int si[256];
    __shared__ float red[256];
    __shared__ float tv[4];    __shared__ int ti[4];
    __shared__ float we[4];    __shared__ int ie[4];
    int tid = threadIdx.x;

    for (int j = tid; j < kB * kNC; j += 256) g_cnt[j] = 0;

    auto top4 = [&](const float* x, int n) {
        for (int r = 0; r < 4; r++) {
            float bv = -INFINITY; int bi = 0x7fffffff;
            for (int j = tid; j < n; j += 256) {
                bool skip = false;
                for (int q = 0; q < r; q++) if (ti[q] == j) skip = true;
                float v = x[j];
                if (!skip && bet(v, j, bv, bi)) { bv = v; bi = j; }
            }
            sv[tid] = bv; si[tid] = bi; __syncthreads();
            for (int s = 128; s > 0; s >>= 1) {
                if (tid < s && bet(sv[tid + s], si[tid + s], sv[tid], si[tid])) {
                    sv[tid] = sv[tid + s]; si[tid] = si[tid + s];
                }
                __syncthreads();
            }
            if (tid == 0) { tv[r] = sv[0]; ti[r] = si[0]; }
            __syncthreads();
        }
    };
    auto softmax4 = [&](float* wout) {
        if (tid == 0) {
            float m = tv[0];
            float e0 = expf(tv[0] - m), e1 = expf(tv[1] - m);
            float e2 = expf(tv[2] - m), e3 = expf(tv[3] - m);
            float inv = 1.0f / (e0 + e1 + e2 + e3);
            wout[0] = e0 * inv; wout[1] = e1 * inv;
            wout[2] = e2 * inv; wout[3] = e3 * inv;
        }
        __syncthreads();
    };

    top4(b_expand, kNE); softmax4(we);
    if (tid < 4) ie[tid] = ti[tid];
    __syncthreads();
    top4(b_b2s, kS); softmax4(g_ws);
    if (tid < 4) g_is[tid] = ti[tid];
    __syncthreads();
    top4(b_comp, kNC); softmax4(g_wc);
    if (tid < 4) g_ic[tid] = ti[tid];
    __syncthreads();

    int d = tid;
    float cval = ln_b_c[d];
    float rowval[4];
    float dvE = 0.0f;
    #pragma unroll
    for (int j = 0; j < 4; j++) {
        rowval[j] = SC_B * (float)kNC * we[j] * cval;
        if (ie[j] < 4) dvE += rowval[j];
    }
    dvE *= 0.25f;
    float base = SC_B * dvE;

    auto bsum = [&](float x) -> float {
        red[tid] = x; __syncthreads();
        for (int s = 128; s > 0; s >>= 1) {
            if (tid < s) red[tid] += red[tid + s];
            __syncthreads();
        }
        float r = red[0]; __syncthreads(); return r;
    };
    float ge = ln_g_e[d], be = ln_b_e[d];
    auto LN_e = [&](float x) -> float {
        float m  = bsum(x) * (1.0f / kD);
        float dv = x - m;
        float var = bsum(dv * dv) * (1.0f / kD);
        return dv * rsqrtf(var + EPSL) * ge + be;
    };

    float other = LN_e(base);
    float esum = (float)(kNE - 4) * other;
    #pragma unroll
    for (int j = 0; j < 4; j++) esum += LN_e(rowval[j] + base);
    g_esum[d] = esum;
}

// ---------------------------------------------------------------------------
// K1: split W_s2b into transposed bf16 hi/lo
// ---------------------------------------------------------------------------
__global__ void k1_splitW(const float* __restrict__ W)
{
    __shared__ float tile[32][33];
    int n0 = blockIdx.x * 32, k0 = blockIdx.y * 32;
    int tx = threadIdx.x, ty = threadIdx.y;
    tile[ty][tx] = W[(size_t)(k0 + ty) * kNC + n0 + tx];
    __syncthreads();
    float x = tile[tx][ty];
    __nv_bfloat16 hi = __float2bfloat16(x);
    float lo = x - __bfloat162float(hi);
    g_wth[(size_t)(n0 + ty) * kD + k0 + tx] = hi;
    g_wtl[(size_t)(n0 + ty) * kD + k0 + tx] = __float2bfloat16(lo);
}

// ---------------------------------------------------------------------------
// K2: warp-per-row window prop (unchanged)
// ---------------------------------------------------------------------------
__global__ __launch_bounds__(256) void k2_window(
    const float* __restrict__ s_state, const float* __restrict__ s_val,
    const float* __restrict__ w_pair_s,
    const float* __restrict__ ln_g_s, const float* __restrict__ ln_b_s,
    float* __restrict__ out)
{
    int warp = threadIdx.x >> 5, lane = threadIdx.x & 31;
    int row = blockIdx.x * 8 + warp;
    int b = row >> 13, n = row & (kS - 1);
    const float4* st4 = (const float4*)(s_state + (size_t)b * kS * kD);
    const float4* vl4 = (const float4*)(s_val   + (size_t)b * kS * kD);
    int ci = lane * 2;

    float4 w0 = ((const float4*)w_pair_s)[ci];
    float4 w1 = ((const float4*)w_pair_s)[ci + 1];
    float4 s0a = st4[(size_t)n * 64 + ci];
    float4 s0b = st4[(size_t)n * 64 + ci + 1];
    float4 q0, q1;
    q0.x = s0a.x * w0.x; q0.y = s0a.y * w0.y; q0.z = s0a.z * w0.z; q0.w = s0a.w * w0.w;
    q1.x = s0b.x * w1.x; q1.y = s0b.y * w1.y; q1.z = s0b.z * w1.z; q1.w = s0b.w * w1.w;

    float sc[9];
    #pragma unroll
    for (int k = 0; k < 9; k++) {
        int j = n + k - kWIN;
        bool valid = ((unsigned)j < (unsigned)kS);
        int jc = min(max(j, 0), kS - 1);
        float4 na = st4[(size_t)jc * 64 + ci];
        float4 nb = st4[(size_t)jc * 64 + ci + 1];
        float p = q0.x * na.x + q0.y * na.y + q0.z * na.z + q0.w * na.w
                + q1.x * nb.x + q1.y * nb.y + q1.z * nb.z + q1.w * nb.w;
        p = warpsum(p);
        sc[k] = valid ? p * INV_SQRT_D : -1e30f;
    }
    float mx = sc[0];
    #pragma unroll
    for (int k = 1; k < 9; k++) mx = fmaxf(mx, sc[k]);
    float asum = 0.0f;
    #pragma unroll
    for (int k = 0; k < 9; k++) { sc[k] = expf(sc[k] - mx); asum += sc[k]; }
    float ainv = 1.0f / asum;

    float4 ds0 = {0,0,0,0}, ds1 = {0,0,0,0}, dv0 = {0,0,0,0}, dv1 = {0,0,0,0};
    #pragma unroll
    for (int k = 0; k < 9; k++) {
        int j = n + k - kWIN;
        int jc = min(max(j, 0), kS - 1);
        float a = sc[k] * ainv;
        float4 na = st4[(size_t)jc * 64 + ci];
        float4 nb = st4[(size_t)jc * 64 + ci + 1];
        float4 va = vl4[(size_t)jc * 64 + ci];
        float4 vb = vl4[(size_t)jc * 64 + ci + 1];
        ds0.x += a * na.x; ds0.y += a * na.y; ds0.z += a * na.z; ds0.w += a * na.w;
        ds1.x += a * nb.x; ds1.y += a * nb.y; ds1.z += a * nb.z; ds1.w += a * nb.w;
        dv0.x += a * va.x; dv0.y += a * va.y; dv0.z += a * va.z; dv0.w += a * va.w;
        dv1.x += a * vb.x; dv1.y += a * vb.y; dv1.z += a * vb.z; dv1.w += a * vb.w;
    }

    float so[8];
    so[0] = tanhf(tanhf(s0a.x + S_SC * ds0.x));
    so[1] = tanhf(tanhf(s0a.y + S_SC * ds0.y));
    so[2] = tanhf(tanhf(s0a.z + S_SC * ds0.z));
    so[3] = tanhf(tanhf(s0a.w + S_SC * ds0.w));
    so[4] = tanhf(tanhf(s0b.x + S_SC * ds1.x));
    so[5] = tanhf(tanhf(s0b.y + S_SC * ds1.y));
    so[6] = tanhf(tanhf(s0b.z + S_SC * ds1.z));
    so[7] = tanhf(tanhf(s0b.w + S_SC * ds1.w));

    float4* outS = (float4*)(out + OFF_SSTATE);
    outS[(size_t)row * 64 + ci]     = make_float4(so[0], so[1], so[2], so[3]);
    outS[(size_t)row * 64 + ci + 1] = make_float4(so[4], so[5], so[6], so[7]);

    uint4 hw, lw;
    unsigned* hwp = (unsigned*)&hw; unsigned* lwp = (unsigned*)&lw;
    #pragma unroll
    for (int i = 0; i < 4; i++) {
        float a = so[2 * i], c = so[2 * i + 1];
        __nv_bfloat16 ha = __float2bfloat16(a), hc = __float2bfloat16(c);
        hwp[i] = ((unsigned)__bfloat16_as_ushort(hc) << 16) | __bfloat16_as_ushort(ha);
        float la = a - __bfloat162float(ha), lc = c - __bfloat162float(hc);
        __nv_bfloat16 bla = __float2bfloat16(la), blc = __float2bfloat16(lc);
        lwp[i] = ((unsigned)__bfloat16_as_ushort(blc) << 16) | __bfloat16_as_ushort(bla);
    }
    *(uint4*)&g_shi[(size_t)row * kD + lane * 8] = hw;
    *(uint4*)&g_slo[(size_t)row * kD + lane * 8] = lw;

    float4 va0 = vl4[(size_t)n * 64 + ci];
    float4 va1 = vl4[(size_t)n * 64 + ci + 1];
    float v[8];
    v[0] = va0.x + S_SC * dv0.x; v[1] = va0.y + S_SC * dv0.y;
    v[2] = va0.z + S_SC * dv0.z; v[3] = va0.w + S_SC * dv0.w;
    v[4] = va1.x + S_SC * dv1.x; v[5] = va1.y + S_SC * dv1.y;
    v[6] = va1.z + S_SC * dv1.z; v[7] = va1.w + S_SC * dv1.w;

    float4 g0 = ((const float4*)ln_g_s)[ci], g1 = ((const float4*)ln_g_s)[ci + 1];
    float4 b0v = ((const float4*)ln_b_s)[ci], b1v = ((const float4*)ln_b_s)[ci + 1];
    float gs[8] = {g0.x, g0.y, g0.z, g0.w, g1.x, g1.y, g1.z, g1.w};
    float bs[8] = {b0v.x, b0v.y, b0v.z, b0v.w, b1v.x, b1v.y, b1v.z, b1v.w};

    float s8 = 0.0f;
    #pragma unroll
    for (int i = 0; i < 8; i++) s8 += v[i];
    float mean = warpsum(s8) * (1.0f / kD);
    float vs = 0.0f;
    #pragma unroll
    for (int i = 0; i < 8; i++) { v[i] -= mean; vs += v[i] * v[i]; }
    float rstd = rsqrtf(warpsum(vs) * (1.0f / kD) + EPSL);
    #pragma unroll
    for (int i = 0; i < 8; i++) v[i] = v[i] * rstd * gs[i] + bs[i];

    bool hit = false; float wj = 0.0f;
    #pragma unroll
    for (int j = 0; j < 4; j++)
        if (g_is[j] == n) { hit = true; wj = g_ws[j]; }
    if (hit) {
        float4 e0 = ((const float4*)g_esum)[ci], e1 = ((const float4*)g_esum)[ci + 1];
        float es[8] = {e0.x, e0.y, e0.z, e0.w, e1.x, e1.y, e1.z, e1.w};
        #pragma unroll
        for (int i = 0; i < 8; i++) v[i] += SC_X * wj * es[i];
    }

    s8 = 0.0f;
    #pragma unroll
    for (int i = 0; i < 8; i++) s8 += v[i];
    mean = warpsum(s8) * (1.0f / kD);
    vs = 0.0f;
    #pragma unroll
    for (int i = 0; i < 8; i++) { v[i] -= mean; vs += v[i] * v[i]; }
    rstd = rsqrtf(warpsum(vs) * (1.0f / kD) + EPSL);
    float4* outV = (float4*)(out + OFF_SVAL);
    outV[(size_t)row * 64 + ci] =
        make_float4(v[0] * rstd * gs[0] + bs[0], v[1] * rstd * gs[1] + bs[1],
                    v[2] * rstd * gs[2] + bs[2], v[3] * rstd * gs[3] + bs[3]);
    outV[(size_t)row * 64 + ci + 1] =
        make_float4(v[4] * rstd * gs[4] + bs[4], v[5] * rstd * gs[5] + bs[5],
                    v[6] * rstd * gs[6] + bs[6], v[7] * rstd * gs[7] + bs[7]);
}

// ---------------------------------------------------------------------------
// K3a: split-bf16 tensor-core GEMM. CTA tile 128x64, 8 warps (4m x 2n),
// warp tile 32x32. 3-stage cp.async ring + register-level fragment
// double-buffering (LDSM for chunk k+1 issued before MMAs of chunk k).
// Dynamic smem: 3 stages x (Ah/Al 128x24 + Bh/Bl 64x24) bf16 = 55296 B.
// ---------------------------------------------------------------------------
#define KC   16
#define SROW 24
#define STGE (384 * SROW)            // elems per stage (Ah+Al+Bh+Bl)
#define OA_L (128 * SROW)            // Al offset within stage
#define OB_H (2 * 128 * SROW)        // Bh offset
#define OB_L (OB_H + 64 * SROW)      // Bl offset
#define NCHUNK (kD / KC)             // 16

__global__ __launch_bounds__(256, 2) void k3a_gemm(const float* __restrict__ bias)
{
    extern __shared__ __align__(16) __nv_bfloat16 smd[];
    int tid = threadIdx.x;
    int warp = tid >> 5, lane = tid & 31;
    int mw = warp & 3, nw = warp >> 2;
    int g = lane >> 2, t = lane & 3;
    int m0 = blockIdx.y * 128, n0 = blockIdx.x * 64;

    // cp.async mapping: A rows by tid/2, B rows by (tid&127)/2
    int arow = tid >> 1, ahalf = tid & 1;
    int brow = (tid & 127) >> 1;
    const __nv_bfloat16* srcAh = g_shi + (size_t)(m0 + arow) * kD + ahalf * 8;
    const __nv_bfloat16* srcAl = g_slo + (size_t)(m0 + arow) * kD + ahalf * 8;
    const __nv_bfloat16* srcB  = (tid < 128 ? g_wth : g_wtl) + (size_t)(n0 + brow) * kD + ahalf * 8;
    int dA = arow * SROW + ahalf * 8;
    int dB = (tid < 128 ? OB_H : OB_L) + brow * SROW + ahalf * 8;

    // ldmatrix addressing
    int a_r  = mw * 32 + (lane & 15);            // + mt*16
    int a_kh = (lane >> 4) * 8;
    int b_r  = nw * 32 + (lane & 7) + ((lane >> 4) & 1) * 8;   // + p*16
    int b_kh = ((lane >> 3) & 1) * 8;

    float acc[2][4][4];
    #pragma unroll
    for (int i = 0; i < 2; i++)
        #pragma unroll
        for (int j = 0; j < 4; j++)
            #pragma unroll
            for (int q = 0; q < 4; q++) acc[i][j][q] = 0.0f;

    unsigned ah[2][2][4], al[2][2][4], bh[2][2][4], bl[2][2][4];

    auto load_stage = [&](int st, int kc) {
        int k0 = kc * KC;
        __nv_bfloat16* base = smd + st * STGE;
        cpasync16(base + dA,        srcAh + k0);
        cpasync16(base + OA_L + dA, srcAl + k0);
        cpasync16(base + dB,        srcB  + k0);
    };
    auto ldsm_frags = [&](int st, int buf) {
        __nv_bfloat16* base = smd + st * STGE;
        #pragma unroll
        for (int mt = 0; mt < 2; mt++) {
            ldsm4(ah[buf][mt], base + (a_r + mt * 16) * SROW + a_kh);
            ldsm4(al[buf][mt], base + OA_L + (a_r + mt * 16) * SROW + a_kh);
        }
        #pragma unroll
        for (int p = 0; p < 2; p++) {
            ldsm4(bh[buf][p], base + OB_H + (b_r + p * 16) * SROW + b_kh);
            ldsm4(bl[buf][p], base + OB_L + (b_r + p * 16) * SROW + b_kh);
        }
    };

    load_stage(0, 0); asm volatile("cp.async.commit_group;");
    load_stage(1, 1); asm volatile("cp.async.commit_group;");
    load_stage(2, 2); asm volatile("cp.async.commit_group;");
    asm volatile("cp.async.wait_group 2;");
    __syncthreads();
    ldsm_frags(0, 0);

    int cur = 0;
    #pragma unroll 4
    for (int ks = 0; ks < NCHUNK; ks++) {
        int nxt = cur ^ 1;
        if (ks < NCHUNK - 1) {
            asm volatile("cp.async.wait_group 1;");
            __syncthreads();
            if (ks + 3 < NCHUNK) load_stage((ks + 3) % 3, ks + 3);
            asm volatile("cp.async.commit_group;");
            ldsm_frags((ks + 1) % 3, nxt);
        }
        #pragma unroll
        for (int p = 0; p < 2; p++) {
            #pragma unroll
            for (int half = 0; half < 2; half++) {
                int nt = p * 2 + half;
                unsigned* bhp = bh[cur][p] + half * 2;
                unsigned* blp = bl[cur][p] + half * 2;
                #pragma unroll
                for (int mt = 0; mt < 2; mt++) {
                    mma16816(acc[mt][nt], ah[cur][mt], bhp);
                    mma16816(acc[mt][nt], ah[cur][mt], blp);
                    mma16816(acc[mt][nt], al[cur][mt], bhp);
                }
            }
        }
        cur = nxt;
    }

    float bcol[8];
    #pragma unroll
    for (int nt = 0; nt < 4; nt++) {
        int c = n0 + nw * 32 + nt * 8 + 2 * t;
        bcol[nt * 2]     = bias[c];
        bcol[nt * 2 + 1] = bias[c + 1];
    }

    __syncthreads();                 // all warps done with smem tiles
    float* svv = (float*)&smd[0];
    int*   sii = (int*)(((char*)&smd[0]) + 4096);

    #pragma unroll
    for (int mt = 0; mt < 2; mt++) {
        #pragma unroll
        for (int h = 0; h < 2; h++) {
            float tv[4] = {-INFINITY, -INFINITY, -INFINITY, -INFINITY};
            int   ti[4] = {0x7fffffff, 0x7fffffff, 0x7fffffff, 0x7fffffff};
            #pragma unroll
            for (int nt = 0; nt < 4; nt++) {
                #pragma unroll
                for (int e = 0; e < 2; e++) {
                    float val = acc[mt][nt][h * 2 + e] + bcol[nt * 2 + e];
                    int col = n0 + nw * 32 + nt * 8 + 2 * t + e;
                    ins4(val, col, tv, ti);
                }
            }
            #pragma unroll
            for (int msk = 1; msk <= 2; msk <<= 1) {
                float pv[4]; int pi[4];
                #pragma unroll
                for (int j = 0; j < 4; j++) {
                    pv[j] = __shfl_xor_sync(0xffffffffu, tv[j], msk);
                    pi[j] = __shfl_xor_sync(0xffffffffu, ti[j], msk);
                }
                #pragma unroll
                for (int j = 0; j < 4; j++) ins4(pv[j], pi[j], tv, ti);
            }
            if (t == 0) {
                int lrow = mw * 32 + mt * 16 + h * 8 + g;
                #pragma unroll
                for (int j = 0; j < 4; j++) {
                    svv[(lrow * 2 + nw) * 4 + j] = tv[j];
                    sii[(lrow * 2 + nw) * 4 + j] = ti[j];
                }
            }
        }
    }
    __syncthreads();
    if (tid < 128) {
        float tv[4]; int ti[4];
        #pragma unroll
        for (int j = 0; j < 4; j++) { tv[j] = svv[(tid * 2) * 4 + j]; ti[j] = sii[(tid * 2) * 4 + j]; }
        #pragma unroll
        for (int j = 0; j < 4; j++) ins4(svv[(tid * 2 + 1) * 4 + j], sii[(tid * 2 + 1) * 4 + j], tv, ti);
        size_t base = ((size_t)(m0 + tid) * 8 + blockIdx.x) * 4;
        #pragma unroll
        for (int j = 0; j < 4; j++) { g_candV[base + j] = tv[j]; g_candI[base + j] = ti[j]; }
    }
}

// ---------------------------------------------------------------------------
// K3b: merge 32 candidates per row -> global top4, softmax, bucket push
// ---------------------------------------------------------------------------
__global__ __launch_bounds__(256) void k3b_merge()
{
    int warp = threadIdx.x >> 5, lane = threadIdx.x & 31;
    int row = blockIdx.x * 8 + warp;
    int b = row >> 13;
    float v = g_candV[(size_t)row * 32 + lane];
    int  ix = g_candI[(size_t)row * 32 + lane];

    float topv[4]; int topi[4];
    #pragma unroll
    for (int r = 0; r < 4; r++) {
        float mv = v; int mi = ix;
        #pragma unroll
        for (int off = 16; off > 0; off >>= 1) {
            float ov = __shfl_xor_sync(0xffffffffu, mv, off);
            int   oi = __shfl_xor_sync(0xffffffffu, mi, off);
            if (bet(ov, oi, mv, mi)) { mv = ov; mi = oi; }
        }
        topv[r] = mv; topi[r] = mi;
        if (ix == mi) v = -INFINITY;
    }
    float mx = topv[0];
    float e0 = expf(topv[0] - mx), e1 = expf(topv[1] - mx);
    float e2 = expf(topv[2] - mx), e3 = expf(topv[3] - mx);
    float inv = 1.0f / (e0 + e1 + e2 + e3);
    if (lane < 4) {
        float ej = (lane == 0) ? e0 : (lane == 1) ? e1 : (lane == 2) ? e2 : e3;
        float wgt = SC_X * ej * inv;
        int bt = b * kNC + topi[lane];
        int pos = atomicAdd(&g_cnt[bt], 1);
        if (pos < CAP) {
            g_entR[(size_t)bt * CAP + pos] = row;
            g_entW[(size_t)bt * CAP + pos] = wgt;
        }
    }
}

// ---------------------------------------------------------------------------
// K3c: per-(b,target) gather-sum
// ---------------------------------------------------------------------------
__global__ __launch_bounds__(256) void k3c_gather(
    const float* __restrict__ out, const float* __restrict__ ln_b_c)
{
    int bt = blockIdx.x;
    int t = bt & (kNC - 1);
    int sub = threadIdx.x >> 6, c = threadIdx.x & 63;
    int n = min(g_cnt[bt], CAP);
    const float4* ssf = (const float4*)(out + OFF_SSTATE);
    const float4* svf = (const float4*)(out + OFF_SVAL);
    float4 aS = {0,0,0,0}, aV = {0,0,0,0};
    for (int i = sub; i < n; i += 4) {
        int r   = g_entR[(size_t)bt * CAP + i];
        float w = g_entW[(size_t)bt * CAP + i];
        float4 s = ssf[(size_t)r * 64 + c];
        float4 vv = svf[(size_t)r * 64 + c];
        aS.x += w * s.x;  aS.y += w * s.y;  aS.z += w * s.z;  aS.w += w * s.w;
        aV.x += w * vv.x; aV.y += w * vv.y; aV.z += w * vv.z; aV.w += w * vv.w;
    }
    __shared__ float4 shS[4][64], shV[4][64];
    shS[sub][c] = aS; shV[sub][c] = aV;
    __syncthreads();
    if (sub == 0) {
        float4 S = shS[0][c], V = shV[0][c];
        #pragma unroll
        for (int q = 1; q < 4; q++) {
            float4 s2 = shS[q][c], v2 = shV[q][c];
            S.x += s2.x; S.y += s2.y; S.z += s2.z; S.w += s2.w;
            V.x += v2.x; V.y += v2.y; V.z += v2.z; V.w += v2.w;
        }
        ((float4*)g_ncs)[(size_t)bt * 64 + c] = S;
        float4 nb = ((const float4*)ln_b_c)[c];
        V.x += nb.x; V.y += nb.y; V.z += nb.z; V.w += nb.w;
        #pragma unroll
        for (int j = 0; j < 4; j++)
            if (g_ic[j] == t) {
                float w = SC_B * g_wc[j];
                float4 es = ((const float4*)g_esum)[c];
                V.x += w * es.x; V.y += w * es.y; V.z += w * es.z; V.w += w * es.w;
            }
        ((float4*)g_ncv)[(size_t)bt * 64 + c] = V;
    }
}

// ---------------------------------------------------------------------------
// K4a: per-batch scores
// ---------------------------------------------------------------------------
__global__ __launch_bounds__(256) void k4a_scores(const float* __restrict__ wpc)
{
    int bb = blockIdx.z;
    int m0 = blockIdx.y * 64;
    int n0 = blockIdx.x * 64;
    const float* ncs = g_ncs + (size_t)bb * kNC * kD;
    __shared__ float As[16][64 + 4];
    __shared__ float Bs[16][64 + 4];
    int tid = threadIdx.x;
    int ty = tid / 16, tx = tid % 16;
    float acc[4][4] = {};
    int lrow = tid / 4;
    int lk = (tid % 4) * 4;
    for (int k0 = 0; k0 < kD; k0 += 16) {
        float4 av = *(const float4*)&ncs[(size_t)(m0 + lrow) * kD + k0 + lk];
        float4 bv = *(const float4*)&ncs[(size_t)(n0 + lrow) * kD + k0 + lk];
        float4 wv = *(const float4*)&wpc[k0 + lk];
        As[lk + 0][lrow] = av.x * wv.x; As[lk + 1][lrow] = av.y * wv.y;
        As[lk + 2][lrow] = av.z * wv.z; As[lk + 3][lrow] = av.w * wv.w;
        Bs[lk + 0][lrow] = bv.x; Bs[lk + 1][lrow] = bv.y;
        Bs[lk + 2][lrow] = bv.z; Bs[lk + 3][lrow] = bv.w;
        __syncthreads();
        #pragma unroll
        for (int kk = 0; kk < 16; kk++) {
            float ar[4], br[4];
            #pragma unroll
            for (int i = 0; i < 4; i++) ar[i] = As[kk][ty * 4 + i];
            #pragma unroll
            for (int j = 0; j < 4; j++) br[j] = Bs[kk][tx * 4 + j];
            #pragma unroll
            for (int i = 0; i < 4; i++)
                #pragma unroll
                for (int j = 0; j < 4; j++)
                    acc[i][j] += ar[i] * br[j];
        }
        __syncthreads();
    }
    #pragma unroll
    for (int i = 0; i < 4; i++)
        #pragma unroll
        for (int j = 0; j < 4; j++)
            g_scmat[(size_t)bb * kNC * kNC + (size_t)(m0 + ty * 4 + i) * kNC + (n0 + tx * 4 + j)] =
                acc[i][j] * INV_SQRT_D;
}

// ---------------------------------------------------------------------------
// K4b: per-(b,n) top-4, softmax, gather, tanh/LN finalize
// ---------------------------------------------------------------------------
__global__ __launch_bounds__(256) void k4b_final(
    const float* __restrict__ ln_g_c, const float* __restrict__ ln_b_c,
    float* __restrict__ out)
{
    int bn = blockIdx.x;
    int bb = bn / kNC;
    int d = threadIdx.x;
    const float* sc = g_scmat + (size_t)bn * kNC;
    __shared__ float sv[256]; __shared__ int si[256];
    __shared__ float red[256];
    __shared__ float topw[4]; __shared__ int topidx[4];

    float v0 = sc[d], v1 = sc[d + 256];
    bool t0 = false, t1 = false;
    for (int r = 0; r < 4; r++) {
        float bv = -INFINITY; int bi = 0x7fffffff;
        if (!t0) { bv = v0; bi = d; }
        if (!t1 && bet(v1, d + 256, bv, bi)) { bv = v1; bi = d + 256; }
        sv[d] = bv; si[d] = bi; __syncthreads();
        for (int s = 128; s > 0; s >>= 1) {
            if (d < s && bet(sv[d + s], si[d + s], sv[d], si[d])) {
                sv[d] = sv[d + s]; si[d] = si[d + s];
            }
            __syncthreads();
        }
        if (d == 0) { topw[r] = sv[0]; topidx[r] = si[0]; }
        __syncthreads();
        int widx = topidx[r];
        if (widx == d) t0 = true;
        if (widx == d + 256) t1 = true;
    }

    float mx = topw[0];
    float e[4]; float esum = 0.0f;
    #pragma unroll
    for (int j = 0; j < 4; j++) { e[j] = expf(topw[j] - mx); esum += e[j]; }
    float inv = 1.0f / esum;

    const float* ncsB = g_ncs + (size_t)bb * kNC * kD;
    const float* ncvB = g_ncv + (size_t)bb * kNC * kD;
    float ds = 0.0f, dv = 0.0f;
    #pragma unroll
    for (int j = 0; j < 4; j++) {
        int m = topidx[j];
        float a = e[j] * inv;
        ds += a * ncsB[(size_t)m * kD + d];
        dv += a * ncvB[(size_t)m * kD + d];
    }
    float spre = g_ncs[(size_t)bn * kD + d];
    float vpre = g_ncv[(size_t)bn * kD + d];

    out[OFF_NCS + (size_t)bn * kD + d] = tanhf(spre + SC_B * ds);

    auto bsum = [&](float x) -> float {
        red[d] = x; __syncthreads();
        for (int s = 128; s > 0; s >>= 1) {
            if (d < s) red[d] += red[d + s];
            __syncthreads();
        }
        float r = red[0]; __syncthreads(); return r;
    };
    float x = vpre + SC_B * dv;
    float m = bsum(x) * (1.0f / kD);
    float xd = x - m;
    float var = bsum(xd * xd) * (1.0f / kD);
    out[OFF_NCV + (size_t)bn * kD + d] = xd * rsqrtf(var + EPSL) * ln_g_c[d] + ln_b_c[d];
}

// ---------------------------------------------------------------------------
extern "C" void kernel_launch(void* const* d_in, const int* in_sizes, int n_in,
                              void* d_out, int out_size) {
    const float* s_state  = (const float*)d_in[0];
    const float* s_val    = (const float*)d_in[1];
    const float* w_pair_s = (const float*)d_in[2];
    const float* w_pair_c = (const float*)d_in[4];
    const float* b_expand = (const float*)d_in[6];
    const float* b_b2s    = (const float*)d_in[8];
    const float* b_comp   = (const float*)d_in[10];
    const float* W_s2b    = (const float*)d_in[11];
    const float* b_s2b    = (const float*)d_in[12];
    const float* ln_g_s   = (const float*)d_in[13];
    const float* ln_b_s   = (const float*)d_in[14];
    const float* ln_g_e   = (const float*)d_in[15];
    const float* ln_b_e   = (const float*)d_in[16];
    const float* ln_g_c   = (const float*)d_in[17];
    const float* ln_b_c   = (const float*)d_in[18];
    float* out = (float*)d_out;

    static int smem_set = 0;
    if (!smem_set) {
        cudaFuncSetAttribute(k3a_gemm, cudaFuncAttributeMaxDynamicSharedMemorySize,
                             3 * STGE * (int)sizeof(__nv_bfloat16));
        smem_set = 1;
    }

    k0_prep<<<1, 256>>>(b_expand, b_b2s, b_comp, ln_b_c, ln_g_e, ln_b_e);
    k1_splitW<<<dim3(kNC / 32, kD / 32), dim3(32, 32)>>>(W_s2b);
    k2_window<<<kM / 8, 256>>>(s_state, s_val, w_pair_s, ln_g_s, ln_b_s, out);
    k3a_gemm<<<dim3(kNC / 64, kM / 128), 256, 3 * STGE * sizeof(__nv_bfloat16)>>>(b_s2b);
    k3b_merge<<<kM / 8, 256>>>();
    k3c_gather<<<kB * kNC, 256>>>(out, ln_b_c);
    k4a_scores<<<dim3(kNC / 64, kNC / 64, kB), 256>>>(w_pair_c);
    k4b_final<<<kB * kNC, 256>>>(ln_g_c, ln_b_c, out);
}

// round 10
// speedup vs baseline: 1.0371x; 1.0371x over previous
#include <cuda_runtime.h>
#include <cuda_bf16.h>
#include <math.h>
#include <cstdint>

// ---------------------------------------------------------------------------
#define kD   256
#define kB   4
#define kS   8192
#define kNE  2048
#define kNC  512
#define kWIN 4
#define kM   (kB * kS)

#define S_SC       0.25f
#define SC_B       0.2f
#define SC_X       0.075f
#define EPSL       1e-5f
#define INV_SQRT_D 0.0625f
#define CAP        2048

#define OFF_SSTATE ((size_t)0)
#define OFF_SVAL   ((size_t)kB * kS * kD)
#define OFF_NCS    ((size_t)2 * kB * kS * kD)
#define OFF_NCV    (OFF_NCS + (size_t)kB * kNC * kD)

// ---------------------------------------------------------------------------
__device__ float g_scmat[(size_t)kB * kNC * kNC];
__device__ int   g_entR[(size_t)kB * kNC * CAP];
__device__ float g_entW[(size_t)kB * kNC * CAP];
__device__ int   g_cnt[kB * kNC];
__device__ float g_esum[kD];
__device__ int   g_is[4]; __device__ float g_ws[4];
__device__ int   g_ic[4]; __device__ float g_wc[4];
__device__ float g_ncs[(size_t)kB * kNC * kD];
__device__ float g_ncv[(size_t)kB * kNC * kD];

__device__ __nv_bfloat16 g_shi[(size_t)kM * kD];    // bf16 of s_state_final
__device__ __nv_bfloat16 g_wth[(size_t)kNC * kD];   // W_s2b^T bf16 [512][256]
__device__ float         g_wtf[(size_t)kNC * kD];   // W_s2b^T fp32 [512][256]
__device__ float g_candV[(size_t)kM * 16];          // 4 slabs x 4 candidates
__device__ int   g_candI[(size_t)kM * 16];

__device__ __forceinline__ bool bet(float v, int i, float bv, int bi) {
    return (v > bv) || (v == bv && i < bi);
}

__device__ __forceinline__ float warpsum(float v) {
    #pragma unroll
    for (int off = 16; off > 0; off >>= 1) v += __shfl_xor_sync(0xffffffffu, v, off);
    return v;
}

__device__ __forceinline__ void ins4(float v, int i, float* tv, int* ti) {
    if (bet(v, i, tv[3], ti[3])) {
        tv[3] = v; ti[3] = i;
        #pragma unroll
        for (int q = 3; q > 0; q--) {
            if (bet(tv[q], ti[q], tv[q - 1], ti[q - 1])) {
                float fv = tv[q]; tv[q] = tv[q - 1]; tv[q - 1] = fv;
                int   fi = ti[q]; ti[q] = ti[q - 1]; ti[q - 1] = fi;
            } else break;
        }
    }
}

__device__ __forceinline__ void mma16816(float* c, const unsigned* a, const unsigned* b) {
    asm volatile(
        "mma.sync.aligned.m16n8k16.row.col.f32.bf16.bf16.f32 "
        "{%0,%1,%2,%3}, {%4,%5,%6,%7}, {%8,%9}, {%0,%1,%2,%3};"
        : "+f"(c[0]), "+f"(c[1]), "+f"(c[2]), "+f"(c[3])
        : "r"(a[0]), "r"(a[1]), "r"(a[2]), "r"(a[3]), "r"(b[0]), "r"(b[1]));
}

__device__ __forceinline__ void ldsm4(unsigned* r, const void* p) {
    unsigned a = (unsigned)__cvta_generic_to_shared(p);
    asm volatile("ldmatrix.sync.aligned.m8n8.x4.shared.b16 {%0,%1,%2,%3}, [%4];"
        : "=r"(r[0]), "=r"(r[1]), "=r"(r[2]), "=r"(r[3]) : "r"(a));
}

__device__ __forceinline__ void cpasync16(void* dst, const void* src) {
    unsigned sd = (unsigned)__cvta_generic_to_shared(dst);
    asm volatile("cp.async.cg.shared.global [%0], [%1], 16;" :: "r"(sd), "l"(src));
}

// ---------------------------------------------------------------------------
// K0: prep (top4 of biases, collapsed e_val algebra, zero counters)
// ---------------------------------------------------------------------------
__global__ __launch_bounds__(256) void k0_prep(
    const float* __restrict__ b_expand, const float* __restrict__ b_b2s,
    const float* __restrict__ b_comp,   const float* __restrict__ ln_b_c,
    const float* __restrict__ ln_g_e,   const float* __restrict__ ln_b_e)
{
    __shared__ float sv[256];  __shared__ int si[256];
    __shared__ float red[256];
    __shared__ float tv[4];    __shared__ int ti[4];
    __shared__ float we[4];    __shared__ int ie[4];
    int tid = threadIdx.x;

    for (int j = tid; j < kB * kNC; j += 256) g_cnt[j] = 0;

    auto top4 = [&](const float* x, int n) {
        for (int r = 0; r < 4; r++) {
            float bv = -INFINITY; int bi = 0x7fffffff;
            for (int j = tid; j < n; j += 256) {
                bool skip = false;
                for (int q = 0; q < r; q++) if (ti[q] == j) skip = true;
                float v = x[j];
                if (!skip && bet(v, j, bv, bi)) { bv = v; bi = j; }
            }
            sv[tid] = bv; si[tid] = bi; __syncthreads();
            for (int s = 128; s > 0; s >>= 1) {
                if (tid < s && bet(sv[tid + s], si[tid + s], sv[tid], si[tid])) {
                    sv[tid] = sv[tid + s]; si[tid] = si[tid + s];
                }
                __syncthreads();
            }
            if (tid == 0) { tv[r] = sv[0]; ti[r] = si[0]; }
            __syncthreads();
        }
    };
    auto softmax4 = [&](float* wout) {
        if (tid == 0) {
            float m = tv[0];
            float e0 = expf(tv[0] - m), e1 = expf(tv[1] - m);
            float e2 = expf(tv[2] - m), e3 = expf(tv[3] - m);
            float inv = 1.0f / (e0 + e1 + e2 + e3);
            wout[0] = e0 * inv; wout[1] = e1 * inv;
            wout[2] = e2 * inv; wout[3] = e3 * inv;
        }
        __syncthreads();
    };

    top4(b_expand, kNE); softmax4(we);
    if (tid < 4) ie[tid] = ti[tid];
    __syncthreads();
    top4(b_b2s, kS); softmax4(g_ws);
    if (tid < 4) g_is[tid] = ti[tid];
    __syncthreads();
    top4(b_comp, kNC); softmax4(g_wc);
    if (tid < 4) g_ic[tid] = ti[tid];
    __syncthreads();

    int d = tid;
    float cval = ln_b_c[d];
    float rowval[4];
    float dvE = 0.0f;
    #pragma unroll
    for (int j = 0; j < 4; j++) {
        rowval[j] = SC_B * (float)kNC * we[j] * cval;
        if (ie[j] < 4) dvE += rowval[j];
    }
    dvE *= 0.25f;
    float base = SC_B * dvE;

    auto bsum = [&](float x) -> float {
        red[tid] = x; __syncthreads();
        for (int s = 128; s > 0; s >>= 1) {
            if (tid < s) red[tid] += red[tid + s];
            __syncthreads();
        }
        float r = red[0]; __syncthreads(); return r;
    };
    float ge = ln_g_e[d], be = ln_b_e[d];
    auto LN_e = [&](float x) -> float {
        float m  = bsum(x) * (1.0f / kD);
        float dv = x - m;
        float var = bsum(dv * dv) * (1.0f / kD);
        return dv * rsqrtf(var + EPSL) * ge + be;
    };

    float other = LN_e(base);
    float esum = (float)(kNE - 4) * other;
    #pragma unroll
    for (int j = 0; j < 4; j++) esum += LN_e(rowval[j] + base);
    g_esum[d] = esum;
}

// ---------------------------------------------------------------------------
// K1: W_s2b -> transposed bf16 [512 n][256 k] + transposed fp32 copy
// ---------------------------------------------------------------------------
__global__ void k1_splitW(const float* __restrict__ W)
{
    __shared__ float tile[32][33];
    int n0 = blockIdx.x * 32, k0 = blockIdx.y * 32;
    int tx = threadIdx.x, ty = threadIdx.y;
    tile[ty][tx] = W[(size_t)(k0 + ty) * kNC + n0 + tx];
    __syncthreads();
    float x = tile[tx][ty];                    // W[k0+tx][n0+ty]
    g_wth[(size_t)(n0 + ty) * kD + k0 + tx] = __float2bfloat16(x);
    g_wtf[(size_t)(n0 + ty) * kD + k0 + tx] = x;
}

// ---------------------------------------------------------------------------
// K2: warp-per-row window prop + double tanh + double LN; emits bf16 of state
// ---------------------------------------------------------------------------
__global__ __launch_bounds__(256) void k2_window(
    const float* __restrict__ s_state, const float* __restrict__ s_val,
    const float* __restrict__ w_pair_s,
    const float* __restrict__ ln_g_s, const float* __restrict__ ln_b_s,
    float* __restrict__ out)
{
    int warp = threadIdx.x >> 5, lane = threadIdx.x & 31;
    int row = blockIdx.x * 8 + warp;
    int b = row >> 13, n = row & (kS - 1);
    const float4* st4 = (const float4*)(s_state + (size_t)b * kS * kD);
    const float4* vl4 = (const float4*)(s_val   + (size_t)b * kS * kD);
    int ci = lane * 2;

    float4 w0 = ((const float4*)w_pair_s)[ci];
    float4 w1 = ((const float4*)w_pair_s)[ci + 1];
    float4 s0a = st4[(size_t)n * 64 + ci];
    float4 s0b = st4[(size_t)n * 64 + ci + 1];
    float4 q0, q1;
    q0.x = s0a.x * w0.x; q0.y = s0a.y * w0.y; q0.z = s0a.z * w0.z; q0.w = s0a.w * w0.w;
    q1.x = s0b.x * w1.x; q1.y = s0b.y * w1.y; q1.z = s0b.z * w1.z; q1.w = s0b.w * w1.w;

    float scw[9];
    #pragma unroll
    for (int k = 0; k < 9; k++) {
        int j = n + k - kWIN;
        bool valid = ((unsigned)j < (unsigned)kS);
        int jc = min(max(j, 0), kS - 1);
        float4 na = st4[(size_t)jc * 64 + ci];
        float4 nb = st4[(size_t)jc * 64 + ci + 1];
        float p = q0.x * na.x + q0.y * na.y + q0.z * na.z + q0.w * na.w
                + q1.x * nb.x + q1.y * nb.y + q1.z * nb.z + q1.w * nb.w;
        p = warpsum(p);
        scw[k] = valid ? p * INV_SQRT_D : -1e30f;
    }
    float mx = scw[0];
    #pragma unroll
    for (int k = 1; k < 9; k++) mx = fmaxf(mx, scw[k]);
    float asum = 0.0f;
    #pragma unroll
    for (int k = 0; k < 9; k++) { scw[k] = expf(scw[k] - mx); asum += scw[k]; }
    float ainv = 1.0f / asum;

    float4 ds0 = {0,0,0,0}, ds1 = {0,0,0,0}, dv0 = {0,0,0,0}, dv1 = {0,0,0,0};
    #pragma unroll
    for (int k = 0; k < 9; k++) {
        int j = n + k - kWIN;
        int jc = min(max(j, 0), kS - 1);
        float a = scw[k] * ainv;
        float4 na = st4[(size_t)jc * 64 + ci];
        float4 nb = st4[(size_t)jc * 64 + ci + 1];
        float4 va = vl4[(size_t)jc * 64 + ci];
        float4 vb = vl4[(size_t)jc * 64 + ci + 1];
        ds0.x += a * na.x; ds0.y += a * na.y; ds0.z += a * na.z; ds0.w += a * na.w;
        ds1.x += a * nb.x; ds1.y += a * nb.y; ds1.z += a * nb.z; ds1.w += a * nb.w;
        dv0.x += a * va.x; dv0.y += a * va.y; dv0.z += a * va.z; dv0.w += a * va.w;
        dv1.x += a * vb.x; dv1.y += a * vb.y; dv1.z += a * vb.z; dv1.w += a * vb.w;
    }

    float sv0[8] = {s0a.x, s0a.y, s0a.z, s0a.w, s0b.x, s0b.y, s0b.z, s0b.w};
    float dss[8] = {ds0.x, ds0.y, ds0.z, ds0.w, ds1.x, ds1.y, ds1.z, ds1.w};
    float sq[8];
    #pragma unroll
    for (int i = 0; i < 8; i++) sq[i] = tanhf(tanhf(sv0[i] + S_SC * dss[i]));

    float4* outS = (float4*)(out + OFF_SSTATE);
    outS[(size_t)row * 64 + ci]     = make_float4(sq[0], sq[1], sq[2], sq[3]);
    outS[(size_t)row * 64 + ci + 1] = make_float4(sq[4], sq[5], sq[6], sq[7]);

    uint4 hw;
    unsigned* hwp = (unsigned*)&hw;
    #pragma unroll
    for (int i = 0; i < 4; i++) {
        __nv_bfloat16 ha = __float2bfloat16(sq[2 * i]);
        __nv_bfloat16 hc = __float2bfloat16(sq[2 * i + 1]);
        hwp[i] = ((unsigned)__bfloat16_as_ushort(hc) << 16) | __bfloat16_as_ushort(ha);
    }
    *(uint4*)&g_shi[(size_t)row * kD + lane * 8] = hw;

    float4 va0 = vl4[(size_t)n * 64 + ci];
    float4 va1 = vl4[(size_t)n * 64 + ci + 1];
    float v[8];
    v[0] = va0.x + S_SC * dv0.x; v[1] = va0.y + S_SC * dv0.y;
    v[2] = va0.z + S_SC * dv0.z; v[3] = va0.w + S_SC * dv0.w;
    v[4] = va1.x + S_SC * dv1.x; v[5] = va1.y + S_SC * dv1.y;
    v[6] = va1.z + S_SC * dv1.z; v[7] = va1.w + S_SC * dv1.w;

    float4 g0 = ((const float4*)ln_g_s)[ci], g1 = ((const float4*)ln_g_s)[ci + 1];
    float4 b0v = ((const float4*)ln_b_s)[ci], b1v = ((const float4*)ln_b_s)[ci + 1];
    float gs[8] = {g0.x, g0.y, g0.z, g0.w, g1.x, g1.y, g1.z, g1.w};
    float bs[8] = {b0v.x, b0v.y, b0v.z, b0v.w, b1v.x, b1v.y, b1v.z, b1v.w};

    float s8 = 0.0f;
    #pragma unroll
    for (int i = 0; i < 8; i++) s8 += v[i];
    float mean = warpsum(s8) * (1.0f / kD);
    float vs = 0.0f;
    #pragma unroll
    for (int i = 0; i < 8; i++) { v[i] -= mean; vs += v[i] * v[i]; }
    float rstd = rsqrtf(warpsum(vs) * (1.0f / kD) + EPSL);
    #pragma unroll
    for (int i = 0; i < 8; i++) v[i] = v[i] * rstd * gs[i] + bs[i];

    bool hit = false; float wj = 0.0f;
    #pragma unroll
    for (int j = 0; j < 4; j++)
        if (g_is[j] == n) { hit = true; wj = g_ws[j]; }
    if (hit) {
        float4 e0 = ((const float4*)g_esum)[ci], e1 = ((const float4*)g_esum)[ci + 1];
        float es[8] = {e0.x, e0.y, e0.z, e0.w, e1.x, e1.y, e1.z, e1.w};
        #pragma unroll
        for (int i = 0; i < 8; i++) v[i] += SC_X * wj * es[i];
    }

    s8 = 0.0f;
    #pragma unroll
    for (int i = 0; i < 8; i++) s8 += v[i];
    mean = warpsum(s8) * (1.0f / kD);
    vs = 0.0f;
    #pragma unroll
    for (int i = 0; i < 8; i++) { v[i] -= mean; vs += v[i] * v[i]; }
    rstd = rsqrtf(warpsum(vs) * (1.0f / kD) + EPSL);
    float4* outV = (float4*)(out + OFF_SVAL);
    outV[(size_t)row * 64 + ci] =
        make_float4(v[0] * rstd * gs[0] + bs[0], v[1] * rstd * gs[1] + bs[1],
                    v[2] * rstd * gs[2] + bs[2], v[3] * rstd * gs[3] + bs[3]);
    outV[(size_t)row * 64 + ci + 1] =
        make_float4(v[4] * rstd * gs[4] + bs[4], v[5] * rstd * gs[5] + bs[5],
                    v[6] * rstd * gs[6] + bs[6], v[7] * rstd * gs[7] + bs[7]);
}

// ---------------------------------------------------------------------------
// K3a: single-term bf16 tensor-core GEMM (candidate generation),
// cp.async double-buffered + ldmatrix, fused per-slab top4 epilogue.
// 128x128 tile, K-chunk 16, 2 stages, 8 warps (4m x 2n), warp tile 32x64.
// ---------------------------------------------------------------------------
#define KC 16
#define SROW 24
__global__ __launch_bounds__(256, 2) void k3a_gemm(const float* __restrict__ bias)
{
    __shared__ __align__(16) __nv_bfloat16 sm[2][2][128 * SROW];
    int tid = threadIdx.x;
    int warp = tid >> 5, lane = tid & 31;
    int mw = warp & 3, nw = warp >> 2;
    int g = lane >> 2, t = lane & 3;
    int m0 = blockIdx.y * 128, n0 = blockIdx.x * 128;

    int lrow = tid >> 1, lhalf = tid & 1;
    const __nv_bfloat16* srcA = g_shi + (size_t)(m0 + lrow) * kD + lhalf * 8;
    const __nv_bfloat16* srcB = g_wth + (size_t)(n0 + lrow) * kD + lhalf * 8;
    int dOff = lrow * SROW + lhalf * 8;

    int a_row = mw * 32 + (lane & 7) + ((lane >> 3) & 1) * 8;   // + mt*16
    int a_kh  = ((lane >> 4) & 1) * 8;
    int b_row = nw * 64 + (lane & 7) + ((lane >> 4) & 1) * 8;   // + p*16
    int b_kh  = ((lane >> 3) & 1) * 8;

    float acc[2][8][4];
    #pragma unroll
    for (int i = 0; i < 2; i++)
        #pragma unroll
        for (int j = 0; j < 8; j++)
            #pragma unroll
            for (int q = 0; q < 4; q++) acc[i][j][q] = 0.0f;

    auto load_stage = [&](int st, int k0) {
        cpasync16(&sm[st][0][dOff], srcA + k0);
        cpasync16(&sm[st][1][dOff], srcB + k0);
        asm volatile("cp.async.commit_group;");
    };

    load_stage(0, 0);

    #pragma unroll 4
    for (int ks = 0; ks < kD / KC; ks++) {
        int st = ks & 1;
        if (ks + 1 < kD / KC) {
            load_stage(st ^ 1, (ks + 1) * KC);
            asm volatile("cp.async.wait_group 1;");
        } else {
            asm volatile("cp.async.wait_group 0;");
        }
        __syncthreads();

        unsigned ah[2][4];
        #pragma unroll
        for (int mt = 0; mt < 2; mt++)
            ldsm4(ah[mt], &sm[st][0][(a_row + mt * 16) * SROW + a_kh]);
        #pragma unroll
        for (int p = 0; p < 4; p++) {
            unsigned bh[4];
            ldsm4(bh, &sm[st][1][(b_row + p * 16) * SROW + b_kh]);
            #pragma unroll
            for (int half = 0; half < 2; half++) {
                int nt = p * 2 + half;
                unsigned* bhp = bh + half * 2;
                #pragma unroll
                for (int mt = 0; mt < 2; mt++)
                    mma16816(acc[mt][nt], ah[mt], bhp);
            }
        }
        __syncthreads();
    }

    float bcol[16];
    #pragma unroll
    for (int nt = 0; nt < 8; nt++) {
        int c = n0 + nw * 64 + nt * 8 + 2 * t;
        bcol[nt * 2]     = bias[c];
        bcol[nt * 2 + 1] = bias[c + 1];
    }

    float* svv = (float*)&sm[0][0][0];
    int*   sii = (int*)(((char*)&sm[0][0][0]) + 4096);
    __syncthreads();

    #pragma unroll
    for (int mt = 0; mt < 2; mt++) {
        #pragma unroll
        for (int h = 0; h < 2; h++) {
            float tv[4] = {-INFINITY, -INFINITY, -INFINITY, -INFINITY};
            int   ti[4] = {0x7fffffff, 0x7fffffff, 0x7fffffff, 0x7fffffff};
            #pragma unroll
            for (int nt = 0; nt < 8; nt++) {
                #pragma unroll
                for (int e = 0; e < 2; e++) {
                    float val = acc[mt][nt][h * 2 + e] + bcol[nt * 2 + e];
                    int col = n0 + nw * 64 + nt * 8 + 2 * t + e;
                    ins4(val, col, tv, ti);
                }
            }
            #pragma unroll
            for (int msk = 1; msk <= 2; msk <<= 1) {
                float pv[4]; int pi[4];
                #pragma unroll
                for (int j = 0; j < 4; j++) {
                    pv[j] = __shfl_xor_sync(0xffffffffu, tv[j], msk);
                    pi[j] = __shfl_xor_sync(0xffffffffu, ti[j], msk);
                }
                #pragma unroll
                for (int j = 0; j < 4; j++) ins4(pv[j], pi[j], tv, ti);
            }
            if (t == 0) {
                int lrow2 = mw * 32 + mt * 16 + h * 8 + g;
                #pragma unroll
                for (int j = 0; j < 4; j++) {
                    svv[(lrow2 * 2 + nw) * 4 + j] = tv[j];
                    sii[(lrow2 * 2 + nw) * 4 + j] = ti[j];
                }
            }
        }
    }
    __syncthreads();
    if (tid < 128) {
        float tv[4]; int ti[4];
        #pragma unroll
        for (int j = 0; j < 4; j++) { tv[j] = svv[(tid * 2) * 4 + j]; ti[j] = sii[(tid * 2) * 4 + j]; }
        #pragma unroll
        for (int j = 0; j < 4; j++) ins4(svv[(tid * 2 + 1) * 4 + j], sii[(tid * 2 + 1) * 4 + j], tv, ti);
        size_t base = ((size_t)(m0 + tid) * 4 + blockIdx.x) * 4;
        #pragma unroll
        for (int j = 0; j < 4; j++) { g_candV[base + j] = tv[j]; g_candI[base + j] = ti[j]; }
    }
}

// ---------------------------------------------------------------------------
// K3b: rescore — merge 16 bf16 candidates -> top-8, recompute those 8 logits
// exactly in fp32, exact top-4 -> softmax -> bucket push. Warp per row.
// ---------------------------------------------------------------------------
__global__ __launch_bounds__(256) void k3b_rescore(
    const float* __restrict__ out, const float* __restrict__ bias)
{
    int warp = threadIdx.x >> 5, lane = threadIdx.x & 31;
    int row = blockIdx.x * 8 + warp;
    int b = row >> 13;

    float v = (lane < 16) ? g_candV[(size_t)row * 16 + lane] : -INFINITY;
    int  ix = (lane < 16) ? g_candI[(size_t)row * 16 + lane] : 0x7fffffff;

    int cand8[8];
    #pragma unroll
    for (int r = 0; r < 8; r++) {
        float mv = v; int mi = ix;
        #pragma unroll
        for (int off = 16; off > 0; off >>= 1) {
            float ov = __shfl_xor_sync(0xffffffffu, mv, off);
            int   oi = __shfl_xor_sync(0xffffffffu, mi, off);
            if (bet(ov, oi, mv, mi)) { mv = ov; mi = oi; }
        }
        cand8[r] = mi;
        if (ix == mi) v = -INFINITY;
    }

    const float4* ar = (const float4*)(out + OFF_SSTATE + (size_t)row * kD);
    float4 a0 = ar[lane * 2], a1 = ar[lane * 2 + 1];

    float ex[8];
    #pragma unroll
    for (int r = 0; r < 8; r++) {
        const float4* wr = (const float4*)(g_wtf + (size_t)cand8[r] * kD);
        float4 w0 = wr[lane * 2], w1 = wr[lane * 2 + 1];
        float p = a0.x * w0.x + a0.y * w0.y + a0.z * w0.z + a0.w * w0.w
                + a1.x * w1.x + a1.y * w1.y + a1.z * w1.z + a1.w * w1.w;
        ex[r] = warpsum(p) + bias[cand8[r]];
    }

    float tv[4] = {-INFINITY, -INFINITY, -INFINITY, -INFINITY};
    int   ti[4] = {0x7fffffff, 0x7fffffff, 0x7fffffff, 0x7fffffff};
    #pragma unroll
    for (int r = 0; r < 8; r++) ins4(ex[r], cand8[r], tv, ti);

    float mx = tv[0];
    float e0 = expf(tv[0] - mx), e1 = expf(tv[1] - mx);
    float e2 = expf(tv[2] - mx), e3 = expf(tv[3] - mx);
    float inv = 1.0f / (e0 + e1 + e2 + e3);
    if (lane < 4) {
        float ej = (lane == 0) ? e0 : (lane == 1) ? e1 : (lane == 2) ? e2 : e3;
        float wgt = SC_X * ej * inv;
        int bt = b * kNC + ti[lane];
        int pos = atomicAdd(&g_cnt[bt], 1);
        if (pos < CAP) {
            g_entR[(size_t)bt * CAP + pos] = row;
            g_entW[(size_t)bt * CAP + pos] = wgt;
        }
    }
}

// ---------------------------------------------------------------------------
// K3c: per-(b,target) gather-sum
// ---------------------------------------------------------------------------
__global__ __launch_bounds__(256) void k3c_gather(
    const float* __restrict__ out, const float* __restrict__ ln_b_c)
{
    int bt = blockIdx.x;
    int t = bt & (kNC - 1);
    int sub = threadIdx.x >> 6, c = threadIdx.x & 63;
    int n = min(g_cnt[bt], CAP);
    const float4* ssf = (const float4*)(out + OFF_SSTATE);
    const float4* svf = (const float4*)(out + OFF_SVAL);
    float4 aS = {0,0,0,0}, aV = {0,0,0,0};
    for (int i = sub; i < n; i += 4) {
        int r   = g_entR[(size_t)bt * CAP + i];
        float w = g_entW[(size_t)bt * CAP + i];
        float4 s = ssf[(size_t)r * 64 + c];
        float4 vv = svf[(size_t)r * 64 + c];
        aS.x += w * s.x;  aS.y += w * s.y;  aS.z += w * s.z;  aS.w += w * s.w;
        aV.x += w * vv.x; aV.y += w * vv.y; aV.z += w * vv.z; aV.w += w * vv.w;
    }
    __shared__ float4 shS[4][64], shV[4][64];
    shS[sub][c] = aS; shV[sub][c] = aV;
    __syncthreads();
    if (sub == 0) {
        float4 S = shS[0][c], V = shV[0][c];
        #pragma unroll
        for (int q = 1; q < 4; q++) {
            float4 s2 = shS[q][c], v2 = shV[q][c];
            S.x += s2.x; S.y += s2.y; S.z += s2.z; S.w += s2.w;
            V.x += v2.x; V.y += v2.y; V.z += v2.z; V.w += v2.w;
        }
        ((float4*)g_ncs)[(size_t)bt * 64 + c] = S;
        float4 nb = ((const float4*)ln_b_c)[c];
        V.x += nb.x; V.y += nb.y; V.z += nb.z; V.w += nb.w;
        #pragma unroll
        for (int j = 0; j < 4; j++)
            if (g_ic[j] == t) {
                float w = SC_B * g_wc[j];
                float4 es = ((const float4*)g_esum)[c];
                V.x += w * es.x; V.y += w * es.y; V.z += w * es.z; V.w += w * es.w;
            }
        ((float4*)g_ncv)[(size_t)bt * 64 + c] = V;
    }
}

// ---------------------------------------------------------------------------
// K4a: per-batch scores
// ---------------------------------------------------------------------------
__global__ __launch_bounds__(256) void k4a_scores(const float* __restrict__ wpc)
{
    int bb = blockIdx.z;
    int m0 = blockIdx.y * 64;
    int n0 = blockIdx.x * 64;
    const float* ncs = g_ncs + (size_t)bb * kNC * kD;
    __shared__ float As[16][64 + 4];
    __shared__ float Bs[16][64 + 4];
    int tid = threadIdx.x;
    int ty = tid / 16, tx = tid % 16;
    float acc[4][4] = {};
    int lrow = tid / 4;
    int lk = (tid % 4) * 4;
    for (int k0 = 0; k0 < kD; k0 += 16) {
        float4 av = *(const float4*)&ncs[(size_t)(m0 + lrow) * kD + k0 + lk];
        float4 bv = *(const float4*)&ncs[(size_t)(n0 + lrow) * kD + k0 + lk];
        float4 wv = *(const float4*)&wpc[k0 + lk];
        As[lk + 0][lrow] = av.x * wv.x; As[lk + 1][lrow] = av.y * wv.y;
        As[lk + 2][lrow] = av.z * wv.z; As[lk + 3][lrow] = av.w * wv.w;
        Bs[lk + 0][lrow] = bv.x; Bs[lk + 1][lrow] = bv.y;
        Bs[lk + 2][lrow] = bv.z; Bs[lk + 3][lrow] = bv.w;
        __syncthreads();
        #pragma unroll
        for (int kk = 0; kk < 16; kk++) {
            float ar[4], br[4];
            #pragma unroll
            for (int i = 0; i < 4; i++) ar[i] = As[kk][ty * 4 + i];
            #pragma unroll
            for (int j = 0; j < 4; j++) br[j] = Bs[kk][tx * 4 + j];
            #pragma unroll
            for (int i = 0; i < 4; i++)
                #pragma unroll
                for (int j = 0; j < 4; j++)
                    acc[i][j] += ar[i] * br[j];
        }
        __syncthreads();
    }
    #pragma unroll
    for (int i = 0; i < 4; i++)
        #pragma unroll
        for (int j = 0; j < 4; j++)
            g_scmat[(size_t)bb * kNC * kNC + (size_t)(m0 + ty * 4 + i) * kNC + (n0 + tx * 4 + j)] =
                acc[i][j] * INV_SQRT_D;
}

// ---------------------------------------------------------------------------
// K4b: per-(b,n) top-4, softmax, gather, tanh/LN finalize
// ---------------------------------------------------------------------------
__global__ __launch_bounds__(256) void k4b_final(
    const float* __restrict__ ln_g_c, const float* __restrict__ ln_b_c,
    float* __restrict__ out)
{
    int bn = blockIdx.x;
    int bb = bn / kNC;
    int d = threadIdx.x;
    const float* sc = g_scmat + (size_t)bn * kNC;
    __shared__ float sv[256]; __shared__ int si[256];
    __shared__ float red[256];
    __shared__ float topw[4]; __shared__ int topidx[4];

    float v0 = sc[d], v1 = sc[d + 256];
    bool t0 = false, t1 = false;
    for (int r = 0; r < 4; r++) {
        float bv = -INFINITY; int bi = 0x7fffffff;
        if (!t0) { bv = v0; bi = d; }
        if (!t1 && bet(v1, d + 256, bv, bi)) { bv = v1; bi = d + 256; }
        sv[d] = bv; si[d] = bi; __syncthreads();
        for (int s = 128; s > 0; s >>= 1) {
            if (d < s && bet(sv[d + s], si[d + s], sv[d], si[d])) {
                sv[d] = sv[d + s]; si[d] = si[d + s];
            }
            __syncthreads();
        }
        if (d == 0) { topw[r] = sv[0]; topidx[r] = si[0]; }
        __syncthreads();
        int widx = topidx[r];
        if (widx == d) t0 = true;
        if (widx == d + 256) t1 = true;
    }

    float mx = topw[0];
    float e[4]; float esum = 0.0f;
    #pragma unroll
    for (int j = 0; j < 4; j++) { e[j] = expf(topw[j] - mx); esum += e[j]; }
    float inv = 1.0f / esum;

    const float* ncsB = g_ncs + (size_t)bb * kNC * kD;
    const float* ncvB = g_ncv + (size_t)bb * kNC * kD;
    float ds = 0.0f, dv = 0.0f;
    #pragma unroll
    for (int j = 0; j < 4; j++) {
        int m = topidx[j];
        float a = e[j] * inv;
        ds += a * ncsB[(size_t)m * kD + d];
        dv += a * ncvB[(size_t)m * kD + d];
    }
    float spre = g_ncs[(size_t)bn * kD + d];
    float vpre = g_ncv[(size_t)bn * kD + d];

    out[OFF_NCS + (size_t)bn * kD + d] = tanhf(spre + SC_B * ds);

    auto bsum = [&](float x) -> float {
        red[d] = x; __syncthreads();
        for (int s = 128; s > 0; s >>= 1) {
            if (d < s) red[d] += red[d + s];
            __syncthreads();
        }
        float r = red[0]; __syncthreads(); return r;
    };
    float x = vpre + SC_B * dv;
    float m = bsum(x) * (1.0f / kD);
    float xd = x - m;
    float var = bsum(xd * xd) * (1.0f / kD);
    out[OFF_NCV + (size_t)bn * kD + d] = xd * rsqrtf(var + EPSL) * ln_g_c[d] + ln_b_c[d];
}

// ---------------------------------------------------------------------------
extern "C" void kernel_launch(void* const* d_in, const int* in_sizes, int n_in,
                              void* d_out, int out_size) {
    const float* s_state  = (const float*)d_in[0];
    const float* s_val    = (const float*)d_in[1];
    const float* w_pair_s = (const float*)d_in[2];
    const float* w_pair_c = (const float*)d_in[4];
    const float* b_expand = (const float*)d_in[6];
    const float* b_b2s    = (const float*)d_in[8];
    const float* b_comp   = (const float*)d_in[10];
    const float* W_s2b    = (const float*)d_in[11];
    const float* b_s2b    = (const float*)d_in[12];
    const float* ln_g_s   = (const float*)d_in[13];
    const float* ln_b_s   = (const float*)d_in[14];
    const float* ln_g_e   = (const float*)d_in[15];
    const float* ln_b_e   = (const float*)d_in[16];
    const float* ln_g_c   = (const float*)d_in[17];
    const float* ln_b_c   = (const float*)d_in[18];
    float* out = (float*)d_out;

    k0_prep<<<1, 256>>>(b_expand, b_b2s, b_comp, ln_b_c, ln_g_e, ln_b_e);
    k1_splitW<<<dim3(kNC / 32, kD / 32), dim3(32, 32)>>>(W_s2b);
    k2_window<<<kM / 8, 256>>>(s_state, s_val, w_pair_s, ln_g_s, ln_b_s, out);
    k3a_gemm<<<dim3(kNC / 128, kM / 128), 256>>>(b_s2b);
    k3b_rescore<<<kM / 8, 256>>>(out, b_s2b);
    k3c_gather<<<kB * kNC, 256>>>(out, ln_b_c);
    k4a_scores<<<dim3(kNC / 64, kNC / 64, kB), 256>>>(w_pair_c);
    k4b_final<<<kB * kNC, 256>>>(ln_g_c, ln_b_c, out);
}

// round 11
// speedup vs baseline: 1.0790x; 1.0404x over previous
#include <cuda_runtime.h>
#include <cuda_bf16.h>
#include <math.h>
#include <cstdint>

// ---------------------------------------------------------------------------
#define kD   256
#define kB   4
#define kS   8192
#define kNE  2048
#define kNC  512
#define kWIN 4
#define kM   (kB * kS)

#define S_SC       0.25f
#define SC_B       0.2f
#define SC_X       0.075f
#define EPSL       1e-5f
#define INV_SQRT_D 0.0625f
#define CAP        2048

#define OFF_SSTATE ((size_t)0)
#define OFF_SVAL   ((size_t)kB * kS * kD)
#define OFF_NCS    ((size_t)2 * kB * kS * kD)
#define OFF_NCV    (OFF_NCS + (size_t)kB * kNC * kD)

// ---------------------------------------------------------------------------
__device__ float g_scmat[(size_t)kB * kNC * kNC];
__device__ int   g_entR[(size_t)kB * kNC * CAP];
__device__ float g_entW[(size_t)kB * kNC * CAP];
__device__ int   g_cnt[kB * kNC];
__device__ float g_esum[kD];
__device__ int   g_is[4]; __device__ float g_ws[4];
__device__ int   g_ic[4]; __device__ float g_wc[4];
__device__ float g_ncs[(size_t)kB * kNC * kD];
__device__ float g_ncv[(size_t)kB * kNC * kD];

__device__ __nv_bfloat16 g_shi[(size_t)kM * kD];    // bf16 of s_state_final
__device__ __nv_bfloat16 g_wth[(size_t)kNC * kD];   // W_s2b^T bf16 [512][256]
__device__ float         g_wtf[(size_t)kNC * kD];   // W_s2b^T fp32 [512][256]
__device__ float g_candV[(size_t)kM * 16];          // 4 slabs x 4 candidates
__device__ int   g_candI[(size_t)kM * 16];

__device__ __forceinline__ bool bet(float v, int i, float bv, int bi) {
    return (v > bv) || (v == bv && i < bi);
}

__device__ __forceinline__ float warpsum(float v) {
    #pragma unroll
    for (int off = 16; off > 0; off >>= 1) v += __shfl_xor_sync(0xffffffffu, v, off);
    return v;
}

__device__ __forceinline__ void ins4(float v, int i, float* tv, int* ti) {
    if (bet(v, i, tv[3], ti[3])) {
        tv[3] = v; ti[3] = i;
        #pragma unroll
        for (int q = 3; q > 0; q--) {
            if (bet(tv[q], ti[q], tv[q - 1], ti[q - 1])) {
                float fv = tv[q]; tv[q] = tv[q - 1]; tv[q - 1] = fv;
                int   fi = ti[q]; ti[q] = ti[q - 1]; ti[q - 1] = fi;
            } else break;
        }
    }
}

__device__ __forceinline__ void mma16816(float* c, const unsigned* a, const unsigned* b) {
    asm volatile(
        "mma.sync.aligned.m16n8k16.row.col.f32.bf16.bf16.f32 "
        "{%0,%1,%2,%3}, {%4,%5,%6,%7}, {%8,%9}, {%0,%1,%2,%3};"
        : "+f"(c[0]), "+f"(c[1]), "+f"(c[2]), "+f"(c[3])
        : "r"(a[0]), "r"(a[1]), "r"(a[2]), "r"(a[3]), "r"(b[0]), "r"(b[1]));
}

__device__ __forceinline__ void ldsm4(unsigned* r, const void* p) {
    unsigned a = (unsigned)__cvta_generic_to_shared(p);
    asm volatile("ldmatrix.sync.aligned.m8n8.x4.shared.b16 {%0,%1,%2,%3}, [%4];"
        : "=r"(r[0]), "=r"(r[1]), "=r"(r[2]), "=r"(r[3]) : "r"(a));
}

__device__ __forceinline__ void cpasync16(void* dst, const void* src) {
    unsigned sd = (unsigned)__cvta_generic_to_shared(dst);
    asm volatile("cp.async.cg.shared.global [%0], [%1], 16;" :: "r"(sd), "l"(src));
}

// ---------------------------------------------------------------------------
// K0: prep (top4 of biases, collapsed e_val algebra, zero counters)
// ---------------------------------------------------------------------------
__global__ __launch_bounds__(256) void k0_prep(
    const float* __restrict__ b_expand, const float* __restrict__ b_b2s,
    const float* __restrict__ b_comp,   const float* __restrict__ ln_b_c,
    const float* __restrict__ ln_g_e,   const float* __restrict__ ln_b_e)
{
    __shared__ float sv[256];  __shared__ int si[256];
    __shared__ float red[256];
    __shared__ float tv[4];    __shared__ int ti[4];
    __shared__ float we[4];    __shared__ int ie[4];
    int tid = threadIdx.x;

    for (int j = tid; j < kB * kNC; j += 256) g_cnt[j] = 0;

    auto top4 = [&](const float* x, int n) {
        for (int r = 0; r < 4; r++) {
            float bv = -INFINITY; int bi = 0x7fffffff;
            for (int j = tid; j < n; j += 256) {
                bool skip = false;
                for (int q = 0; q < r; q++) if (ti[q] == j) skip = true;
                float v = x[j];
                if (!skip && bet(v, j, bv, bi)) { bv = v; bi = j; }
            }
            sv[tid] = bv; si[tid] = bi; __syncthreads();
            for (int s = 128; s > 0; s >>= 1) {
                if (tid < s && bet(sv[tid + s], si[tid + s], sv[tid], si[tid])) {
                    sv[tid] = sv[tid + s]; si[tid] = si[tid + s];
                }
                __syncthreads();
            }
            if (tid == 0) { tv[r] = sv[0]; ti[r] = si[0]; }
            __syncthreads();
        }
    };
    auto softmax4 = [&](float* wout) {
        if (tid == 0) {
            float m = tv[0];
            float e0 = expf(tv[0] - m), e1 = expf(tv[1] - m);
            float e2 = expf(tv[2] - m), e3 = expf(tv[3] - m);
            float inv = 1.0f / (e0 + e1 + e2 + e3);
            wout[0] = e0 * inv; wout[1] = e1 * inv;
            wout[2] = e2 * inv; wout[3] = e3 * inv;
        }
        __syncthreads();
    };

    top4(b_expand, kNE); softmax4(we);
    if (tid < 4) ie[tid] = ti[tid];
    __syncthreads();
    top4(b_b2s, kS); softmax4(g_ws);
    if (tid < 4) g_is[tid] = ti[tid];
    __syncthreads();
    top4(b_comp, kNC); softmax4(g_wc);
    if (tid < 4) g_ic[tid] = ti[tid];
    __syncthreads();

    int d = tid;
    float cval = ln_b_c[d];
    float rowval[4];
    float dvE = 0.0f;
    #pragma unroll
    for (int j = 0; j < 4; j++) {
        rowval[j] = SC_B * (float)kNC * we[j] * cval;
        if (ie[j] < 4) dvE += rowval[j];
    }
    dvE *= 0.25f;
    float base = SC_B * dvE;

    auto bsum = [&](float x) -> float {
        red[tid] = x; __syncthreads();
        for (int s = 128; s > 0; s >>= 1) {
            if (tid < s) red[tid] += red[tid + s];
            __syncthreads();
        }
        float r = red[0]; __syncthreads(); return r;
    };
    float ge = ln_g_e[d], be = ln_b_e[d];
    auto LN_e = [&](float x) -> float {
        float m  = bsum(x) * (1.0f / kD);
        float dv = x - m;
        float var = bsum(dv * dv) * (1.0f / kD);
        return dv * rsqrtf(var + EPSL) * ge + be;
    };

    float other = LN_e(base);
    float esum = (float)(kNE - 4) * other;
    #pragma unroll
    for (int j = 0; j < 4; j++) esum += LN_e(rowval[j] + base);
    g_esum[d] = esum;
}

// ---------------------------------------------------------------------------
// K1: W_s2b -> transposed bf16 [512 n][256 k] + transposed fp32 copy
// ---------------------------------------------------------------------------
__global__ void k1_splitW(const float* __restrict__ W)
{
    __shared__ float tile[32][33];
    int n0 = blockIdx.x * 32, k0 = blockIdx.y * 32;
    int tx = threadIdx.x, ty = threadIdx.y;
    tile[ty][tx] = W[(size_t)(k0 + ty) * kNC + n0 + tx];
    __syncthreads();
    float x = tile[tx][ty];                    // W[k0+tx][n0+ty]
    g_wth[(size_t)(n0 + ty) * kD + k0 + tx] = __float2bfloat16(x);
    g_wtf[(size_t)(n0 + ty) * kD + k0 + tx] = x;
}

// ---------------------------------------------------------------------------
// K2: smem-tiled window prop. Block = 8 consecutive rows (same batch);
// loads state+val rows [n0-4, n0+11] (clamped) once into smem, then each
// warp computes one row entirely from smem. Emits bf16 of final state.
// ---------------------------------------------------------------------------
__global__ __launch_bounds__(256) void k2_window(
    const float* __restrict__ s_state, const float* __restrict__ s_val,
    const float* __restrict__ w_pair_s,
    const float* __restrict__ ln_g_s, const float* __restrict__ ln_b_s,
    float* __restrict__ out)
{
    __shared__ float4 st_s[16][64];
    __shared__ float4 vl_s[16][64];

    int tid = threadIdx.x;
    int warp = tid >> 5, lane = tid & 31;
    int row0 = blockIdx.x * 8;
    int b = row0 >> 13, n0 = row0 & (kS - 1);
    const float4* st4 = (const float4*)(s_state + (size_t)b * kS * kD);
    const float4* vl4 = (const float4*)(s_val   + (size_t)b * kS * kD);

    // cooperative tile load: 2 arrays x 16 rows x 64 float4
    #pragma unroll
    for (int t = 0; t < 8; t++) {
        int i = tid + t * 256;
        int arr = i >> 10, slot = (i >> 6) & 15, c = i & 63;
        int gr = min(max(n0 - 4 + slot, 0), kS - 1);
        float4 v = (arr ? vl4 : st4)[(size_t)gr * 64 + c];
        if (arr) vl_s[slot][c] = v; else st_s[slot][c] = v;
    }
    __syncthreads();

    int n = n0 + warp;
    int row = row0 + warp;
    int ci = lane * 2;

    float4 w0 = ((const float4*)w_pair_s)[ci];
    float4 w1 = ((const float4*)w_pair_s)[ci + 1];
    float4 s0a = st_s[warp + 4][ci];
    float4 s0b = st_s[warp + 4][ci + 1];
    float4 q0, q1;
    q0.x = s0a.x * w0.x; q0.y = s0a.y * w0.y; q0.z = s0a.z * w0.z; q0.w = s0a.w * w0.w;
    q1.x = s0b.x * w1.x; q1.y = s0b.y * w1.y; q1.z = s0b.z * w1.z; q1.w = s0b.w * w1.w;

    float scw[9];
    #pragma unroll
    for (int k = 0; k < 9; k++) {
        int j = n + k - kWIN;
        bool valid = ((unsigned)j < (unsigned)kS);
        float4 na = st_s[warp + k][ci];
        float4 nb = st_s[warp + k][ci + 1];
        float p = q0.x * na.x + q0.y * na.y + q0.z * na.z + q0.w * na.w
                + q1.x * nb.x + q1.y * nb.y + q1.z * nb.z + q1.w * nb.w;
        p = warpsum(p);
        scw[k] = valid ? p * INV_SQRT_D : -1e30f;
    }
    float mx = scw[0];
    #pragma unroll
    for (int k = 1; k < 9; k++) mx = fmaxf(mx, scw[k]);
    float asum = 0.0f;
    #pragma unroll
    for (int k = 0; k < 9; k++) { scw[k] = expf(scw[k] - mx); asum += scw[k]; }
    float ainv = 1.0f / asum;

    float4 ds0 = {0,0,0,0}, ds1 = {0,0,0,0}, dv0 = {0,0,0,0}, dv1 = {0,0,0,0};
    #pragma unroll
    for (int k = 0; k < 9; k++) {
        float a = scw[k] * ainv;
        float4 na = st_s[warp + k][ci];
        float4 nb = st_s[warp + k][ci + 1];
        float4 va = vl_s[warp + k][ci];
        float4 vb = vl_s[warp + k][ci + 1];
        ds0.x += a * na.x; ds0.y += a * na.y; ds0.z += a * na.z; ds0.w += a * na.w;
        ds1.x += a * nb.x; ds1.y += a * nb.y; ds1.z += a * nb.z; ds1.w += a * nb.w;
        dv0.x += a * va.x; dv0.y += a * va.y; dv0.z += a * va.z; dv0.w += a * va.w;
        dv1.x += a * vb.x; dv1.y += a * vb.y; dv1.z += a * vb.z; dv1.w += a * vb.w;
    }

    float sv0[8] = {s0a.x, s0a.y, s0a.z, s0a.w, s0b.x, s0b.y, s0b.z, s0b.w};
    float dss[8] = {ds0.x, ds0.y, ds0.z, ds0.w, ds1.x, ds1.y, ds1.z, ds1.w};
    float sq[8];
    #pragma unroll
    for (int i = 0; i < 8; i++) sq[i] = tanhf(tanhf(sv0[i] + S_SC * dss[i]));

    float4* outS = (float4*)(out + OFF_SSTATE);
    outS[(size_t)row * 64 + ci]     = make_float4(sq[0], sq[1], sq[2], sq[3]);
    outS[(size_t)row * 64 + ci + 1] = make_float4(sq[4], sq[5], sq[6], sq[7]);

    uint4 hw;
    unsigned* hwp = (unsigned*)&hw;
    #pragma unroll
    for (int i = 0; i < 4; i++) {
        __nv_bfloat16 ha = __float2bfloat16(sq[2 * i]);
        __nv_bfloat16 hc = __float2bfloat16(sq[2 * i + 1]);
        hwp[i] = ((unsigned)__bfloat16_as_ushort(hc) << 16) | __bfloat16_as_ushort(ha);
    }
    *(uint4*)&g_shi[(size_t)row * kD + lane * 8] = hw;

    float4 va0 = vl_s[warp + 4][ci];
    float4 va1 = vl_s[warp + 4][ci + 1];
    float v[8];
    v[0] = va0.x + S_SC * dv0.x; v[1] = va0.y + S_SC * dv0.y;
    v[2] = va0.z + S_SC * dv0.z; v[3] = va0.w + S_SC * dv0.w;
    v[4] = va1.x + S_SC * dv1.x; v[5] = va1.y + S_SC * dv1.y;
    v[6] = va1.z + S_SC * dv1.z; v[7] = va1.w + S_SC * dv1.w;

    float4 g0 = ((const float4*)ln_g_s)[ci], g1 = ((const float4*)ln_g_s)[ci + 1];
    float4 b0v = ((const float4*)ln_b_s)[ci], b1v = ((const float4*)ln_b_s)[ci + 1];
    float gs[8] = {g0.x, g0.y, g0.z, g0.w, g1.x, g1.y, g1.z, g1.w};
    float bs[8] = {b0v.x, b0v.y, b0v.z, b0v.w, b1v.x, b1v.y, b1v.z, b1v.w};

    float s8 = 0.0f;
    #pragma unroll
    for (int i = 0; i < 8; i++) s8 += v[i];
    float mean = warpsum(s8) * (1.0f / kD);
    float vs = 0.0f;
    #pragma unroll
    for (int i = 0; i < 8; i++) { v[i] -= mean; vs += v[i] * v[i]; }
    float rstd = rsqrtf(warpsum(vs) * (1.0f / kD) + EPSL);
    #pragma unroll
    for (int i = 0; i < 8; i++) v[i] = v[i] * rstd * gs[i] + bs[i];

    bool hit = false; float wj = 0.0f;
    #pragma unroll
    for (int j = 0; j < 4; j++)
        if (g_is[j] == n) { hit = true; wj = g_ws[j]; }
    if (hit) {
        float4 e0 = ((const float4*)g_esum)[ci], e1 = ((const float4*)g_esum)[ci + 1];
        float es[8] = {e0.x, e0.y, e0.z, e0.w, e1.x, e1.y, e1.z, e1.w};
        #pragma unroll
        for (int i = 0; i < 8; i++) v[i] += SC_X * wj * es[i];
    }

    s8 = 0.0f;
    #pragma unroll
    for (int i = 0; i < 8; i++) s8 += v[i];
    mean = warpsum(s8) * (1.0f / kD);
    vs = 0.0f;
    #pragma unroll
    for (int i = 0; i < 8; i++) { v[i] -= mean; vs += v[i] * v[i]; }
    rstd = rsqrtf(warpsum(vs) * (1.0f / kD) + EPSL);
    float4* outV = (float4*)(out + OFF_SVAL);
    outV[(size_t)row * 64 + ci] =
        make_float4(v[0] * rstd * gs[0] + bs[0], v[1] * rstd * gs[1] + bs[1],
                    v[2] * rstd * gs[2] + bs[2], v[3] * rstd * gs[3] + bs[3]);
    outV[(size_t)row * 64 + ci + 1] =
        make_float4(v[4] * rstd * gs[4] + bs[4], v[5] * rstd * gs[5] + bs[5],
                    v[6] * rstd * gs[6] + bs[6], v[7] * rstd * gs[7] + bs[7]);
}

// ---------------------------------------------------------------------------
// K3a: single-term bf16 tensor-core GEMM (candidate generation).
// K-chunk 64 (4 chunks, 8 barriers total), 2-stage cp.async, ldmatrix.
// 128x128 tile, 8 warps (4m x 2n), warp tile 32x64. SROW=72 (144B rows:
// bank step 4r -> conflict-free LDSM; 16B-aligned cp.async).
// Dynamic smem: 2 stages x 256 rows x 72 bf16 = 73728 B.
// ---------------------------------------------------------------------------
#define KC3   64
#define SROW3 72
#define STG3  (256 * SROW3)
#define K3_SMEM (2 * STG3 * (int)sizeof(__nv_bfloat16))

__global__ __launch_bounds__(256, 2) void k3a_gemm(const float* __restrict__ bias)
{
    extern __shared__ __align__(16) __nv_bfloat16 sm3[];
    int tid = threadIdx.x;
    int warp = tid >> 5, lane = tid & 31;
    int mw = warp & 3, nw = warp >> 2;
    int g = lane >> 2, t = lane & 3;
    int m0 = blockIdx.y * 128, n0 = blockIdx.x * 128;

    int a_row = mw * 32 + (lane & 15);                       // + mt*16
    int a_kh  = ((lane >> 4) & 1) * 8;                       // + kb
    int b_row = 128 + nw * 64 + (lane & 7) + ((lane >> 4) & 1) * 8;  // + p*16
    int b_kh  = ((lane >> 3) & 1) * 8;                       // + kb

    float acc[2][8][4];
    #pragma unroll
    for (int i = 0; i < 2; i++)
        #pragma unroll
        for (int j = 0; j < 8; j++)
            #pragma unroll
            for (int q = 0; q < 4; q++) acc[i][j][q] = 0.0f;

    auto load_stage = [&](int st, int k0) {
        __nv_bfloat16* base = sm3 + st * STG3;
        #pragma unroll
        for (int tt = 0; tt < 8; tt++) {
            int i = tid + tt * 256;
            int r = i >> 3, c16 = i & 7;
            const __nv_bfloat16* src = (r < 128)
                ? g_shi + (size_t)(m0 + r) * kD + k0 + c16 * 8
                : g_wth + (size_t)(n0 + r - 128) * kD + k0 + c16 * 8;
            cpasync16(base + r * SROW3 + c16 * 8, src);
        }
        asm volatile("cp.async.commit_group;");
    };

    load_stage(0, 0);

    #pragma unroll
    for (int ks = 0; ks < kD / KC3; ks++) {
        int st = ks & 1;
        if (ks + 1 < kD / KC3) {
            load_stage(st ^ 1, (ks + 1) * KC3);
            asm volatile("cp.async.wait_group 1;");
        } else {
            asm volatile("cp.async.wait_group 0;");
        }
        __syncthreads();
        __nv_bfloat16* base = sm3 + st * STG3;

        #pragma unroll
        for (int kb = 0; kb < KC3; kb += 16) {
            unsigned ah[2][4];
            #pragma unroll
            for (int mt = 0; mt < 2; mt++)
                ldsm4(ah[mt], base + (a_row + mt * 16) * SROW3 + kb + a_kh);
            #pragma unroll
            for (int p = 0; p < 4; p++) {
                unsigned bh[4];
                ldsm4(bh, base + (b_row + p * 16) * SROW3 + kb + b_kh);
                #pragma unroll
                for (int half = 0; half < 2; half++) {
                    int nt = p * 2 + half;
                    unsigned* bhp = bh + half * 2;
                    #pragma unroll
                    for (int mt = 0; mt < 2; mt++)
                        mma16816(acc[mt][nt], ah[mt], bhp);
                }
            }
        }
        __syncthreads();
    }

    float bcol[16];
    #pragma unroll
    for (int nt = 0; nt < 8; nt++) {
        int c = n0 + nw * 64 + nt * 8 + 2 * t;
        bcol[nt * 2]     = bias[c];
        bcol[nt * 2 + 1] = bias[c + 1];
    }

    float* svv = (float*)&sm3[0];
    int*   sii = (int*)(((char*)&sm3[0]) + 4096);

    #pragma unroll
    for (int mt = 0; mt < 2; mt++) {
        #pragma unroll
        for (int h = 0; h < 2; h++) {
            float tv[4] = {-INFINITY, -INFINITY, -INFINITY, -INFINITY};
            int   ti[4] = {0x7fffffff, 0x7fffffff, 0x7fffffff, 0x7fffffff};
            #pragma unroll
            for (int nt = 0; nt < 8; nt++) {
                #pragma unroll
                for (int e = 0; e < 2; e++) {
                    float val = acc[mt][nt][h * 2 + e] + bcol[nt * 2 + e];
                    int col = n0 + nw * 64 + nt * 8 + 2 * t + e;
                    ins4(val, col, tv, ti);
                }
            }
            #pragma unroll
            for (int msk = 1; msk <= 2; msk <<= 1) {
                float pv[4]; int pi[4];
                #pragma unroll
                for (int j = 0; j < 4; j++) {
                    pv[j] = __shfl_xor_sync(0xffffffffu, tv[j], msk);
                    pi[j] = __shfl_xor_sync(0xffffffffu, ti[j], msk);
                }
                #pragma unroll
                for (int j = 0; j < 4; j++) ins4(pv[j], pi[j], tv, ti);
            }
            if (t == 0) {
                int lrow2 = mw * 32 + mt * 16 + h * 8 + g;
                #pragma unroll
                for (int j = 0; j < 4; j++) {
                    svv[(lrow2 * 2 + nw) * 4 + j] = tv[j];
                    sii[(lrow2 * 2 + nw) * 4 + j] = ti[j];
                }
            }
        }
    }
    __syncthreads();
    if (tid < 128) {
        float tv[4]; int ti[4];
        #pragma unroll
        for (int j = 0; j < 4; j++) { tv[j] = svv[(tid * 2) * 4 + j]; ti[j] = sii[(tid * 2) * 4 + j]; }
        #pragma unroll
        for (int j = 0; j < 4; j++) ins4(svv[(tid * 2 + 1) * 4 + j], sii[(tid * 2 + 1) * 4 + j], tv, ti);
        size_t base = ((size_t)(m0 + tid) * 4 + blockIdx.x) * 4;
        #pragma unroll
        for (int j = 0; j < 4; j++) { g_candV[base + j] = tv[j]; g_candI[base + j] = ti[j]; }
    }
}

// ---------------------------------------------------------------------------
// K3b: rescore — merge 16 bf16 candidates -> top-8, recompute those 8 logits
// exactly in fp32, exact top-4 -> softmax -> bucket push. Warp per row.
// ---------------------------------------------------------------------------
__global__ __launch_bounds__(256) void k3b_rescore(
    const float* __restrict__ out, const float* __restrict__ bias)
{
    int warp = threadIdx.x >> 5, lane = threadIdx.x & 31;
    int row = blockIdx.x * 8 + warp;
    int b = row >> 13;

    float v = (lane < 16) ? g_candV[(size_t)row * 16 + lane] : -INFINITY;
    int  ix = (lane < 16) ? g_candI[(size_t)row * 16 + lane] : 0x7fffffff;

    int cand8[8];
    #pragma unroll
    for (int r = 0; r < 8; r++) {
        float mv = v; int mi = ix;
        #pragma unroll
        for (int off = 16; off > 0; off >>= 1) {
            float ov = __shfl_xor_sync(0xffffffffu, mv, off);
            int   oi = __shfl_xor_sync(0xffffffffu, mi, off);
            if (bet(ov, oi, mv, mi)) { mv = ov; mi = oi; }
        }
        cand8[r] = mi;
        if (ix == mi) v = -INFINITY;
    }

    const float4* ar = (const float4*)(out + OFF_SSTATE + (size_t)row * kD);
    float4 a0 = ar[lane * 2], a1 = ar[lane * 2 + 1];

    float ex[8];
    #pragma unroll
    for (int r = 0; r < 8; r++) {
        const float4* wr = (const float4*)(g_wtf + (size_t)cand8[r] * kD);
        float4 w0 = wr[lane * 2], w1 = wr[lane * 2 + 1];
        float p = a0.x * w0.x + a0.y * w0.y + a0.z * w0.z + a0.w * w0.w
                + a1.x * w1.x + a1.y * w1.y + a1.z * w1.z + a1.w * w1.w;
        ex[r] = warpsum(p) + bias[cand8[r]];
    }

    float tv[4] = {-INFINITY, -INFINITY, -INFINITY, -INFINITY};
    int   ti[4] = {0x7fffffff, 0x7fffffff, 0x7fffffff, 0x7fffffff};
    #pragma unroll
    for (int r = 0; r < 8; r++) ins4(ex[r], cand8[r], tv, ti);

    float mx = tv[0];
    float e0 = expf(tv[0] - mx), e1 = expf(tv[1] - mx);
    float e2 = expf(tv[2] - mx), e3 = expf(tv[3] - mx);
    float inv = 1.0f / (e0 + e1 + e2 + e3);
    if (lane < 4) {
        float ej = (lane == 0) ? e0 : (lane == 1) ? e1 : (lane == 2) ? e2 : e3;
        float wgt = SC_X * ej * inv;
        int bt = b * kNC + ti[lane];
        int pos = atomicAdd(&g_cnt[bt], 1);
        if (pos < CAP) {
            g_entR[(size_t)bt * CAP + pos] = row;
            g_entW[(size_t)bt * CAP + pos] = wgt;
        }
    }
}

// ---------------------------------------------------------------------------
// K3c: per-(b,target) gather-sum
// ---------------------------------------------------------------------------
__global__ __launch_bounds__(256) void k3c_gather(
    const float* __restrict__ out, const float* __restrict__ ln_b_c)
{
    int bt = blockIdx.x;
    int t = bt & (kNC - 1);
    int sub = threadIdx.x >> 6, c = threadIdx.x & 63;
    int n = min(g_cnt[bt], CAP);
    const float4* ssf = (const float4*)(out + OFF_SSTATE);
    const float4* svf = (const float4*)(out + OFF_SVAL);
    float4 aS = {0,0,0,0}, aV = {0,0,0,0};
    for (int i = sub; i < n; i += 4) {
        int r   = g_entR[(size_t)bt * CAP + i];
        float w = g_entW[(size_t)bt * CAP + i];
        float4 s = ssf[(size_t)r * 64 + c];
        float4 vv = svf[(size_t)r * 64 + c];
        aS.x += w * s.x;  aS.y += w * s.y;  aS.z += w * s.z;  aS.w += w * s.w;
        aV.x += w * vv.x; aV.y += w * vv.y; aV.z += w * vv.z; aV.w += w * vv.w;
    }
    __shared__ float4 shS[4][64], shV[4][64];
    shS[sub][c] = aS; shV[sub][c] = aV;
    __syncthreads();
    if (sub == 0) {
        float4 S = shS[0][c], V = shV[0][c];
        #pragma unroll
        for (int q = 1; q < 4; q++) {
            float4 s2 = shS[q][c], v2 = shV[q][c];
            S.x += s2.x; S.y += s2.y; S.z += s2.z; S.w += s2.w;
            V.x += v2.x; V.y += v2.y; V.z += v2.z; V.w += v2.w;
        }
        ((float4*)g_ncs)[(size_t)bt * 64 + c] = S;
        float4 nb = ((const float4*)ln_b_c)[c];
        V.x += nb.x; V.y += nb.y; V.z += nb.z; V.w += nb.w;
        #pragma unroll
        for (int j = 0; j < 4; j++)
            if (g_ic[j] == t) {
                float w = SC_B * g_wc[j];
                float4 es = ((const float4*)g_esum)[c];
                V.x += w * es.x; V.y += w * es.y; V.z += w * es.z; V.w += w * es.w;
            }
        ((float4*)g_ncv)[(size_t)bt * 64 + c] = V;
    }
}

// ---------------------------------------------------------------------------
// K4a: per-batch scores
// ---------------------------------------------------------------------------
__global__ __launch_bounds__(256) void k4a_scores(const float* __restrict__ wpc)
{
    int bb = blockIdx.z;
    int m0 = blockIdx.y * 64;
    int n0 = blockIdx.x * 64;
    const float* ncs = g_ncs + (size_t)bb * kNC * kD;
    __shared__ float As[16][64 + 4];
    __shared__ float Bs[16][64 + 4];
    int tid = threadIdx.x;
    int ty = tid / 16, tx = tid % 16;
    float acc[4][4] = {};
    int lrow = tid / 4;
    int lk = (tid % 4) * 4;
    for (int k0 = 0; k0 < kD; k0 += 16) {
        float4 av = *(const float4*)&ncs[(size_t)(m0 + lrow) * kD + k0 + lk];
        float4 bv = *(const float4*)&ncs[(size_t)(n0 + lrow) * kD + k0 + lk];
        float4 wv = *(const float4*)&wpc[k0 + lk];
        As[lk + 0][lrow] = av.x * wv.x; As[lk + 1][lrow] = av.y * wv.y;
        As[lk + 2][lrow] = av.z * wv.z; As[lk + 3][lrow] = av.w * wv.w;
        Bs[lk + 0][lrow] = bv.x; Bs[lk + 1][lrow] = bv.y;
        Bs[lk + 2][lrow] = bv.z; Bs[lk + 3][lrow] = bv.w;
        __syncthreads();
        #pragma unroll
        for (int kk = 0; kk < 16; kk++) {
            float ar[4], br[4];
            #pragma unroll
            for (int i = 0; i < 4; i++) ar[i] = As[kk][ty * 4 + i];
            #pragma unroll
            for (int j = 0; j < 4; j++) br[j] = Bs[kk][tx * 4 + j];
            #pragma unroll
            for (int i = 0; i < 4; i++)
                #pragma unroll
                for (int j = 0; j < 4; j++)
                    acc[i][j] += ar[i] * br[j];
        }
        __syncthreads();
    }
    #pragma unroll
    for (int i = 0; i < 4; i++)
        #pragma unroll
        for (int j = 0; j < 4; j++)
            g_scmat[(size_t)bb * kNC * kNC + (size_t)(m0 + ty * 4 + i) * kNC + (n0 + tx * 4 + j)] =
                acc[i][j] * INV_SQRT_D;
}

// ---------------------------------------------------------------------------
// K4b: per-(b,n) top-4, softmax, gather, tanh/LN finalize
// ---------------------------------------------------------------------------
__global__ __launch_bounds__(256) void k4b_final(
    const float* __restrict__ ln_g_c, const float* __restrict__ ln_b_c,
    float* __restrict__ out)
{
    int bn = blockIdx.x;
    int bb = bn / kNC;
    int d = threadIdx.x;
    const float* sc = g_scmat + (size_t)bn * kNC;
    __shared__ float sv[256]; __shared__ int si[256];
    __shared__ float red[256];
    __shared__ float topw[4]; __shared__ int topidx[4];

    float v0 = sc[d], v1 = sc[d + 256];
    bool t0 = false, t1 = false;
    for (int r = 0; r < 4; r++) {
        float bv = -INFINITY; int bi = 0x7fffffff;
        if (!t0) { bv = v0; bi = d; }
        if (!t1 && bet(v1, d + 256, bv, bi)) { bv = v1; bi = d + 256; }
        sv[d] = bv; si[d] = bi; __syncthreads();
        for (int s = 128; s > 0; s >>= 1) {
            if (d < s && bet(sv[d + s], si[d + s], sv[d], si[d])) {
                sv[d] = sv[d + s]; si[d] = si[d + s];
            }
            __syncthreads();
        }
        if (d == 0) { topw[r] = sv[0]; topidx[r] = si[0]; }
        __syncthreads();
        int widx = topidx[r];
        if (widx == d) t0 = true;
        if (widx == d + 256) t1 = true;
    }

    float mx = topw[0];
    float e[4]; float esum = 0.0f;
    #pragma unroll
    for (int j = 0; j < 4; j++) { e[j] = expf(topw[j] - mx); esum += e[j]; }
    float inv = 1.0f / esum;

    const float* ncsB = g_ncs + (size_t)bb * kNC * kD;
    const float* ncvB = g_ncv + (size_t)bb * kNC * kD;
    float ds = 0.0f, dv = 0.0f;
    #pragma unroll
    for (int j = 0; j < 4; j++) {
        int m = topidx[j];
        float a = e[j] * inv;
        ds += a * ncsB[(size_t)m * kD + d];
        dv += a * ncvB[(size_t)m * kD + d];
    }
    float spre = g_ncs[(size_t)bn * kD + d];
    float vpre = g_ncv[(size_t)bn * kD + d];

    out[OFF_NCS + (size_t)bn * kD + d] = tanhf(spre + SC_B * ds);

    auto bsum = [&](float x) -> float {
        red[d] = x; __syncthreads();
        for (int s = 128; s > 0; s >>= 1) {
            if (d < s) red[d] += red[d + s];
            __syncthreads();
        }
        float r = red[0]; __syncthreads(); return r;
    };
    float x = vpre + SC_B * dv;
    float m = bsum(x) * (1.0f / kD);
    float xd = x - m;
    float var = bsum(xd * xd) * (1.0f / kD);
    out[OFF_NCV + (size_t)bn * kD + d] = xd * rsqrtf(var + EPSL) * ln_g_c[d] + ln_b_c[d];
}

// ---------------------------------------------------------------------------
extern "C" void kernel_launch(void* const* d_in, const int* in_sizes, int n_in,
                              void* d_out, int out_size) {
    const float* s_state  = (const float*)d_in[0];
    const float* s_val    = (const float*)d_in[1];
    const float* w_pair_s = (const float*)d_in[2];
    const float* w_pair_c = (const float*)d_in[4];
    const float* b_expand = (const float*)d_in[6];
    const float* b_b2s    = (const float*)d_in[8];
    const float* b_comp   = (const float*)d_in[10];
    const float* W_s2b    = (const float*)d_in[11];
    const float* b_s2b    = (const float*)d_in[12];
    const float* ln_g_s   = (const float*)d_in[13];
    const float* ln_b_s   = (const float*)d_in[14];
    const float* ln_g_e   = (const float*)d_in[15];
    const float* ln_b_e   = (const float*)d_in[16];
    const float* ln_g_c   = (const float*)d_in[17];
    const float* ln_b_c   = (const float*)d_in[18];
    float* out = (float*)d_out;

    static int smem_set = 0;
    if (!smem_set) {
        cudaFuncSetAttribute(k3a_gemm, cudaFuncAttributeMaxDynamicSharedMemorySize, K3_SMEM);
        smem_set = 1;
    }

    k0_prep<<<1, 256>>>(b_expand, b_b2s, b_comp, ln_b_c, ln_g_e, ln_b_e);
    k1_splitW<<<dim3(kNC / 32, kD / 32), dim3(32, 32)>>>(W_s2b);
    k2_window<<<kM / 8, 256>>>(s_state, s_val, w_pair_s, ln_g_s, ln_b_s, out);
    k3a_gemm<<<dim3(kNC / 128, kM / 128), 256, K3_SMEM>>>(b_s2b);
    k3b_rescore<<<kM / 8, 256>>>(out, b_s2b);
    k3c_gather<<<kB * kNC, 256>>>(out, ln_b_c);
    k4a_scores<<<dim3(kNC / 64, kNC / 64, kB), 256>>>(w_pair_c);
    k4b_final<<<kB * kNC, 256>>>(ln_g_c, ln_b_c, out);
}

// round 12
// speedup vs baseline: 1.1318x; 1.0489x over previous
#include <cuda_runtime.h>
#include <cuda_bf16.h>
#include <math.h>
#include <cstdint>

// ---------------------------------------------------------------------------
#define kD   256
#define kB   4
#define kS   8192
#define kNE  2048
#define kNC  512
#define kWIN 4
#define kM   (kB * kS)

#define S_SC       0.25f
#define SC_B       0.2f
#define SC_X       0.075f
#define EPSL       1e-5f
#define INV_SQRT_D 0.0625f
#define CAP        2048

#define OFF_SSTATE ((size_t)0)
#define OFF_SVAL   ((size_t)kB * kS * kD)
#define OFF_NCS    ((size_t)2 * kB * kS * kD)
#define OFF_NCV    (OFF_NCS + (size_t)kB * kNC * kD)

// ---------------------------------------------------------------------------
__device__ float g_scmat[(size_t)kB * kNC * kNC];
__device__ int   g_entR[(size_t)kB * kNC * CAP];
__device__ float g_entW[(size_t)kB * kNC * CAP];
__device__ int   g_cnt[kB * kNC];
__device__ float g_esum[kD];
__device__ int   g_is[4]; __device__ float g_ws[4];
__device__ int   g_ic[4]; __device__ float g_wc[4];
__device__ float g_ncs[(size_t)kB * kNC * kD];
__device__ float g_ncv[(size_t)kB * kNC * kD];

__device__ __nv_bfloat16 g_shi[(size_t)kM * kD];    // bf16 of s_state_final
__device__ __nv_bfloat16 g_wth[(size_t)kNC * kD];   // W_s2b^T bf16 [512][256]
__device__ float         g_wtf[(size_t)kNC * kD];   // W_s2b^T fp32 [512][256]
__device__ float g_candV[(size_t)kM * 32];          // 8 slabs x 4 candidates
__device__ int   g_candI[(size_t)kM * 32];

__device__ __forceinline__ bool bet(float v, int i, float bv, int bi) {
    return (v > bv) || (v == bv && i < bi);
}

__device__ __forceinline__ float warpsum(float v) {
    #pragma unroll
    for (int off = 16; off > 0; off >>= 1) v += __shfl_xor_sync(0xffffffffu, v, off);
    return v;
}

__device__ __forceinline__ void ins4(float v, int i, float* tv, int* ti) {
    if (bet(v, i, tv[3], ti[3])) {
        tv[3] = v; ti[3] = i;
        #pragma unroll
        for (int q = 3; q > 0; q--) {
            if (bet(tv[q], ti[q], tv[q - 1], ti[q - 1])) {
                float fv = tv[q]; tv[q] = tv[q - 1]; tv[q - 1] = fv;
                int   fi = ti[q]; ti[q] = ti[q - 1]; ti[q - 1] = fi;
            } else break;
        }
    }
}

__device__ __forceinline__ void mma16816(float* c, const unsigned* a, const unsigned* b) {
    asm volatile(
        "mma.sync.aligned.m16n8k16.row.col.f32.bf16.bf16.f32 "
        "{%0,%1,%2,%3}, {%4,%5,%6,%7}, {%8,%9}, {%0,%1,%2,%3};"
        : "+f"(c[0]), "+f"(c[1]), "+f"(c[2]), "+f"(c[3])
        : "r"(a[0]), "r"(a[1]), "r"(a[2]), "r"(a[3]), "r"(b[0]), "r"(b[1]));
}

__device__ __forceinline__ void ldsm4(unsigned* r, const void* p) {
    unsigned a = (unsigned)__cvta_generic_to_shared(p);
    asm volatile("ldmatrix.sync.aligned.m8n8.x4.shared.b16 {%0,%1,%2,%3}, [%4];"
        : "=r"(r[0]), "=r"(r[1]), "=r"(r[2]), "=r"(r[3]) : "r"(a));
}

__device__ __forceinline__ void cpasync16(void* dst, const void* src) {
    unsigned sd = (unsigned)__cvta_generic_to_shared(dst);
    asm volatile("cp.async.cg.shared.global [%0], [%1], 16;" :: "r"(sd), "l"(src));
}

// ---------------------------------------------------------------------------
// K0: prep (top4 of biases, collapsed e_val algebra, zero counters)
// ---------------------------------------------------------------------------
__global__ __launch_bounds__(256) void k0_prep(
    const float* __restrict__ b_expand, const float* __restrict__ b_b2s,
    const float* __restrict__ b_comp,   const float* __restrict__ ln_b_c,
    const float* __restrict__ ln_g_e,   const float* __restrict__ ln_b_e)
{
    __shared__ float sv[256];  __shared__ int si[256];
    __shared__ float red[256];
    __shared__ float tv[4];    __shared__ int ti[4];
    __shared__ float we[4];    __shared__ int ie[4];
    int tid = threadIdx.x;

    for (int j = tid; j < kB * kNC; j += 256) g_cnt[j] = 0;

    auto top4 = [&](const float* x, int n) {
        for (int r = 0; r < 4; r++) {
            float bv = -INFINITY; int bi = 0x7fffffff;
            for (int j = tid; j < n; j += 256) {
                bool skip = false;
                for (int q = 0; q < r; q++) if (ti[q] == j) skip = true;
                float v = x[j];
                if (!skip && bet(v, j, bv, bi)) { bv = v; bi = j; }
            }
            sv[tid] = bv; si[tid] = bi; __syncthreads();
            for (int s = 128; s > 0; s >>= 1) {
                if (tid < s && bet(sv[tid + s], si[tid + s], sv[tid], si[tid])) {
                    sv[tid] = sv[tid + s]; si[tid] = si[tid + s];
                }
                __syncthreads();
            }
            if (tid == 0) { tv[r] = sv[0]; ti[r] = si[0]; }
            __syncthreads();
        }
    };
    auto softmax4 = [&](float* wout) {
        if (tid == 0) {
            float m = tv[0];
            float e0 = expf(tv[0] - m), e1 = expf(tv[1] - m);
            float e2 = expf(tv[2] - m), e3 = expf(tv[3] - m);
            float inv = 1.0f / (e0 + e1 + e2 + e3);
            wout[0] = e0 * inv; wout[1] = e1 * inv;
            wout[2] = e2 * inv; wout[3] = e3 * inv;
        }
        __syncthreads();
    };

    top4(b_expand, kNE); softmax4(we);
    if (tid < 4) ie[tid] = ti[tid];
    __syncthreads();
    top4(b_b2s, kS); softmax4(g_ws);
    if (tid < 4) g_is[tid] = ti[tid];
    __syncthreads();
    top4(b_comp, kNC); softmax4(g_wc);
    if (tid < 4) g_ic[tid] = ti[tid];
    __syncthreads();

    int d = tid;
    float cval = ln_b_c[d];
    float rowval[4];
    float dvE = 0.0f;
    #pragma unroll
    for (int j = 0; j < 4; j++) {
        rowval[j] = SC_B * (float)kNC * we[j] * cval;
        if (ie[j] < 4) dvE += rowval[j];
    }
    dvE *= 0.25f;
    float base = SC_B * dvE;

    auto bsum = [&](float x) -> float {
        red[tid] = x; __syncthreads();
        for (int s = 128; s > 0; s >>= 1) {
            if (tid < s) red[tid] += red[tid + s];
            __syncthreads();
        }
        float r = red[0]; __syncthreads(); return r;
    };
    float ge = ln_g_e[d], be = ln_b_e[d];
    auto LN_e = [&](float x) -> float {
        float m  = bsum(x) * (1.0f / kD);
        float dv = x - m;
        float var = bsum(dv * dv) * (1.0f / kD);
        return dv * rsqrtf(var + EPSL) * ge + be;
    };

    float other = LN_e(base);
    float esum = (float)(kNE - 4) * other;
    #pragma unroll
    for (int j = 0; j < 4; j++) esum += LN_e(rowval[j] + base);
    g_esum[d] = esum;
}

// ---------------------------------------------------------------------------
// K1: W_s2b -> transposed bf16 [512 n][256 k] + transposed fp32 copy
// ---------------------------------------------------------------------------
__global__ void k1_splitW(const float* __restrict__ W)
{
    __shared__ float tile[32][33];
    int n0 = blockIdx.x * 32, k0 = blockIdx.y * 32;
    int tx = threadIdx.x, ty = threadIdx.y;
    tile[ty][tx] = W[(size_t)(k0 + ty) * kNC + n0 + tx];
    __syncthreads();
    float x = tile[tx][ty];                    // W[k0+tx][n0+ty]
    g_wth[(size_t)(n0 + ty) * kD + k0 + tx] = __float2bfloat16(x);
    g_wtf[(size_t)(n0 + ty) * kD + k0 + tx] = x;
}

// ---------------------------------------------------------------------------
// K2: smem-tiled window prop (8 rows/block), emits bf16 of final state
// ---------------------------------------------------------------------------
__global__ __launch_bounds__(256) void k2_window(
    const float* __restrict__ s_state, const float* __restrict__ s_val,
    const float* __restrict__ w_pair_s,
    const float* __restrict__ ln_g_s, const float* __restrict__ ln_b_s,
    float* __restrict__ out)
{
    __shared__ float4 st_s[16][64];
    __shared__ float4 vl_s[16][64];

    int tid = threadIdx.x;
    int warp = tid >> 5, lane = tid & 31;
    int row0 = blockIdx.x * 8;
    int b = row0 >> 13, n0 = row0 & (kS - 1);
    const float4* st4 = (const float4*)(s_state + (size_t)b * kS * kD);
    const float4* vl4 = (const float4*)(s_val   + (size_t)b * kS * kD);

    #pragma unroll
    for (int t = 0; t < 8; t++) {
        int i = tid + t * 256;
        int arr = i >> 10, slot = (i >> 6) & 15, c = i & 63;
        int gr = min(max(n0 - 4 + slot, 0), kS - 1);
        float4 v = (arr ? vl4 : st4)[(size_t)gr * 64 + c];
        if (arr) vl_s[slot][c] = v; else st_s[slot][c] = v;
    }
    __syncthreads();

    int n = n0 + warp;
    int row = row0 + warp;
    int ci = lane * 2;

    float4 w0 = ((const float4*)w_pair_s)[ci];
    float4 w1 = ((const float4*)w_pair_s)[ci + 1];
    float4 s0a = st_s[warp + 4][ci];
    float4 s0b = st_s[warp + 4][ci + 1];
    float4 q0, q1;
    q0.x = s0a.x * w0.x; q0.y = s0a.y * w0.y; q0.z = s0a.z * w0.z; q0.w = s0a.w * w0.w;
    q1.x = s0b.x * w1.x; q1.y = s0b.y * w1.y; q1.z = s0b.z * w1.z; q1.w = s0b.w * w1.w;

    float scw[9];
    #pragma unroll
    for (int k = 0; k < 9; k++) {
        int j = n + k - kWIN;
        bool valid = ((unsigned)j < (unsigned)kS);
        float4 na = st_s[warp + k][ci];
        float4 nb = st_s[warp + k][ci + 1];
        float p = q0.x * na.x + q0.y * na.y + q0.z * na.z + q0.w * na.w
                + q1.x * nb.x + q1.y * nb.y + q1.z * nb.z + q1.w * nb.w;
        p = warpsum(p);
        scw[k] = valid ? p * INV_SQRT_D : -1e30f;
    }
    float mx = scw[0];
    #pragma unroll
    for (int k = 1; k < 9; k++) mx = fmaxf(mx, scw[k]);
    float asum = 0.0f;
    #pragma unroll
    for (int k = 0; k < 9; k++) { scw[k] = expf(scw[k] - mx); asum += scw[k]; }
    float ainv = 1.0f / asum;

    float4 ds0 = {0,0,0,0}, ds1 = {0,0,0,0}, dv0 = {0,0,0,0}, dv1 = {0,0,0,0};
    #pragma unroll
    for (int k = 0; k < 9; k++) {
        float a = scw[k] * ainv;
        float4 na = st_s[warp + k][ci];
        float4 nb = st_s[warp + k][ci + 1];
        float4 va = vl_s[warp + k][ci];
        float4 vb = vl_s[warp + k][ci + 1];
        ds0.x += a * na.x; ds0.y += a * na.y; ds0.z += a * na.z; ds0.w += a * na.w;
        ds1.x += a * nb.x; ds1.y += a * nb.y; ds1.z += a * nb.z; ds1.w += a * nb.w;
        dv0.x += a * va.x; dv0.y += a * va.y; dv0.z += a * va.z; dv0.w += a * va.w;
        dv1.x += a * vb.x; dv1.y += a * vb.y; dv1.z += a * vb.z; dv1.w += a * vb.w;
    }

    float sv0[8] = {s0a.x, s0a.y, s0a.z, s0a.w, s0b.x, s0b.y, s0b.z, s0b.w};
    float dss[8] = {ds0.x, ds0.y, ds0.z, ds0.w, ds1.x, ds1.y, ds1.z, ds1.w};
    float sq[8];
    #pragma unroll
    for (int i = 0; i < 8; i++) sq[i] = tanhf(tanhf(sv0[i] + S_SC * dss[i]));

    float4* outS = (float4*)(out + OFF_SSTATE);
    outS[(size_t)row * 64 + ci]     = make_float4(sq[0], sq[1], sq[2], sq[3]);
    outS[(size_t)row * 64 + ci + 1] = make_float4(sq[4], sq[5], sq[6], sq[7]);

    uint4 hw;
    unsigned* hwp = (unsigned*)&hw;
    #pragma unroll
    for (int i = 0; i < 4; i++) {
        __nv_bfloat16 ha = __float2bfloat16(sq[2 * i]);
        __nv_bfloat16 hc = __float2bfloat16(sq[2 * i + 1]);
        hwp[i] = ((unsigned)__bfloat16_as_ushort(hc) << 16) | __bfloat16_as_ushort(ha);
    }
    *(uint4*)&g_shi[(size_t)row * kD + lane * 8] = hw;

    float4 va0 = vl_s[warp + 4][ci];
    float4 va1 = vl_s[warp + 4][ci + 1];
    float v[8];
    v[0] = va0.x + S_SC * dv0.x; v[1] = va0.y + S_SC * dv0.y;
    v[2] = va0.z + S_SC * dv0.z; v[3] = va0.w + S_SC * dv0.w;
    v[4] = va1.x + S_SC * dv1.x; v[5] = va1.y + S_SC * dv1.y;
    v[6] = va1.z + S_SC * dv1.z; v[7] = va1.w + S_SC * dv1.w;

    float4 g0 = ((const float4*)ln_g_s)[ci], g1 = ((const float4*)ln_g_s)[ci + 1];
    float4 b0v = ((const float4*)ln_b_s)[ci], b1v = ((const float4*)ln_b_s)[ci + 1];
    float gs[8] = {g0.x, g0.y, g0.z, g0.w, g1.x, g1.y, g1.z, g1.w};
    float bs[8] = {b0v.x, b0v.y, b0v.z, b0v.w, b1v.x, b1v.y, b1v.z, b1v.w};

    float s8 = 0.0f;
    #pragma unroll
    for (int i = 0; i < 8; i++) s8 += v[i];
    float mean = warpsum(s8) * (1.0f / kD);
    float vs = 0.0f;
    #pragma unroll
    for (int i = 0; i < 8; i++) { v[i] -= mean; vs += v[i] * v[i]; }
    float rstd = rsqrtf(warpsum(vs) * (1.0f / kD) + EPSL);
    #pragma unroll
    for (int i = 0; i < 8; i++) v[i] = v[i] * rstd * gs[i] + bs[i];

    bool hit = false; float wj = 0.0f;
    #pragma unroll
    for (int j = 0; j < 4; j++)
        if (g_is[j] == n) { hit = true; wj = g_ws[j]; }
    if (hit) {
        float4 e0 = ((const float4*)g_esum)[ci], e1 = ((const float4*)g_esum)[ci + 1];
        float es[8] = {e0.x, e0.y, e0.z, e0.w, e1.x, e1.y, e1.z, e1.w};
        #pragma unroll
        for (int i = 0; i < 8; i++) v[i] += SC_X * wj * es[i];
    }

    s8 = 0.0f;
    #pragma unroll
    for (int i = 0; i < 8; i++) s8 += v[i];
    mean = warpsum(s8) * (1.0f / kD);
    vs = 0.0f;
    #pragma unroll
    for (int i = 0; i < 8; i++) { v[i] -= mean; vs += v[i] * v[i]; }
    rstd = rsqrtf(warpsum(vs) * (1.0f / kD) + EPSL);
    float4* outV = (float4*)(out + OFF_SVAL);
    outV[(size_t)row * 64 + ci] =
        make_float4(v[0] * rstd * gs[0] + bs[0], v[1] * rstd * gs[1] + bs[1],
                    v[2] * rstd * gs[2] + bs[2], v[3] * rstd * gs[3] + bs[3]);
    outV[(size_t)row * 64 + ci + 1] =
        make_float4(v[4] * rstd * gs[4] + bs[4], v[5] * rstd * gs[5] + bs[5],
                    v[6] * rstd * gs[6] + bs[6], v[7] * rstd * gs[7] + bs[7]);
}

// ---------------------------------------------------------------------------
// K3a: single-term bf16 GEMM, occupancy-optimized: CTA tile 128x64,
// warp tile 32x32 (acc 32 regs), launch_bounds(256,3) -> 24 warps/SM.
// K-chunk 64, 2-stage cp.async, ldmatrix. SROW=72 rows (A 128 + B 64 = 192).
// Dynamic smem: 2 x 192 x 72 bf16 = 55296 B.
// ---------------------------------------------------------------------------
#define KC3   64
#define SROW3 72
#define STG3  (192 * SROW3)
#define K3_SMEM (2 * STG3 * (int)sizeof(__nv_bfloat16))

__global__ __launch_bounds__(256, 3) void k3a_gemm(const float* __restrict__ bias)
{
    extern __shared__ __align__(16) __nv_bfloat16 sm3[];
    int tid = threadIdx.x;
    int warp = tid >> 5, lane = tid & 31;
    int mw = warp & 3, nw = warp >> 2;      // 4 m-warps x 2 n-warps
    int g = lane >> 2, t = lane & 3;
    int m0 = blockIdx.y * 128, n0 = blockIdx.x * 64;

    int a_row = mw * 32 + (lane & 15);                          // + mt*16
    int a_kh  = ((lane >> 4) & 1) * 8;
    int b_row = 128 + nw * 32 + (lane & 7) + ((lane >> 4) & 1) * 8;  // + p*16
    int b_kh  = ((lane >> 3) & 1) * 8;

    float acc[2][4][4];
    #pragma unroll
    for (int i = 0; i < 2; i++)
        #pragma unroll
        for (int j = 0; j < 4; j++)
            #pragma unroll
            for (int q = 0; q < 4; q++) acc[i][j][q] = 0.0f;

    auto load_stage = [&](int st, int k0) {
        __nv_bfloat16* base = sm3 + st * STG3;
        #pragma unroll
        for (int tt = 0; tt < 6; tt++) {
            int i = tid + tt * 256;
            int r = i >> 3, c16 = i & 7;
            const __nv_bfloat16* src = (r < 128)
                ? g_shi + (size_t)(m0 + r) * kD + k0 + c16 * 8
                : g_wth + (size_t)(n0 + r - 128) * kD + k0 + c16 * 8;
            cpasync16(base + r * SROW3 + c16 * 8, src);
        }
        asm volatile("cp.async.commit_group;");
    };

    load_stage(0, 0);

    #pragma unroll
    for (int ks = 0; ks < kD / KC3; ks++) {
        int st = ks & 1;
        if (ks + 1 < kD / KC3) {
            load_stage(st ^ 1, (ks + 1) * KC3);
            asm volatile("cp.async.wait_group 1;");
        } else {
            asm volatile("cp.async.wait_group 0;");
        }
        __syncthreads();
        __nv_bfloat16* base = sm3 + st * STG3;

        #pragma unroll
        for (int kb = 0; kb < KC3; kb += 16) {
            unsigned ah[2][4];
            #pragma unroll
            for (int mt = 0; mt < 2; mt++)
                ldsm4(ah[mt], base + (a_row + mt * 16) * SROW3 + kb + a_kh);
            #pragma unroll
            for (int p = 0; p < 2; p++) {
                unsigned bh[4];
                ldsm4(bh, base + (b_row + p * 16) * SROW3 + kb + b_kh);
                #pragma unroll
                for (int half = 0; half < 2; half++) {
                    int nt = p * 2 + half;
                    unsigned* bhp = bh + half * 2;
                    #pragma unroll
                    for (int mt = 0; mt < 2; mt++)
                        mma16816(acc[mt][nt], ah[mt], bhp);
                }
            }
        }
        __syncthreads();
    }

    float bcol[8];
    #pragma unroll
    for (int nt = 0; nt < 4; nt++) {
        int c = n0 + nw * 32 + nt * 8 + 2 * t;
        bcol[nt * 2]     = bias[c];
        bcol[nt * 2 + 1] = bias[c + 1];
    }

    float* svv = (float*)&sm3[0];
    int*   sii = (int*)(((char*)&sm3[0]) + 4096);

    #pragma unroll
    for (int mt = 0; mt < 2; mt++) {
        #pragma unroll
        for (int h = 0; h < 2; h++) {
            float tv[4] = {-INFINITY, -INFINITY, -INFINITY, -INFINITY};
            int   ti[4] = {0x7fffffff, 0x7fffffff, 0x7fffffff, 0x7fffffff};
            #pragma unroll
            for (int nt = 0; nt < 4; nt++) {
                #pragma unroll
                for (int e = 0; e < 2; e++) {
                    float val = acc[mt][nt][h * 2 + e] + bcol[nt * 2 + e];
                    int col = n0 + nw * 32 + nt * 8 + 2 * t + e;
                    ins4(val, col, tv, ti);
                }
            }
            #pragma unroll
            for (int msk = 1; msk <= 2; msk <<= 1) {
                float pv[4]; int pi[4];
                #pragma unroll
                for (int j = 0; j < 4; j++) {
                    pv[j] = __shfl_xor_sync(0xffffffffu, tv[j], msk);
                    pi[j] = __shfl_xor_sync(0xffffffffu, ti[j], msk);
                }
                #pragma unroll
                for (int j = 0; j < 4; j++) ins4(pv[j], pi[j], tv, ti);
            }
            if (t == 0) {
                int lrow2 = mw * 32 + mt * 16 + h * 8 + g;
                #pragma unroll
                for (int j = 0; j < 4; j++) {
                    svv[(lrow2 * 2 + nw) * 4 + j] = tv[j];
                    sii[(lrow2 * 2 + nw) * 4 + j] = ti[j];
                }
            }
        }
    }
    __syncthreads();
    if (tid < 128) {
        float tv[4]; int ti[4];
        #pragma unroll
        for (int j = 0; j < 4; j++) { tv[j] = svv[(tid * 2) * 4 + j]; ti[j] = sii[(tid * 2) * 4 + j]; }
        #pragma unroll
        for (int j = 0; j < 4; j++) ins4(svv[(tid * 2 + 1) * 4 + j], sii[(tid * 2 + 1) * 4 + j], tv, ti);
        size_t base = ((size_t)(m0 + tid) * 8 + blockIdx.x) * 4;
        #pragma unroll
        for (int j = 0; j < 4; j++) { g_candV[base + j] = tv[j]; g_candI[base + j] = ti[j]; }
    }
}

// ---------------------------------------------------------------------------
// K3b: rescore — merge 32 bf16 candidates -> top-8, recompute those 8 logits
// exactly in fp32, exact top-4 -> softmax -> bucket push. Warp per row.
// ---------------------------------------------------------------------------
__global__ __launch_bounds__(256) void k3b_rescore(
    const float* __restrict__ out, const float* __restrict__ bias)
{
    int warp = threadIdx.x >> 5, lane = threadIdx.x & 31;
    int row = blockIdx.x * 8 + warp;
    int b = row >> 13;

    float v = g_candV[(size_t)row * 32 + lane];
    int  ix = g_candI[(size_t)row * 32 + lane];

    int cand8[8];
    #pragma unroll
    for (int r = 0; r < 8; r++) {
        float mv = v; int mi = ix;
        #pragma unroll
        for (int off = 16; off > 0; off >>= 1) {
            float ov = __shfl_xor_sync(0xffffffffu, mv, off);
            int   oi = __shfl_xor_sync(0xffffffffu, mi, off);
            if (bet(ov, oi, mv, mi)) { mv = ov; mi = oi; }
        }
        cand8[r] = mi;
        if (ix == mi) v = -INFINITY;
    }

    const float4* ar = (const float4*)(out + OFF_SSTATE + (size_t)row * kD);
    float4 a0 = ar[lane * 2], a1 = ar[lane * 2 + 1];

    float ex[8];
    #pragma unroll
    for (int r = 0; r < 8; r++) {
        const float4* wr = (const float4*)(g_wtf + (size_t)cand8[r] * kD);
        float4 w0 = wr[lane * 2], w1 = wr[lane * 2 + 1];
        float p = a0.x * w0.x + a0.y * w0.y + a0.z * w0.z + a0.w * w0.w
                + a1.x * w1.x + a1.y * w1.y + a1.z * w1.z + a1.w * w1.w;
        ex[r] = warpsum(p) + bias[cand8[r]];
    }

    float tv[4] = {-INFINITY, -INFINITY, -INFINITY, -INFINITY};
    int   ti[4] = {0x7fffffff, 0x7fffffff, 0x7fffffff, 0x7fffffff};
    #pragma unroll
    for (int r = 0; r < 8; r++) ins4(ex[r], cand8[r], tv, ti);

    float mx = tv[0];
    float e0 = expf(tv[0] - mx), e1 = expf(tv[1] - mx);
    float e2 = expf(tv[2] - mx), e3 = expf(tv[3] - mx);
    float inv = 1.0f / (e0 + e1 + e2 + e3);
    if (lane < 4) {
        float ej = (lane == 0) ? e0 : (lane == 1) ? e1 : (lane == 2) ? e2 : e3;
        float wgt = SC_X * ej * inv;
        int bt = b * kNC + ti[lane];
        int pos = atomicAdd(&g_cnt[bt], 1);
        if (pos < CAP) {
            g_entR[(size_t)bt * CAP + pos] = row;
            g_entW[(size_t)bt * CAP + pos] = wgt;
        }
    }
}

// ---------------------------------------------------------------------------
// K3c: per-(b,target) gather-sum
// ---------------------------------------------------------------------------
__global__ __launch_bounds__(256) void k3c_gather(
    const float* __restrict__ out, const float* __restrict__ ln_b_c)
{
    int bt = blockIdx.x;
    int t = bt & (kNC - 1);
    int sub = threadIdx.x >> 6, c = threadIdx.x & 63;
    int n = min(g_cnt[bt], CAP);
    const float4* ssf = (const float4*)(out + OFF_SSTATE);
    const float4* svf = (const float4*)(out + OFF_SVAL);
    float4 aS = {0,0,0,0}, aV = {0,0,0,0};
    for (int i = sub; i < n; i += 4) {
        int r   = g_entR[(size_t)bt * CAP + i];
        float w = g_entW[(size_t)bt * CAP + i];
        float4 s = ssf[(size_t)r * 64 + c];
        float4 vv = svf[(size_t)r * 64 + c];
        aS.x += w * s.x;  aS.y += w * s.y;  aS.z += w * s.z;  aS.w += w * s.w;
        aV.x += w * vv.x; aV.y += w * vv.y; aV.z += w * vv.z; aV.w += w * vv.w;
    }
    __shared__ float4 shS[4][64], shV[4][64];
    shS[sub][c] = aS; shV[sub][c] = aV;
    __syncthreads();
    if (sub == 0) {
        float4 S = shS[0][c], V = shV[0][c];
        #pragma unroll
        for (int q = 1; q < 4; q++) {
            float4 s2 = shS[q][c], v2 = shV[q][c];
            S.x += s2.x; S.y += s2.y; S.z += s2.z; S.w += s2.w;
            V.x += v2.x; V.y += v2.y; V.z += v2.z; V.w += v2.w;
        }
        ((float4*)g_ncs)[(size_t)bt * 64 + c] = S;
        float4 nb = ((const float4*)ln_b_c)[c];
        V.x += nb.x; V.y += nb.y; V.z += nb.z; V.w += nb.w;
        #pragma unroll
        for (int j = 0; j < 4; j++)
            if (g_ic[j] == t) {
                float w = SC_B * g_wc[j];
                float4 es = ((const float4*)g_esum)[c];
                V.x += w * es.x; V.y += w * es.y; V.z += w * es.z; V.w += w * es.w;
            }
        ((float4*)g_ncv)[(size_t)bt * 64 + c] = V;
    }
}

// ---------------------------------------------------------------------------
// K4a: per-batch scores
// ---------------------------------------------------------------------------
__global__ __launch_bounds__(256) void k4a_scores(const float* __restrict__ wpc)
{
    int bb = blockIdx.z;
    int m0 = blockIdx.y * 64;
    int n0 = blockIdx.x * 64;
    const float* ncs = g_ncs + (size_t)bb * kNC * kD;
    __shared__ float As[16][64 + 4];
    __shared__ float Bs[16][64 + 4];
    int tid = threadIdx.x;
    int ty = tid / 16, tx = tid % 16;
    float acc[4][4] = {};
    int lrow = tid / 4;
    int lk = (tid % 4) * 4;
    for (int k0 = 0; k0 < kD; k0 += 16) {
        float4 av = *(const float4*)&ncs[(size_t)(m0 + lrow) * kD + k0 + lk];
        float4 bv = *(const float4*)&ncs[(size_t)(n0 + lrow) * kD + k0 + lk];
        float4 wv = *(const float4*)&wpc[k0 + lk];
        As[lk + 0][lrow] = av.x * wv.x; As[lk + 1][lrow] = av.y * wv.y;
        As[lk + 2][lrow] = av.z * wv.z; As[lk + 3][lrow] = av.w * wv.w;
        Bs[lk + 0][lrow] = bv.x; Bs[lk + 1][lrow] = bv.y;
        Bs[lk + 2][lrow] = bv.z; Bs[lk + 3][lrow] = bv.w;
        __syncthreads();
        #pragma unroll
        for (int kk = 0; kk < 16; kk++) {
            float ar[4], br[4];
            #pragma unroll
            for (int i = 0; i < 4; i++) ar[i] = As[kk][ty * 4 + i];
            #pragma unroll
            for (int j = 0; j < 4; j++) br[j] = Bs[kk][tx * 4 + j];
            #pragma unroll
            for (int i = 0; i < 4; i++)
                #pragma unroll
                for (int j = 0; j < 4; j++)
                    acc[i][j] += ar[i] * br[j];
        }
        __syncthreads();
    }
    #pragma unroll
    for (int i = 0; i < 4; i++)
        #pragma unroll
        for (int j = 0; j < 4; j++)
            g_scmat[(size_t)bb * kNC * kNC + (size_t)(m0 + ty * 4 + i) * kNC + (n0 + tx * 4 + j)] =
                acc[i][j] * INV_SQRT_D;
}

// ---------------------------------------------------------------------------
// K4b: per-(b,n) top-4, softmax, gather, tanh/LN finalize
// ---------------------------------------------------------------------------
__global__ __launch_bounds__(256) void k4b_final(
    const float* __restrict__ ln_g_c, const float* __restrict__ ln_b_c,
    float* __restrict__ out)
{
    int bn = blockIdx.x;
    int bb = bn / kNC;
    int d = threadIdx.x;
    const float* sc = g_scmat + (size_t)bn * kNC;
    __shared__ float sv[256]; __shared__ int si[256];
    __shared__ float red[256];
    __shared__ float topw[4]; __shared__ int topidx[4];

    float v0 = sc[d], v1 = sc[d + 256];
    bool t0 = false, t1 = false;
    for (int r = 0; r < 4; r++) {
        float bv = -INFINITY; int bi = 0x7fffffff;
        if (!t0) { bv = v0; bi = d; }
        if (!t1 && bet(v1, d + 256, bv, bi)) { bv = v1; bi = d + 256; }
        sv[d] = bv; si[d] = bi; __syncthreads();
        for (int s = 128; s > 0; s >>= 1) {
            if (d < s && bet(sv[d + s], si[d + s], sv[d], si[d])) {
                sv[d] = sv[d + s]; si[d] = si[d + s];
            }
            __syncthreads();
        }
        if (d == 0) { topw[r] = sv[0]; topidx[r] = si[0]; }
        __syncthreads();
        int widx = topidx[r];
        if (widx == d) t0 = true;
        if (widx == d + 256) t1 = true;
    }

    float mx = topw[0];
    float e[4]; float esum = 0.0f;
    #pragma unroll
    for (int j = 0; j < 4; j++) { e[j] = expf(topw[j] - mx); esum += e[j]; }
    float inv = 1.0f / esum;

    const float* ncsB = g_ncs + (size_t)bb * kNC * kD;
    const float* ncvB = g_ncv + (size_t)bb * kNC * kD;
    float ds = 0.0f, dv = 0.0f;
    #pragma unroll
    for (int j = 0; j < 4; j++) {
        int m = topidx[j];
        float a = e[j] * inv;
        ds += a * ncsB[(size_t)m * kD + d];
        dv += a * ncvB[(size_t)m * kD + d];
    }
    float spre = g_ncs[(size_t)bn * kD + d];
    float vpre = g_ncv[(size_t)bn * kD + d];

    out[OFF_NCS + (size_t)bn * kD + d] = tanhf(spre + SC_B * ds);

    auto bsum = [&](float x) -> float {
        red[d] = x; __syncthreads();
        for (int s = 128; s > 0; s >>= 1) {
            if (d < s) red[d] += red[d + s];
            __syncthreads();
        }
        float r = red[0]; __syncthreads(); return r;
    };
    float x = vpre + SC_B * dv;
    float m = bsum(x) * (1.0f / kD);
    float xd = x - m;
    float var = bsum(xd * xd) * (1.0f / kD);
    out[OFF_NCV + (size_t)bn * kD + d] = xd * rsqrtf(var + EPSL) * ln_g_c[d] + ln_b_c[d];
}

// ---------------------------------------------------------------------------
extern "C" void kernel_launch(void* const* d_in, const int* in_sizes, int n_in,
                              void* d_out, int out_size) {
    const float* s_state  = (const float*)d_in[0];
    const float* s_val    = (const float*)d_in[1];
    const float* w_pair_s = (const float*)d_in[2];
    const float* w_pair_c = (const float*)d_in[4];
    const float* b_expand = (const float*)d_in[6];
    const float* b_b2s    = (const float*)d_in[8];
    const float* b_comp   = (const float*)d_in[10];
    const float* W_s2b    = (const float*)d_in[11];
    const float* b_s2b    = (const float*)d_in[12];
    const float* ln_g_s   = (const float*)d_in[13];
    const float* ln_b_s   = (const float*)d_in[14];
    const float* ln_g_e   = (const float*)d_in[15];
    const float* ln_b_e   = (const float*)d_in[16];
    const float* ln_g_c   = (const float*)d_in[17];
    const float* ln_b_c   = (const float*)d_in[18];
    float* out = (float*)d_out;

    static int smem_set = 0;
    if (!smem_set) {
        cudaFuncSetAttribute(k3a_gemm, cudaFuncAttributeMaxDynamicSharedMemorySize, K3_SMEM);
        smem_set = 1;
    }

    k0_prep<<<1, 256>>>(b_expand, b_b2s, b_comp, ln_b_c, ln_g_e, ln_b_e);
    k1_splitW<<<dim3(kNC / 32, kD / 32), dim3(32, 32)>>>(W_s2b);
    k2_window<<<kM / 8, 256>>>(s_state, s_val, w_pair_s, ln_g_s, ln_b_s, out);
    k3a_gemm<<<dim3(kNC / 64, kM / 128), 256, K3_SMEM>>>(b_s2b);
    k3b_rescore<<<kM / 8, 256>>>(out, b_s2b);
    k3c_gather<<<kB * kNC, 256>>>(out, ln_b_c);
    k4a_scores<<<dim3(kNC / 64, kNC / 64, kB), 256>>>(w_pair_c);
    k4b_final<<<kB * kNC, 256>>>(ln_g_c, ln_b_c, out);
}

// round 13
// speedup vs baseline: 1.1902x; 1.0516x over previous
#include <cuda_runtime.h>
#include <cuda_bf16.h>
#include <math.h>
#include <cstdint>

// ---------------------------------------------------------------------------
#define kD   256
#define kB   4
#define kS   8192
#define kNE  2048
#define kNC  512
#define kWIN 4
#define kM   (kB * kS)

#define S_SC       0.25f
#define SC_B       0.2f
#define SC_X       0.075f
#define EPSL       1e-5f
#define INV_SQRT_D 0.0625f
#define CAP        2048

#define OFF_SSTATE ((size_t)0)
#define OFF_SVAL   ((size_t)kB * kS * kD)
#define OFF_NCS    ((size_t)2 * kB * kS * kD)
#define OFF_NCV    (OFF_NCS + (size_t)kB * kNC * kD)

// ---------------------------------------------------------------------------
__device__ float g_scmat[(size_t)kB * kNC * kNC];
__device__ int   g_entR[(size_t)kB * kNC * CAP];
__device__ float g_entW[(size_t)kB * kNC * CAP];
__device__ int   g_cnt[kB * kNC];
__device__ float g_esum[kD];
__device__ int   g_is[4]; __device__ float g_ws[4];
__device__ int   g_ic[4]; __device__ float g_wc[4];
__device__ float g_ncs[(size_t)kB * kNC * kD];
__device__ float g_ncv[(size_t)kB * kNC * kD];

__device__ __nv_bfloat16 g_shi[(size_t)kM * kD];
__device__ __nv_bfloat16 g_wth[(size_t)kNC * kD];
__device__ float         g_wtf[(size_t)kNC * kD];
__device__ float g_candV[(size_t)kM * 32];
__device__ int   g_candI[(size_t)kM * 32];

__device__ __forceinline__ bool bet(float v, int i, float bv, int bi) {
    return (v > bv) || (v == bv && i < bi);
}

__device__ __forceinline__ float warpsum(float v) {
    #pragma unroll
    for (int off = 16; off > 0; off >>= 1) v += __shfl_xor_sync(0xffffffffu, v, off);
    return v;
}

__device__ __forceinline__ void ins4(float v, int i, float* tv, int* ti) {
    if (bet(v, i, tv[3], ti[3])) {
        tv[3] = v; ti[3] = i;
        #pragma unroll
        for (int q = 3; q > 0; q--) {
            if (bet(tv[q], ti[q], tv[q - 1], ti[q - 1])) {
                float fv = tv[q]; tv[q] = tv[q - 1]; tv[q - 1] = fv;
                int   fi = ti[q]; ti[q] = ti[q - 1]; ti[q - 1] = fi;
            } else break;
        }
    }
}

// warp-butterfly merge of per-lane sorted-4 lists -> all lanes hold warp top4
__device__ __forceinline__ void warpmerge4(float* tv, int* ti) {
    #pragma unroll
    for (int msk = 1; msk <= 16; msk <<= 1) {
        float pv[4]; int pi[4];
        #pragma unroll
        for (int j = 0; j < 4; j++) {
            pv[j] = __shfl_xor_sync(0xffffffffu, tv[j], msk);
            pi[j] = __shfl_xor_sync(0xffffffffu, ti[j], msk);
        }
        #pragma unroll
        for (int j = 0; j < 4; j++) ins4(pv[j], pi[j], tv, ti);
    }
}

__device__ __forceinline__ void mma16816(float* c, const unsigned* a, const unsigned* b) {
    asm volatile(
        "mma.sync.aligned.m16n8k16.row.col.f32.bf16.bf16.f32 "
        "{%0,%1,%2,%3}, {%4,%5,%6,%7}, {%8,%9}, {%0,%1,%2,%3};"
        : "+f"(c[0]), "+f"(c[1]), "+f"(c[2]), "+f"(c[3])
        : "r"(a[0]), "r"(a[1]), "r"(a[2]), "r"(a[3]), "r"(b[0]), "r"(b[1]));
}

__device__ __forceinline__ void ldsm4(unsigned* r, const void* p) {
    unsigned a = (unsigned)__cvta_generic_to_shared(p);
    asm volatile("ldmatrix.sync.aligned.m8n8.x4.shared.b16 {%0,%1,%2,%3}, [%4];"
        : "=r"(r[0]), "=r"(r[1]), "=r"(r[2]), "=r"(r[3]) : "r"(a));
}

__device__ __forceinline__ void cpasync16(void* dst, const void* src) {
    unsigned sd = (unsigned)__cvta_generic_to_shared(dst);
    asm volatile("cp.async.cg.shared.global [%0], [%1], 16;" :: "r"(sd), "l"(src));
}

// ---------------------------------------------------------------------------
// K0: prep — single-pass top4 + warp-based reductions (barrier-light)
// ---------------------------------------------------------------------------
__global__ __launch_bounds__(256) void k0_prep(
    const float* __restrict__ b_expand, const float* __restrict__ b_b2s,
    const float* __restrict__ b_comp,   const float* __restrict__ ln_b_c,
    const float* __restrict__ ln_g_e,   const float* __restrict__ ln_b_e)
{
    __shared__ float wvv[8][4]; __shared__ int wii[8][4];
    __shared__ float tv[4];     __shared__ int ti[4];
    __shared__ float we[4];     __shared__ int ie[4];
    __shared__ float red[8];
    int tid = threadIdx.x;
    int wid = tid >> 5, lane = tid & 31;

    for (int j = tid; j < kB * kNC; j += 256) g_cnt[j] = 0;

    auto top4 = [&](const float* x, int n) {
        float lv[4] = {-INFINITY, -INFINITY, -INFINITY, -INFINITY};
        int   li[4] = {0x7fffffff, 0x7fffffff, 0x7fffffff, 0x7fffffff};
        for (int j = tid; j < n; j += 256) ins4(x[j], j, lv, li);
        warpmerge4(lv, li);
        if (lane == 0) {
            #pragma unroll
            for (int j = 0; j < 4; j++) { wvv[wid][j] = lv[j]; wii[wid][j] = li[j]; }
        }
        __syncthreads();
        if (wid == 0) {
            float v = wvv[lane >> 2][lane & 3];
            int  ix = wii[lane >> 2][lane & 3];
            #pragma unroll
            for (int r = 0; r < 4; r++) {
                float mv = v; int mi = ix;
                #pragma unroll
                for (int off = 16; off > 0; off >>= 1) {
                    float ov = __shfl_xor_sync(0xffffffffu, mv, off);
                    int   oi = __shfl_xor_sync(0xffffffffu, mi, off);
                    if (bet(ov, oi, mv, mi)) { mv = ov; mi = oi; }
                }
                if (lane == 0) { tv[r] = mv; ti[r] = mi; }
                if (ix == mi) v = -INFINITY;
            }
        }
        __syncthreads();
    };
    auto softmax4 = [&](float* wout) {
        if (tid == 0) {
            float m = tv[0];
            float e0 = expf(tv[0] - m), e1 = expf(tv[1] - m);
            float e2 = expf(tv[2] - m), e3 = expf(tv[3] - m);
            float inv = 1.0f / (e0 + e1 + e2 + e3);
            wout[0] = e0 * inv; wout[1] = e1 * inv;
            wout[2] = e2 * inv; wout[3] = e3 * inv;
        }
        __syncthreads();
    };

    top4(b_expand, kNE); softmax4(we);
    if (tid < 4) ie[tid] = ti[tid];
    __syncthreads();
    top4(b_b2s, kS); softmax4(g_ws);
    if (tid < 4) g_is[tid] = ti[tid];
    __syncthreads();
    top4(b_comp, kNC); softmax4(g_wc);
    if (tid < 4) g_ic[tid] = ti[tid];
    __syncthreads();

    int d = tid;
    float cval = ln_b_c[d];
    float rowval[4];
    float dvE = 0.0f;
    #pragma unroll
    for (int j = 0; j < 4; j++) {
        rowval[j] = SC_B * (float)kNC * we[j] * cval;
        if (ie[j] < 4) dvE += rowval[j];
    }
    dvE *= 0.25f;
    float base = SC_B * dvE;

    auto bsum = [&](float x) -> float {
        float w = warpsum(x);
        if (lane == 0) red[wid] = w;
        __syncthreads();
        float s = 0.0f;
        #pragma unroll
        for (int i = 0; i < 8; i++) s += red[i];
        __syncthreads();
        return s;
    };
    float ge = ln_g_e[d], be = ln_b_e[d];
    auto LN_e = [&](float x) -> float {
        float m  = bsum(x) * (1.0f / kD);
        float dv = x - m;
        float var = bsum(dv * dv) * (1.0f / kD);
        return dv * rsqrtf(var + EPSL) * ge + be;
    };

    float other = LN_e(base);
    float esum = (float)(kNE - 4) * other;
    #pragma unroll
    for (int j = 0; j < 4; j++) esum += LN_e(rowval[j] + base);
    g_esum[d] = esum;
}

// ---------------------------------------------------------------------------
// K1: W_s2b -> transposed bf16 [512 n][256 k] + transposed fp32 copy
// ---------------------------------------------------------------------------
__global__ void k1_splitW(const float* __restrict__ W)
{
    __shared__ float tile[32][33];
    int n0 = blockIdx.x * 32, k0 = blockIdx.y * 32;
    int tx = threadIdx.x, ty = threadIdx.y;
    tile[ty][tx] = W[(size_t)(k0 + ty) * kNC + n0 + tx];
    __syncthreads();
    float x = tile[tx][ty];
    g_wth[(size_t)(n0 + ty) * kD + k0 + tx] = __float2bfloat16(x);
    g_wtf[(size_t)(n0 + ty) * kD + k0 + tx] = x;
}

// ---------------------------------------------------------------------------
// K2: smem-tiled window prop. Lane owns float4 slots {lane, lane+32}
// (16B lane stride -> conflict-free LDS.128). Emits bf16 of final state.
// ---------------------------------------------------------------------------
__global__ __launch_bounds__(256) void k2_window(
    const float* __restrict__ s_state, const float* __restrict__ s_val,
    const float* __restrict__ w_pair_s,
    const float* __restrict__ ln_g_s, const float* __restrict__ ln_b_s,
    float* __restrict__ out)
{
    __shared__ float4 st_s[16][64];
    __shared__ float4 vl_s[16][64];

    int tid = threadIdx.x;
    int warp = tid >> 5, lane = tid & 31;
    int row0 = blockIdx.x * 8;
    int b = row0 >> 13, n0 = row0 & (kS - 1);
    const float4* st4 = (const float4*)(s_state + (size_t)b * kS * kD);
    const float4* vl4 = (const float4*)(s_val   + (size_t)b * kS * kD);

    #pragma unroll
    for (int t = 0; t < 8; t++) {
        int i = tid + t * 256;
        int arr = i >> 10, slot = (i >> 6) & 15, c = i & 63;
        int gr = min(max(n0 - 4 + slot, 0), kS - 1);
        float4 v = (arr ? vl4 : st4)[(size_t)gr * 64 + c];
        if (arr) vl_s[slot][c] = v; else st_s[slot][c] = v;
    }
    __syncthreads();

    int n = n0 + warp;
    int row = row0 + warp;
    int c1 = lane, c2 = lane + 32;

    float4 w0 = ((const float4*)w_pair_s)[c1];
    float4 w1 = ((const float4*)w_pair_s)[c2];
    float4 s0a = st_s[warp + 4][c1];
    float4 s0b = st_s[warp + 4][c2];
    float4 q0, q1;
    q0.x = s0a.x * w0.x; q0.y = s0a.y * w0.y; q0.z = s0a.z * w0.z; q0.w = s0a.w * w0.w;
    q1.x = s0b.x * w1.x; q1.y = s0b.y * w1.y; q1.z = s0b.z * w1.z; q1.w = s0b.w * w1.w;

    float scw[9];
    #pragma unroll
    for (int k = 0; k < 9; k++) {
        int j = n + k - kWIN;
        bool valid = ((unsigned)j < (unsigned)kS);
        float4 na = st_s[warp + k][c1];
        float4 nb = st_s[warp + k][c2];
        float p = q0.x * na.x + q0.y * na.y + q0.z * na.z + q0.w * na.w
                + q1.x * nb.x + q1.y * nb.y + q1.z * nb.z + q1.w * nb.w;
        p = warpsum(p);
        scw[k] = valid ? p * INV_SQRT_D : -1e30f;
    }
    float mx = scw[0];
    #pragma unroll
    for (int k = 1; k < 9; k++) mx = fmaxf(mx, scw[k]);
    float asum = 0.0f;
    #pragma unroll
    for (int k = 0; k < 9; k++) { scw[k] = expf(scw[k] - mx); asum += scw[k]; }
    float ainv = 1.0f / asum;

    float4 ds0 = {0,0,0,0}, ds1 = {0,0,0,0}, dv0 = {0,0,0,0}, dv1 = {0,0,0,0};
    #pragma unroll
    for (int k = 0; k < 9; k++) {
        float a = scw[k] * ainv;
        float4 na = st_s[warp + k][c1];
        float4 nb = st_s[warp + k][c2];
        float4 va = vl_s[warp + k][c1];
        float4 vb = vl_s[warp + k][c2];
        ds0.x += a * na.x; ds0.y += a * na.y; ds0.z += a * na.z; ds0.w += a * na.w;
        ds1.x += a * nb.x; ds1.y += a * nb.y; ds1.z += a * nb.z; ds1.w += a * nb.w;
        dv0.x += a * va.x; dv0.y += a * va.y; dv0.z += a * va.z; dv0.w += a * va.w;
        dv1.x += a * vb.x; dv1.y += a * vb.y; dv1.z += a * vb.z; dv1.w += a * vb.w;
    }

    float sv0[8] = {s0a.x, s0a.y, s0a.z, s0a.w, s0b.x, s0b.y, s0b.z, s0b.w};
    float dss[8] = {ds0.x, ds0.y, ds0.z, ds0.w, ds1.x, ds1.y, ds1.z, ds1.w};
    float sq[8];
    #pragma unroll
    for (int i = 0; i < 8; i++) sq[i] = tanhf(tanhf(sv0[i] + S_SC * dss[i]));

    float4* outS = (float4*)(out + OFF_SSTATE);
    outS[(size_t)row * 64 + c1] = make_float4(sq[0], sq[1], sq[2], sq[3]);
    outS[(size_t)row * 64 + c2] = make_float4(sq[4], sq[5], sq[6], sq[7]);

    // bf16 write: two 8B chunks at dims 4*lane and 128+4*lane
    unsigned hw1[2], hw2[2];
    #pragma unroll
    for (int i = 0; i < 2; i++) {
        __nv_bfloat16 ha = __float2bfloat16(sq[2 * i]);
        __nv_bfloat16 hc = __float2bfloat16(sq[2 * i + 1]);
        hw1[i] = ((unsigned)__bfloat16_as_ushort(hc) << 16) | __bfloat16_as_ushort(ha);
        __nv_bfloat16 hb = __float2bfloat16(sq[4 + 2 * i]);
        __nv_bfloat16 hd = __float2bfloat16(sq[4 + 2 * i + 1]);
        hw2[i] = ((unsigned)__bfloat16_as_ushort(hd) << 16) | __bfloat16_as_ushort(hb);
    }
    *(uint2*)&g_shi[(size_t)row * kD + lane * 4]       = make_uint2(hw1[0], hw1[1]);
    *(uint2*)&g_shi[(size_t)row * kD + 128 + lane * 4] = make_uint2(hw2[0], hw2[1]);

    float4 va0 = vl_s[warp + 4][c1];
    float4 va1 = vl_s[warp + 4][c2];
    float v[8];
    v[0] = va0.x + S_SC * dv0.x; v[1] = va0.y + S_SC * dv0.y;
    v[2] = va0.z + S_SC * dv0.z; v[3] = va0.w + S_SC * dv0.w;
    v[4] = va1.x + S_SC * dv1.x; v[5] = va1.y + S_SC * dv1.y;
    v[6] = va1.z + S_SC * dv1.z; v[7] = va1.w + S_SC * dv1.w;

    float4 g0 = ((const float4*)ln_g_s)[c1], g1 = ((const float4*)ln_g_s)[c2];
    float4 b0v = ((const float4*)ln_b_s)[c1], b1v = ((const float4*)ln_b_s)[c2];
    float gs[8] = {g0.x, g0.y, g0.z, g0.w, g1.x, g1.y, g1.z, g1.w};
    float bs[8] = {b0v.x, b0v.y, b0v.z, b0v.w, b1v.x, b1v.y, b1v.z, b1v.w};

    float s8 = 0.0f;
    #pragma unroll
    for (int i = 0; i < 8; i++) s8 += v[i];
    float mean = warpsum(s8) * (1.0f / kD);
    float vs = 0.0f;
    #pragma unroll
    for (int i = 0; i < 8; i++) { v[i] -= mean; vs += v[i] * v[i]; }
    float rstd = rsqrtf(warpsum(vs) * (1.0f / kD) + EPSL);
    #pragma unroll
    for (int i = 0; i < 8; i++) v[i] = v[i] * rstd * gs[i] + bs[i];

    bool hit = false; float wj = 0.0f;
    #pragma unroll
    for (int j = 0; j < 4; j++)
        if (g_is[j] == n) { hit = true; wj = g_ws[j]; }
    if (hit) {
        float4 e0 = ((const float4*)g_esum)[c1], e1 = ((const float4*)g_esum)[c2];
        float es[8] = {e0.x, e0.y, e0.z, e0.w, e1.x, e1.y, e1.z, e1.w};
        #pragma unroll
        for (int i = 0; i < 8; i++) v[i] += SC_X * wj * es[i];
    }

    s8 = 0.0f;
    #pragma unroll
    for (int i = 0; i < 8; i++) s8 += v[i];
    mean = warpsum(s8) * (1.0f / kD);
    vs = 0.0f;
    #pragma unroll
    for (int i = 0; i < 8; i++) { v[i] -= mean; vs += v[i] * v[i]; }
    rstd = rsqrtf(warpsum(vs) * (1.0f / kD) + EPSL);
    float4* outV = (float4*)(out + OFF_SVAL);
    outV[(size_t)row * 64 + c1] =
        make_float4(v[0] * rstd * gs[0] + bs[0], v[1] * rstd * gs[1] + bs[1],
                    v[2] * rstd * gs[2] + bs[2], v[3] * rstd * gs[3] + bs[3]);
    outV[(size_t)row * 64 + c2] =
        make_float4(v[4] * rstd * gs[4] + bs[4], v[5] * rstd * gs[5] + bs[5],
                    v[6] * rstd * gs[6] + bs[6], v[7] * rstd * gs[7] + bs[7]);
}

// ---------------------------------------------------------------------------
// K3a: single-term bf16 GEMM (unchanged from R12: 128x64 tile, 3 CTAs/SM)
// ---------------------------------------------------------------------------
#define KC3   64
#define SROW3 72
#define STG3  (192 * SROW3)
#define K3_SMEM (2 * STG3 * (int)sizeof(__nv_bfloat16))

__global__ __launch_bounds__(256, 3) void k3a_gemm(const float* __restrict__ bias)
{
    extern __shared__ __align__(16) __nv_bfloat16 sm3[];
    int tid = threadIdx.x;
    int warp = tid >> 5, lane = tid & 31;
    int mw = warp & 3, nw = warp >> 2;
    int g = lane >> 2, t = lane & 3;
    int m0 = blockIdx.y * 128, n0 = blockIdx.x * 64;

    int a_row = mw * 32 + (lane & 15);
    int a_kh  = ((lane >> 4) & 1) * 8;
    int b_row = 128 + nw * 32 + (lane & 7) + ((lane >> 4) & 1) * 8;
    int b_kh  = ((lane >> 3) & 1) * 8;

    float acc[2][4][4];
    #pragma unroll
    for (int i = 0; i < 2; i++)
        #pragma unroll
        for (int j = 0; j < 4; j++)
            #pragma unroll
            for (int q = 0; q < 4; q++) acc[i][j][q] = 0.0f;

    auto load_stage = [&](int st, int k0) {
        __nv_bfloat16* base = sm3 + st * STG3;
        #pragma unroll
        for (int tt = 0; tt < 6; tt++) {
            int i = tid + tt * 256;
            int r = i >> 3, c16 = i & 7;
            const __nv_bfloat16* src = (r < 128)
                ? g_shi + (size_t)(m0 + r) * kD + k0 + c16 * 8
                : g_wth + (size_t)(n0 + r - 128) * kD + k0 + c16 * 8;
            cpasync16(base + r * SROW3 + c16 * 8, src);
        }
        asm volatile("cp.async.commit_group;");
    };

    load_stage(0, 0);

    #pragma unroll
    for (int ks = 0; ks < kD / KC3; ks++) {
        int st = ks & 1;
        if (ks + 1 < kD / KC3) {
            load_stage(st ^ 1, (ks + 1) * KC3);
            asm volatile("cp.async.wait_group 1;");
        } else {
            asm volatile("cp.async.wait_group 0;");
        }
        __syncthreads();
        __nv_bfloat16* base = sm3 + st * STG3;

        #pragma unroll
        for (int kb = 0; kb < KC3; kb += 16) {
            unsigned ah[2][4];
            #pragma unroll
            for (int mt = 0; mt < 2; mt++)
                ldsm4(ah[mt], base + (a_row + mt * 16) * SROW3 + kb + a_kh);
            #pragma unroll
            for (int p = 0; p < 2; p++) {
                unsigned bh[4];
                ldsm4(bh, base + (b_row + p * 16) * SROW3 + kb + b_kh);
                #pragma unroll
                for (int half = 0; half < 2; half++) {
                    int nt = p * 2 + half;
                    unsigned* bhp = bh + half * 2;
                    #pragma unroll
                    for (int mt = 0; mt < 2; mt++)
                        mma16816(acc[mt][nt], ah[mt], bhp);
                }
            }
        }
        __syncthreads();
    }

    float bcol[8];
    #pragma unroll
    for (int nt = 0; nt < 4; nt++) {
        int c = n0 + nw * 32 + nt * 8 + 2 * t;
        bcol[nt * 2]     = bias[c];
        bcol[nt * 2 + 1] = bias[c + 1];
    }

    float* svv = (float*)&sm3[0];
    int*   sii = (int*)(((char*)&sm3[0]) + 4096);

    #pragma unroll
    for (int mt = 0; mt < 2; mt++) {
        #pragma unroll
        for (int h = 0; h < 2; h++) {
            float tv[4] = {-INFINITY, -INFINITY, -INFINITY, -INFINITY};
            int   ti[4] = {0x7fffffff, 0x7fffffff, 0x7fffffff, 0x7fffffff};
            #pragma unroll
            for (int nt = 0; nt < 4; nt++) {
                #pragma unroll
                for (int e = 0; e < 2; e++) {
                    float val = acc[mt][nt][h * 2 + e] + bcol[nt * 2 + e];
                    int col = n0 + nw * 32 + nt * 8 + 2 * t + e;
                    ins4(val, col, tv, ti);
                }
            }
            #pragma unroll
            for (int msk = 1; msk <= 2; msk <<= 1) {
                float pv[4]; int pi[4];
                #pragma unroll
                for (int j = 0; j < 4; j++) {
                    pv[j] = __shfl_xor_sync(0xffffffffu, tv[j], msk);
                    pi[j] = __shfl_xor_sync(0xffffffffu, ti[j], msk);
                }
                #pragma unroll
                for (int j = 0; j < 4; j++) ins4(pv[j], pi[j], tv, ti);
            }
            if (t == 0) {
                int lrow2 = mw * 32 + mt * 16 + h * 8 + g;
                #pragma unroll
                for (int j = 0; j < 4; j++) {
                    svv[(lrow2 * 2 + nw) * 4 + j] = tv[j];
                    sii[(lrow2 * 2 + nw) * 4 + j] = ti[j];
                }
            }
        }
    }
    __syncthreads();
    if (tid < 128) {
        float tv[4]; int ti[4];
        #pragma unroll
        for (int j = 0; j < 4; j++) { tv[j] = svv[(tid * 2) * 4 + j]; ti[j] = sii[(tid * 2) * 4 + j]; }
        #pragma unroll
        for (int j = 0; j < 4; j++) ins4(svv[(tid * 2 + 1) * 4 + j], sii[(tid * 2 + 1) * 4 + j], tv, ti);
        size_t base = ((size_t)(m0 + tid) * 8 + blockIdx.x) * 4;
        #pragma unroll
        for (int j = 0; j < 4; j++) { g_candV[base + j] = tv[j]; g_candI[base + j] = ti[j]; }
    }
}

// ---------------------------------------------------------------------------
// K3b: rescore — merge 32 candidates -> top-8, fp32 exact rescore, top-4,
// softmax, bucket push. Warp per row.
// ---------------------------------------------------------------------------
__global__ __launch_bounds__(256) void k3b_rescore(
    const float* __restrict__ out, const float* __restrict__ bias)
{
    int warp = threadIdx.x >> 5, lane = threadIdx.x & 31;
    int row = blockIdx.x * 8 + warp;
    int b = row >> 13;

    float v = g_candV[(size_t)row * 32 + lane];
    int  ix = g_candI[(size_t)row * 32 + lane];

    int cand8[8];
    #pragma unroll
    for (int r = 0; r < 8; r++) {
        float mv = v; int mi = ix;
        #pragma unroll
        for (int off = 16; off > 0; off >>= 1) {
            float ov = __shfl_xor_sync(0xffffffffu, mv, off);
            int   oi = __shfl_xor_sync(0xffffffffu, mi, off);
            if (bet(ov, oi, mv, mi)) { mv = ov; mi = oi; }
        }
        cand8[r] = mi;
        if (ix == mi) v = -INFINITY;
    }

    const float4* ar = (const float4*)(out + OFF_SSTATE + (size_t)row * kD);
    float4 a0 = ar[lane * 2], a1 = ar[lane * 2 + 1];

    float ex[8];
    #pragma unroll
    for (int r = 0; r < 8; r++) {
        const float4* wr = (const float4*)(g_wtf + (size_t)cand8[r] * kD);
        float4 w0 = wr[lane * 2], w1 = wr[lane * 2 + 1];
        float p = a0.x * w0.x + a0.y * w0.y + a0.z * w0.z + a0.w * w0.w
                + a1.x * w1.x + a1.y * w1.y + a1.z * w1.z + a1.w * w1.w;
        ex[r] = warpsum(p) + bias[cand8[r]];
    }

    float tv[4] = {-INFINITY, -INFINITY, -INFINITY, -INFINITY};
    int   ti[4] = {0x7fffffff, 0x7fffffff, 0x7fffffff, 0x7fffffff};
    #pragma unroll
    for (int r = 0; r < 8; r++) ins4(ex[r], cand8[r], tv, ti);

    float mx = tv[0];
    float e0 = expf(tv[0] - mx), e1 = expf(tv[1] - mx);
    float e2 = expf(tv[2] - mx), e3 = expf(tv[3] - mx);
    float inv = 1.0f / (e0 + e1 + e2 + e3);
    if (lane < 4) {
        float ej = (lane == 0) ? e0 : (lane == 1) ? e1 : (lane == 2) ? e2 : e3;
        float wgt = SC_X * ej * inv;
        int bt = b * kNC + ti[lane];
        int pos = atomicAdd(&g_cnt[bt], 1);
        if (pos < CAP) {
            g_entR[(size_t)bt * CAP + pos] = row;
            g_entW[(size_t)bt * CAP + pos] = wgt;
        }
    }
}

// ---------------------------------------------------------------------------
// K3c: per-(b,target) gather-sum
// ---------------------------------------------------------------------------
__global__ __launch_bounds__(256) void k3c_gather(
    const float* __restrict__ out, const float* __restrict__ ln_b_c)
{
    int bt = blockIdx.x;
    int t = bt & (kNC - 1);
    int sub = threadIdx.x >> 6, c = threadIdx.x & 63;
    int n = min(g_cnt[bt], CAP);
    const float4* ssf = (const float4*)(out + OFF_SSTATE);
    const float4* svf = (const float4*)(out + OFF_SVAL);
    float4 aS = {0,0,0,0}, aV = {0,0,0,0};
    for (int i = sub; i < n; i += 4) {
        int r   = g_entR[(size_t)bt * CAP + i];
        float w = g_entW[(size_t)bt * CAP + i];
        float4 s = ssf[(size_t)r * 64 + c];
        float4 vv = svf[(size_t)r * 64 + c];
        aS.x += w * s.x;  aS.y += w * s.y;  aS.z += w * s.z;  aS.w += w * s.w;
        aV.x += w * vv.x; aV.y += w * vv.y; aV.z += w * vv.z; aV.w += w * vv.w;
    }
    __shared__ float4 shS[4][64], shV[4][64];
    shS[sub][c] = aS; shV[sub][c] = aV;
    __syncthreads();
    if (sub == 0) {
        float4 S = shS[0][c], V = shV[0][c];
        #pragma unroll
        for (int q = 1; q < 4; q++) {
            float4 s2 = shS[q][c], v2 = shV[q][c];
            S.x += s2.x; S.y += s2.y; S.z += s2.z; S.w += s2.w;
            V.x += v2.x; V.y += v2.y; V.z += v2.z; V.w += v2.w;
        }
        ((float4*)g_ncs)[(size_t)bt * 64 + c] = S;
        float4 nb = ((const float4*)ln_b_c)[c];
        V.x += nb.x; V.y += nb.y; V.z += nb.z; V.w += nb.w;
        #pragma unroll
        for (int j = 0; j < 4; j++)
            if (g_ic[j] == t) {
                float w = SC_B * g_wc[j];
                float4 es = ((const float4*)g_esum)[c];
                V.x += w * es.x; V.y += w * es.y; V.z += w * es.z; V.w += w * es.w;
            }
        ((float4*)g_ncv)[(size_t)bt * 64 + c] = V;
    }
}

// ---------------------------------------------------------------------------
// K4a: per-batch scores
// ---------------------------------------------------------------------------
__global__ __launch_bounds__(256) void k4a_scores(const float* __restrict__ wpc)
{
    int bb = blockIdx.z;
    int m0 = blockIdx.y * 64;
    int n0 = blockIdx.x * 64;
    const float* ncs = g_ncs + (size_t)bb * kNC * kD;
    __shared__ float As[16][64 + 4];
    __shared__ float Bs[16][64 + 4];
    int tid = threadIdx.x;
    int ty = tid / 16, tx = tid % 16;
    float acc[4][4] = {};
    int lrow = tid / 4;
    int lk = (tid % 4) * 4;
    for (int k0 = 0; k0 < kD; k0 += 16) {
        float4 av = *(const float4*)&ncs[(size_t)(m0 + lrow) * kD + k0 + lk];
        float4 bv = *(const float4*)&ncs[(size_t)(n0 + lrow) * kD + k0 + lk];
        float4 wv = *(const float4*)&wpc[k0 + lk];
        As[lk + 0][lrow] = av.x * wv.x; As[lk + 1][lrow] = av.y * wv.y;
        As[lk + 2][lrow] = av.z * wv.z; As[lk + 3][lrow] = av.w * wv.w;
        Bs[lk + 0][lrow] = bv.x; Bs[lk + 1][lrow] = bv.y;
        Bs[lk + 2][lrow] = bv.z; Bs[lk + 3][lrow] = bv.w;
        __syncthreads();
        #pragma unroll
        for (int kk = 0; kk < 16; kk++) {
            float ar[4], br[4];
            #pragma unroll
            for (int i = 0; i < 4; i++) ar[i] = As[kk][ty * 4 + i];
            #pragma unroll
            for (int j = 0; j < 4; j++) br[j] = Bs[kk][tx * 4 + j];
            #pragma unroll
            for (int i = 0; i < 4; i++)
                #pragma unroll
                for (int j = 0; j < 4; j++)
                    acc[i][j] += ar[i] * br[j];
        }
        __syncthreads();
    }
    #pragma unroll
    for (int i = 0; i < 4; i++)
        #pragma unroll
        for (int j = 0; j < 4; j++)
            g_scmat[(size_t)bb * kNC * kNC + (size_t)(m0 + ty * 4 + i) * kNC + (n0 + tx * 4 + j)] =
                acc[i][j] * INV_SQRT_D;
}

// ---------------------------------------------------------------------------
// K4b: per-(b,n) top-4 (single-pass + warp merges), softmax, gather,
// tanh/LN finalize with warp-based bsum.
// ---------------------------------------------------------------------------
__global__ __launch_bounds__(256) void k4b_final(
    const float* __restrict__ ln_g_c, const float* __restrict__ ln_b_c,
    float* __restrict__ out)
{
    int bn = blockIdx.x;
    int bb = bn / kNC;
    int d = threadIdx.x;
    int wid = d >> 5, lane = d & 31;
    const float* sc = g_scmat + (size_t)bn * kNC;
    __shared__ float wvv[8][4]; __shared__ int wii[8][4];
    __shared__ float topw[4];   __shared__ int topidx[4];
    __shared__ float red[8];

    float lv[4] = {-INFINITY, -INFINITY, -INFINITY, -INFINITY};
    int   li[4] = {0x7fffffff, 0x7fffffff, 0x7fffffff, 0x7fffffff};
    ins4(sc[d], d, lv, li);
    ins4(sc[d + 256], d + 256, lv, li);
    warpmerge4(lv, li);
    if (lane == 0) {
        #pragma unroll
        for (int j = 0; j < 4; j++) { wvv[wid][j] = lv[j]; wii[wid][j] = li[j]; }
    }
    __syncthreads();
    if (wid == 0) {
        float v = wvv[lane >> 2][lane & 3];
        int  ix = wii[lane >> 2][lane & 3];
        #pragma unroll
        for (int r = 0; r < 4; r++) {
            float mv = v; int mi = ix;
            #pragma unroll
            for (int off = 16; off > 0; off >>= 1) {
                float ov = __shfl_xor_sync(0xffffffffu, mv, off);
                int   oi = __shfl_xor_sync(0xffffffffu, mi, off);
                if (bet(ov, oi, mv, mi)) { mv = ov; mi = oi; }
            }
            if (lane == 0) { topw[r] = mv; topidx[r] = mi; }
            if (ix == mi) v = -INFINITY;
        }
    }
    __syncthreads();

    float mx = topw[0];
    float e[4]; float esum = 0.0f;
    #pragma unroll
    for (int j = 0; j < 4; j++) { e[j] = expf(topw[j] - mx); esum += e[j]; }
    float inv = 1.0f / esum;

    const float* ncsB = g_ncs + (size_t)bb * kNC * kD;
    const float* ncvB = g_ncv + (size_t)bb * kNC * kD;
    float ds = 0.0f, dv = 0.0f;
    #pragma unroll
    for (int j = 0; j < 4; j++) {
        int m = topidx[j];
        float a = e[j] * inv;
        ds += a * ncsB[(size_t)m * kD + d];
        dv += a * ncvB[(size_t)m * kD + d];
    }
    float spre = g_ncs[(size_t)bn * kD + d];
    float vpre = g_ncv[(size_t)bn * kD + d];

    out[OFF_NCS + (size_t)bn * kD + d] = tanhf(spre + SC_B * ds);

    auto bsum = [&](float x) -> float {
        float w = warpsum(x);
        if (lane == 0) red[wid] = w;
        __syncthreads();
        float s = 0.0f;
        #pragma unroll
        for (int i = 0; i < 8; i++) s += red[i];
        __syncthreads();
        return s;
    };
    float x = vpre + SC_B * dv;
    float m = bsum(x) * (1.0f / kD);
    float xd = x - m;
    float var = bsum(xd * xd) * (1.0f / kD);
    out[OFF_NCV + (size_t)bn * kD + d] = xd * rsqrtf(var + EPSL) * ln_g_c[d] + ln_b_c[d];
}

// ---------------------------------------------------------------------------
extern "C" void kernel_launch(void* const* d_in, const int* in_sizes, int n_in,
                              void* d_out, int out_size) {
    const float* s_state  = (const float*)d_in[0];
    const float* s_val    = (const float*)d_in[1];
    const float* w_pair_s = (const float*)d_in[2];
    const float* w_pair_c = (const float*)d_in[4];
    const float* b_expand = (const float*)d_in[6];
    const float* b_b2s    = (const float*)d_in[8];
    const float* b_comp   = (const float*)d_in[10];
    const float* W_s2b    = (const float*)d_in[11];
    const float* b_s2b    = (const float*)d_in[12];
    const float* ln_g_s   = (const float*)d_in[13];
    const float* ln_b_s   = (const float*)d_in[14];
    const float* ln_g_e   = (const float*)d_in[15];
    const float* ln_b_e   = (const float*)d_in[16];
    const float* ln_g_c   = (const float*)d_in[17];
    const float* ln_b_c   = (const float*)d_in[18];
    float* out = (float*)d_out;

    static int smem_set = 0;
    if (!smem_set) {
        cudaFuncSetAttribute(k3a_gemm, cudaFuncAttributeMaxDynamicSharedMemorySize, K3_SMEM);
        smem_set = 1;
    }

    k0_prep<<<1, 256>>>(b_expand, b_b2s, b_comp, ln_b_c, ln_g_e, ln_b_e);
    k1_splitW<<<dim3(kNC / 32, kD / 32), dim3(32, 32)>>>(W_s2b);
    k2_window<<<kM / 8, 256>>>(s_state, s_val, w_pair_s, ln_g_s, ln_b_s, out);
    k3a_gemm<<<dim3(kNC / 64, kM / 128), 256, K3_SMEM>>>(b_s2b);
    k3b_rescore<<<kM / 8, 256>>>(out, b_s2b);
    k3c_gather<<<kB * kNC, 256>>>(out, ln_b_c);
    k4a_scores<<<dim3(kNC / 64, kNC / 64, kB), 256>>>(w_pair_c);
    k4b_final<<<kB * kNC, 256>>>(ln_g_c, ln_b_c, out);
}

// round 14
// speedup vs baseline: 1.2545x; 1.0540x over previous
#include <cuda_runtime.h>
#include <cuda_bf16.h>
#include <math.h>
#include <cstdint>

// ---------------------------------------------------------------------------
#define kD   256
#define kB   4
#define kS   8192
#define kNE  2048
#define kNC  512
#define kWIN 4
#define kM   (kB * kS)

#define S_SC       0.25f
#define SC_B       0.2f
#define SC_X       0.075f
#define EPSL       1e-5f
#define INV_SQRT_D 0.0625f
#define CAP        2048

#define OFF_SSTATE ((size_t)0)
#define OFF_SVAL   ((size_t)kB * kS * kD)
#define OFF_NCS    ((size_t)2 * kB * kS * kD)
#define OFF_NCV    (OFF_NCS + (size_t)kB * kNC * kD)

// ---------------------------------------------------------------------------
__device__ float g_scmat[(size_t)kB * kNC * kNC];
__device__ int   g_entR[(size_t)kB * kNC * CAP];
__device__ float g_entW[(size_t)kB * kNC * CAP];
__device__ int   g_cnt[kB * kNC];
__device__ float g_esum[kD];
__device__ int   g_is[4]; __device__ float g_ws[4];
__device__ int   g_ic[4]; __device__ float g_wc[4];
__device__ float g_ncs[(size_t)kB * kNC * kD];
__device__ float g_ncv[(size_t)kB * kNC * kD];

__device__ __nv_bfloat16 g_shi[(size_t)kM * kD];
__device__ __nv_bfloat16 g_wth[(size_t)kNC * kD];
__device__ float         g_wtf[(size_t)kNC * kD];
__device__ float g_candV[(size_t)kM * 32];
__device__ int   g_candI[(size_t)kM * 32];

__device__ __forceinline__ bool bet(float v, int i, float bv, int bi) {
    return (v > bv) || (v == bv && i < bi);
}

__device__ __forceinline__ float warpsum(float v) {
    #pragma unroll
    for (int off = 16; off > 0; off >>= 1) v += __shfl_xor_sync(0xffffffffu, v, off);
    return v;
}

__device__ __forceinline__ void ins4(float v, int i, float* tv, int* ti) {
    if (bet(v, i, tv[3], ti[3])) {
        tv[3] = v; ti[3] = i;
        #pragma unroll
        for (int q = 3; q > 0; q--) {
            if (bet(tv[q], ti[q], tv[q - 1], ti[q - 1])) {
                float fv = tv[q]; tv[q] = tv[q - 1]; tv[q - 1] = fv;
                int   fi = ti[q]; ti[q] = ti[q - 1]; ti[q - 1] = fi;
            } else break;
        }
    }
}

// warp-butterfly merge of per-lane sorted-4 lists -> all lanes hold warp top4
__device__ __forceinline__ void warpmerge4(float* tv, int* ti) {
    #pragma unroll
    for (int msk = 1; msk <= 16; msk <<= 1) {
        float pv[4]; int pi[4];
        #pragma unroll
        for (int j = 0; j < 4; j++) {
            pv[j] = __shfl_xor_sync(0xffffffffu, tv[j], msk);
            pi[j] = __shfl_xor_sync(0xffffffffu, ti[j], msk);
        }
        #pragma unroll
        for (int j = 0; j < 4; j++) ins4(pv[j], pi[j], tv, ti);
    }
}

__device__ __forceinline__ void mma16816(float* c, const unsigned* a, const unsigned* b) {
    asm volatile(
        "mma.sync.aligned.m16n8k16.row.col.f32.bf16.bf16.f32 "
        "{%0,%1,%2,%3}, {%4,%5,%6,%7}, {%8,%9}, {%0,%1,%2,%3};"
        : "+f"(c[0]), "+f"(c[1]), "+f"(c[2]), "+f"(c[3])
        : "r"(a[0]), "r"(a[1]), "r"(a[2]), "r"(a[3]), "r"(b[0]), "r"(b[1]));
}

__device__ __forceinline__ void ldsm4(unsigned* r, const void* p) {
    unsigned a = (unsigned)__cvta_generic_to_shared(p);
    asm volatile("ldmatrix.sync.aligned.m8n8.x4.shared.b16 {%0,%1,%2,%3}, [%4];"
        : "=r"(r[0]), "=r"(r[1]), "=r"(r[2]), "=r"(r[3]) : "r"(a));
}

__device__ __forceinline__ void cpasync16(void* dst, const void* src) {
    unsigned sd = (unsigned)__cvta_generic_to_shared(dst);
    asm volatile("cp.async.cg.shared.global [%0], [%1], 16;" :: "r"(sd), "l"(src));
}

// ---------------------------------------------------------------------------
// K0: prep — single-pass top4 + warp-based reductions (barrier-light)
// ---------------------------------------------------------------------------
__global__ __launch_bounds__(256) void k0_prep(
    const float* __restrict__ b_expand, const float* __restrict__ b_b2s,
    const float* __restrict__ b_comp,   const float* __restrict__ ln_b_c,
    const float* __restrict__ ln_g_e,   const float* __restrict__ ln_b_e)
{
    __shared__ float wvv[8][4]; __shared__ int wii[8][4];
    __shared__ float tv[4];     __shared__ int ti[4];
    __shared__ float we[4];     __shared__ int ie[4];
    __shared__ float red[8];
    int tid = threadIdx.x;
    int wid = tid >> 5, lane = tid & 31;

    for (int j = tid; j < kB * kNC; j += 256) g_cnt[j] = 0;

    auto top4 = [&](const float* x, int n) {
        float lv[4] = {-INFINITY, -INFINITY, -INFINITY, -INFINITY};
        int   li[4] = {0x7fffffff, 0x7fffffff, 0x7fffffff, 0x7fffffff};
        for (int j = tid; j < n; j += 256) ins4(x[j], j, lv, li);
        warpmerge4(lv, li);
        if (lane == 0) {
            #pragma unroll
            for (int j = 0; j < 4; j++) { wvv[wid][j] = lv[j]; wii[wid][j] = li[j]; }
        }
        __syncthreads();
        if (wid == 0) {
            float v = wvv[lane >> 2][lane & 3];
            int  ix = wii[lane >> 2][lane & 3];
            #pragma unroll
            for (int r = 0; r < 4; r++) {
                float mv = v; int mi = ix;
                #pragma unroll
                for (int off = 16; off > 0; off >>= 1) {
                    float ov = __shfl_xor_sync(0xffffffffu, mv, off);
                    int   oi = __shfl_xor_sync(0xffffffffu, mi, off);
                    if (bet(ov, oi, mv, mi)) { mv = ov; mi = oi; }
                }
                if (lane == 0) { tv[r] = mv; ti[r] = mi; }
                if (ix == mi) v = -INFINITY;
            }
        }
        __syncthreads();
    };
    auto softmax4 = [&](float* wout) {
        if (tid == 0) {
            float m = tv[0];
            float e0 = expf(tv[0] - m), e1 = expf(tv[1] - m);
            float e2 = expf(tv[2] - m), e3 = expf(tv[3] - m);
            float inv = 1.0f / (e0 + e1 + e2 + e3);
            wout[0] = e0 * inv; wout[1] = e1 * inv;
            wout[2] = e2 * inv; wout[3] = e3 * inv;
        }
        __syncthreads();
    };

    top4(b_expand, kNE); softmax4(we);
    if (tid < 4) ie[tid] = ti[tid];
    __syncthreads();
    top4(b_b2s, kS); softmax4(g_ws);
    if (tid < 4) g_is[tid] = ti[tid];
    __syncthreads();
    top4(b_comp, kNC); softmax4(g_wc);
    if (tid < 4) g_ic[tid] = ti[tid];
    __syncthreads();

    int d = tid;
    float cval = ln_b_c[d];
    float rowval[4];
    float dvE = 0.0f;
    #pragma unroll
    for (int j = 0; j < 4; j++) {
        rowval[j] = SC_B * (float)kNC * we[j] * cval;
        if (ie[j] < 4) dvE += rowval[j];
    }
    dvE *= 0.25f;
    float base = SC_B * dvE;

    auto bsum = [&](float x) -> float {
        float w = warpsum(x);
        if (lane == 0) red[wid] = w;
        __syncthreads();
        float s = 0.0f;
        #pragma unroll
        for (int i = 0; i < 8; i++) s += red[i];
        __syncthreads();
        return s;
    };
    float ge = ln_g_e[d], be = ln_b_e[d];
    auto LN_e = [&](float x) -> float {
        float m  = bsum(x) * (1.0f / kD);
        float dv = x - m;
        float var = bsum(dv * dv) * (1.0f / kD);
        return dv * rsqrtf(var + EPSL) * ge + be;
    };

    float other = LN_e(base);
    float esum = (float)(kNE - 4) * other;
    #pragma unroll
    for (int j = 0; j < 4; j++) esum += LN_e(rowval[j] + base);
    g_esum[d] = esum;
}

// ---------------------------------------------------------------------------
// K1: W_s2b -> transposed bf16 [512 n][256 k] + transposed fp32 copy
// ---------------------------------------------------------------------------
__global__ void k1_splitW(const float* __restrict__ W)
{
    __shared__ float tile[32][33];
    int n0 = blockIdx.x * 32, k0 = blockIdx.y * 32;
    int tx = threadIdx.x, ty = threadIdx.y;
    tile[ty][tx] = W[(size_t)(k0 + ty) * kNC + n0 + tx];
    __syncthreads();
    float x = tile[tx][ty];
    g_wth[(size_t)(n0 + ty) * kD + k0 + tx] = __float2bfloat16(x);
    g_wtf[(size_t)(n0 + ty) * kD + k0 + tx] = x;
}

// ---------------------------------------------------------------------------
// K2: smem-tiled window prop (unchanged from R13)
// ---------------------------------------------------------------------------
__global__ __launch_bounds__(256) void k2_window(
    const float* __restrict__ s_state, const float* __restrict__ s_val,
    const float* __restrict__ w_pair_s,
    const float* __restrict__ ln_g_s, const float* __restrict__ ln_b_s,
    float* __restrict__ out)
{
    __shared__ float4 st_s[16][64];
    __shared__ float4 vl_s[16][64];

    int tid = threadIdx.x;
    int warp = tid >> 5, lane = tid & 31;
    int row0 = blockIdx.x * 8;
    int b = row0 >> 13, n0 = row0 & (kS - 1);
    const float4* st4 = (const float4*)(s_state + (size_t)b * kS * kD);
    const float4* vl4 = (const float4*)(s_val   + (size_t)b * kS * kD);

    #pragma unroll
    for (int t = 0; t < 8; t++) {
        int i = tid + t * 256;
        int arr = i >> 10, slot = (i >> 6) & 15, c = i & 63;
        int gr = min(max(n0 - 4 + slot, 0), kS - 1);
        float4 v = (arr ? vl4 : st4)[(size_t)gr * 64 + c];
        if (arr) vl_s[slot][c] = v; else st_s[slot][c] = v;
    }
    __syncthreads();

    int n = n0 + warp;
    int row = row0 + warp;
    int c1 = lane, c2 = lane + 32;

    float4 w0 = ((const float4*)w_pair_s)[c1];
    float4 w1 = ((const float4*)w_pair_s)[c2];
    float4 s0a = st_s[warp + 4][c1];
    float4 s0b = st_s[warp + 4][c2];
    float4 q0, q1;
    q0.x = s0a.x * w0.x; q0.y = s0a.y * w0.y; q0.z = s0a.z * w0.z; q0.w = s0a.w * w0.w;
    q1.x = s0b.x * w1.x; q1.y = s0b.y * w1.y; q1.z = s0b.z * w1.z; q1.w = s0b.w * w1.w;

    float scw[9];
    #pragma unroll
    for (int k = 0; k < 9; k++) {
        int j = n + k - kWIN;
        bool valid = ((unsigned)j < (unsigned)kS);
        float4 na = st_s[warp + k][c1];
        float4 nb = st_s[warp + k][c2];
        float p = q0.x * na.x + q0.y * na.y + q0.z * na.z + q0.w * na.w
                + q1.x * nb.x + q1.y * nb.y + q1.z * nb.z + q1.w * nb.w;
        p = warpsum(p);
        scw[k] = valid ? p * INV_SQRT_D : -1e30f;
    }
    float mx = scw[0];
    #pragma unroll
    for (int k = 1; k < 9; k++) mx = fmaxf(mx, scw[k]);
    float asum = 0.0f;
    #pragma unroll
    for (int k = 0; k < 9; k++) { scw[k] = expf(scw[k] - mx); asum += scw[k]; }
    float ainv = 1.0f / asum;

    float4 ds0 = {0,0,0,0}, ds1 = {0,0,0,0}, dv0 = {0,0,0,0}, dv1 = {0,0,0,0};
    #pragma unroll
    for (int k = 0; k < 9; k++) {
        float a = scw[k] * ainv;
        float4 na = st_s[warp + k][c1];
        float4 nb = st_s[warp + k][c2];
        float4 va = vl_s[warp + k][c1];
        float4 vb = vl_s[warp + k][c2];
        ds0.x += a * na.x; ds0.y += a * na.y; ds0.z += a * na.z; ds0.w += a * na.w;
        ds1.x += a * nb.x; ds1.y += a * nb.y; ds1.z += a * nb.z; ds1.w += a * nb.w;
        dv0.x += a * va.x; dv0.y += a * va.y; dv0.z += a * va.z; dv0.w += a * va.w;
        dv1.x += a * vb.x; dv1.y += a * vb.y; dv1.z += a * vb.z; dv1.w += a * vb.w;
    }

    float sv0[8] = {s0a.x, s0a.y, s0a.z, s0a.w, s0b.x, s0b.y, s0b.z, s0b.w};
    float dss[8] = {ds0.x, ds0.y, ds0.z, ds0.w, ds1.x, ds1.y, ds1.z, ds1.w};
    float sq[8];
    #pragma unroll
    for (int i = 0; i < 8; i++) sq[i] = tanhf(tanhf(sv0[i] + S_SC * dss[i]));

    float4* outS = (float4*)(out + OFF_SSTATE);
    outS[(size_t)row * 64 + c1] = make_float4(sq[0], sq[1], sq[2], sq[3]);
    outS[(size_t)row * 64 + c2] = make_float4(sq[4], sq[5], sq[6], sq[7]);

    unsigned hw1[2], hw2[2];
    #pragma unroll
    for (int i = 0; i < 2; i++) {
        __nv_bfloat16 ha = __float2bfloat16(sq[2 * i]);
        __nv_bfloat16 hc = __float2bfloat16(sq[2 * i + 1]);
        hw1[i] = ((unsigned)__bfloat16_as_ushort(hc) << 16) | __bfloat16_as_ushort(ha);
        __nv_bfloat16 hb = __float2bfloat16(sq[4 + 2 * i]);
        __nv_bfloat16 hd = __float2bfloat16(sq[4 + 2 * i + 1]);
        hw2[i] = ((unsigned)__bfloat16_as_ushort(hd) << 16) | __bfloat16_as_ushort(hb);
    }
    *(uint2*)&g_shi[(size_t)row * kD + lane * 4]       = make_uint2(hw1[0], hw1[1]);
    *(uint2*)&g_shi[(size_t)row * kD + 128 + lane * 4] = make_uint2(hw2[0], hw2[1]);

    float4 va0 = vl_s[warp + 4][c1];
    float4 va1 = vl_s[warp + 4][c2];
    float v[8];
    v[0] = va0.x + S_SC * dv0.x; v[1] = va0.y + S_SC * dv0.y;
    v[2] = va0.z + S_SC * dv0.z; v[3] = va0.w + S_SC * dv0.w;
    v[4] = va1.x + S_SC * dv1.x; v[5] = va1.y + S_SC * dv1.y;
    v[6] = va1.z + S_SC * dv1.z; v[7] = va1.w + S_SC * dv1.w;

    float4 g0 = ((const float4*)ln_g_s)[c1], g1 = ((const float4*)ln_g_s)[c2];
    float4 b0v = ((const float4*)ln_b_s)[c1], b1v = ((const float4*)ln_b_s)[c2];
    float gs[8] = {g0.x, g0.y, g0.z, g0.w, g1.x, g1.y, g1.z, g1.w};
    float bs[8] = {b0v.x, b0v.y, b0v.z, b0v.w, b1v.x, b1v.y, b1v.z, b1v.w};

    float s8 = 0.0f;
    #pragma unroll
    for (int i = 0; i < 8; i++) s8 += v[i];
    float mean = warpsum(s8) * (1.0f / kD);
    float vs = 0.0f;
    #pragma unroll
    for (int i = 0; i < 8; i++) { v[i] -= mean; vs += v[i] * v[i]; }
    float rstd = rsqrtf(warpsum(vs) * (1.0f / kD) + EPSL);
    #pragma unroll
    for (int i = 0; i < 8; i++) v[i] = v[i] * rstd * gs[i] + bs[i];

    bool hit = false; float wj = 0.0f;
    #pragma unroll
    for (int j = 0; j < 4; j++)
        if (g_is[j] == n) { hit = true; wj = g_ws[j]; }
    if (hit) {
        float4 e0 = ((const float4*)g_esum)[c1], e1 = ((const float4*)g_esum)[c2];
        float es[8] = {e0.x, e0.y, e0.z, e0.w, e1.x, e1.y, e1.z, e1.w};
        #pragma unroll
        for (int i = 0; i < 8; i++) v[i] += SC_X * wj * es[i];
    }

    s8 = 0.0f;
    #pragma unroll
    for (int i = 0; i < 8; i++) s8 += v[i];
    mean = warpsum(s8) * (1.0f / kD);
    vs = 0.0f;
    #pragma unroll
    for (int i = 0; i < 8; i++) { v[i] -= mean; vs += v[i] * v[i]; }
    rstd = rsqrtf(warpsum(vs) * (1.0f / kD) + EPSL);
    float4* outV = (float4*)(out + OFF_SVAL);
    outV[(size_t)row * 64 + c1] =
        make_float4(v[0] * rstd * gs[0] + bs[0], v[1] * rstd * gs[1] + bs[1],
                    v[2] * rstd * gs[2] + bs[2], v[3] * rstd * gs[3] + bs[3]);
    outV[(size_t)row * 64 + c2] =
        make_float4(v[4] * rstd * gs[4] + bs[4], v[5] * rstd * gs[5] + bs[5],
                    v[6] * rstd * gs[6] + bs[6], v[7] * rstd * gs[7] + bs[7]);
}

// ---------------------------------------------------------------------------
// K3a: single-term bf16 GEMM, 128x64 tile, 3 CTAs/SM. NEW smem-scan epilogue:
// dump biased acc to padded smem tile, 2 threads/row scan 32 cols each with
// running top4, shfl-merge halves. Same (value, lower-index) tie-break.
// ---------------------------------------------------------------------------
#define KC3   64
#define SROW3 72
#define STG3  (192 * SROW3)
#define K3_SMEM (2 * STG3 * (int)sizeof(__nv_bfloat16))

__global__ __launch_bounds__(256, 3) void k3a_gemm(const float* __restrict__ bias)
{
    extern __shared__ __align__(16) __nv_bfloat16 sm3[];
    int tid = threadIdx.x;
    int warp = tid >> 5, lane = tid & 31;
    int mw = warp & 3, nw = warp >> 2;
    int g = lane >> 2, t = lane & 3;
    int m0 = blockIdx.y * 128, n0 = blockIdx.x * 64;

    int a_row = mw * 32 + (lane & 15);
    int a_kh  = ((lane >> 4) & 1) * 8;
    int b_row = 128 + nw * 32 + (lane & 7) + ((lane >> 4) & 1) * 8;
    int b_kh  = ((lane >> 3) & 1) * 8;

    float acc[2][4][4];
    #pragma unroll
    for (int i = 0; i < 2; i++)
        #pragma unroll
        for (int j = 0; j < 4; j++)
            #pragma unroll
            for (int q = 0; q < 4; q++) acc[i][j][q] = 0.0f;

    auto load_stage = [&](int st, int k0) {
        __nv_bfloat16* base = sm3 + st * STG3;
        #pragma unroll
        for (int tt = 0; tt < 6; tt++) {
            int i = tid + tt * 256;
            int r = i >> 3, c16 = i & 7;
            const __nv_bfloat16* src = (r < 128)
                ? g_shi + (size_t)(m0 + r) * kD + k0 + c16 * 8
                : g_wth + (size_t)(n0 + r - 128) * kD + k0 + c16 * 8;
            cpasync16(base + r * SROW3 + c16 * 8, src);
        }
        asm volatile("cp.async.commit_group;");
    };

    load_stage(0, 0);

    #pragma unroll
    for (int ks = 0; ks < kD / KC3; ks++) {
        int st = ks & 1;
        if (ks + 1 < kD / KC3) {
            load_stage(st ^ 1, (ks + 1) * KC3);
            asm volatile("cp.async.wait_group 1;");
        } else {
            asm volatile("cp.async.wait_group 0;");
        }
        __syncthreads();
        __nv_bfloat16* base = sm3 + st * STG3;

        #pragma unroll
        for (int kb = 0; kb < KC3; kb += 16) {
            unsigned ah[2][4];
            #pragma unroll
            for (int mt = 0; mt < 2; mt++)
                ldsm4(ah[mt], base + (a_row + mt * 16) * SROW3 + kb + a_kh);
            #pragma unroll
            for (int p = 0; p < 2; p++) {
                unsigned bh[4];
                ldsm4(bh, base + (b_row + p * 16) * SROW3 + kb + b_kh);
                #pragma unroll
                for (int half = 0; half < 2; half++) {
                    int nt = p * 2 + half;
                    unsigned* bhp = bh + half * 2;
                    #pragma unroll
                    for (int mt = 0; mt < 2; mt++)
                        mma16816(acc[mt][nt], ah[mt], bhp);
                }
            }
        }
        __syncthreads();
    }

    // ---- NEW epilogue: smem scan ----
    float bcol[8];
    #pragma unroll
    for (int nt = 0; nt < 4; nt++) {
        int c = n0 + nw * 32 + nt * 8 + 2 * t;
        bcol[nt * 2]     = bias[c];
        bcol[nt * 2 + 1] = bias[c + 1];
    }

    float* smf = (float*)&sm3[0];          // 128 rows x 65 floats = 33280 B
    #pragma unroll
    for (int mt = 0; mt < 2; mt++) {
        #pragma unroll
        for (int h = 0; h < 2; h++) {
            int rloc = mw * 32 + mt * 16 + h * 8 + g;
            #pragma unroll
            for (int nt = 0; nt < 4; nt++) {
                int cloc = nw * 32 + nt * 8 + 2 * t;
                smf[rloc * 65 + cloc]     = acc[mt][nt][h * 2]     + bcol[nt * 2];
                smf[rloc * 65 + cloc + 1] = acc[mt][nt][h * 2 + 1] + bcol[nt * 2 + 1];
            }
        }
    }
    __syncthreads();

    {
        int rloc = tid >> 1, half = tid & 1;
        int cbase = half * 32;
        const float* rowp = smf + rloc * 65 + cbase;
        float tv[4] = {-INFINITY, -INFINITY, -INFINITY, -INFINITY};
        int   ti[4] = {0x7fffffff, 0x7fffffff, 0x7fffffff, 0x7fffffff};
        #pragma unroll 8
        for (int j = 0; j < 32; j++) ins4(rowp[j], cbase + j, tv, ti);
        // merge with partner (adjacent lane, same warp)
        float pv[4]; int pi[4];
        #pragma unroll
        for (int j = 0; j < 4; j++) {
            pv[j] = __shfl_xor_sync(0xffffffffu, tv[j], 1);
            pi[j] = __shfl_xor_sync(0xffffffffu, ti[j], 1);
        }
        #pragma unroll
        for (int j = 0; j < 4; j++) ins4(pv[j], pi[j], tv, ti);
        if (half == 0) {
            size_t basec = ((size_t)(m0 + rloc) * 8 + blockIdx.x) * 4;
            #pragma unroll
            for (int j = 0; j < 4; j++) {
                g_candV[basec + j] = tv[j];
                g_candI[basec + j] = n0 + ti[j];
            }
        }
    }
}

// ---------------------------------------------------------------------------
// K3b: rescore — merge 32 candidates -> top-8, fp32 exact rescore, top-4,
// softmax, bucket push. Warp per row.
// ---------------------------------------------------------------------------
__global__ __launch_bounds__(256) void k3b_rescore(
    const float* __restrict__ out, const float* __restrict__ bias)
{
    int warp = threadIdx.x >> 5, lane = threadIdx.x & 31;
    int row = blockIdx.x * 8 + warp;
    int b = row >> 13;

    float v = g_candV[(size_t)row * 32 + lane];
    int  ix = g_candI[(size_t)row * 32 + lane];

    int cand8[8];
    #pragma unroll
    for (int r = 0; r < 8; r++) {
        float mv = v; int mi = ix;
        #pragma unroll
        for (int off = 16; off > 0; off >>= 1) {
            float ov = __shfl_xor_sync(0xffffffffu, mv, off);
            int   oi = __shfl_xor_sync(0xffffffffu, mi, off);
            if (bet(ov, oi, mv, mi)) { mv = ov; mi = oi; }
        }
        cand8[r] = mi;
        if (ix == mi) v = -INFINITY;
    }

    const float4* ar = (const float4*)(out + OFF_SSTATE + (size_t)row * kD);
    float4 a0 = ar[lane * 2], a1 = ar[lane * 2 + 1];

    float ex[8];
    #pragma unroll
    for (int r = 0; r < 8; r++) {
        const float4* wr = (const float4*)(g_wtf + (size_t)cand8[r] * kD);
        float4 w0 = wr[lane * 2], w1 = wr[lane * 2 + 1];
        float p = a0.x * w0.x + a0.y * w0.y + a0.z * w0.z + a0.w * w0.w
                + a1.x * w1.x + a1.y * w1.y + a1.z * w1.z + a1.w * w1.w;
        ex[r] = warpsum(p) + bias[cand8[r]];
    }

    float tv[4] = {-INFINITY, -INFINITY, -INFINITY, -INFINITY};
    int   ti[4] = {0x7fffffff, 0x7fffffff, 0x7fffffff, 0x7fffffff};
    #pragma unroll
    for (int r = 0; r < 8; r++) ins4(ex[r], cand8[r], tv, ti);

    float mx = tv[0];
    float e0 = expf(tv[0] - mx), e1 = expf(tv[1] - mx);
    float e2 = expf(tv[2] - mx), e3 = expf(tv[3] - mx);
    float inv = 1.0f / (e0 + e1 + e2 + e3);
    if (lane < 4) {
        float ej = (lane == 0) ? e0 : (lane == 1) ? e1 : (lane == 2) ? e2 : e3;
        float wgt = SC_X * ej * inv;
        int bt = b * kNC + ti[lane];
        int pos = atomicAdd(&g_cnt[bt], 1);
        if (pos < CAP) {
            g_entR[(size_t)bt * CAP + pos] = row;
            g_entW[(size_t)bt * CAP + pos] = wgt;
        }
    }
}

// ---------------------------------------------------------------------------
// K3c: per-(b,target) gather-sum
// ---------------------------------------------------------------------------
__global__ __launch_bounds__(256) void k3c_gather(
    const float* __restrict__ out, const float* __restrict__ ln_b_c)
{
    int bt = blockIdx.x;
    int t = bt & (kNC - 1);
    int sub = threadIdx.x >> 6, c = threadIdx.x & 63;
    int n = min(g_cnt[bt], CAP);
    const float4* ssf = (const float4*)(out + OFF_SSTATE);
    const float4* svf = (const float4*)(out + OFF_SVAL);
    float4 aS = {0,0,0,0}, aV = {0,0,0,0};
    for (int i = sub; i < n; i += 4) {
        int r   = g_entR[(size_t)bt * CAP + i];
        float w = g_entW[(size_t)bt * CAP + i];
        float4 s = ssf[(size_t)r * 64 + c];
        float4 vv = svf[(size_t)r * 64 + c];
        aS.x += w * s.x;  aS.y += w * s.y;  aS.z += w * s.z;  aS.w += w * s.w;
        aV.x += w * vv.x; aV.y += w * vv.y; aV.z += w * vv.z; aV.w += w * vv.w;
    }
    __shared__ float4 shS[4][64], shV[4][64];
    shS[sub][c] = aS; shV[sub][c] = aV;
    __syncthreads();
    if (sub == 0) {
        float4 S = shS[0][c], V = shV[0][c];
        #pragma unroll
        for (int q = 1; q < 4; q++) {
            float4 s2 = shS[q][c], v2 = shV[q][c];
            S.x += s2.x; S.y += s2.y; S.z += s2.z; S.w += s2.w;
            V.x += v2.x; V.y += v2.y; V.z += v2.z; V.w += v2.w;
        }
        ((float4*)g_ncs)[(size_t)bt * 64 + c] = S;
        float4 nb = ((const float4*)ln_b_c)[c];
        V.x += nb.x; V.y += nb.y; V.z += nb.z; V.w += nb.w;
        #pragma unroll
        for (int j = 0; j < 4; j++)
            if (g_ic[j] == t) {
                float w = SC_B * g_wc[j];
                float4 es = ((const float4*)g_esum)[c];
                V.x += w * es.x; V.y += w * es.y; V.z += w * es.z; V.w += w * es.w;
            }
        ((float4*)g_ncv)[(size_t)bt * 64 + c] = V;
    }
}

// ---------------------------------------------------------------------------
// K4a: per-batch scores
// ---------------------------------------------------------------------------
__global__ __launch_bounds__(256) void k4a_scores(const float* __restrict__ wpc)
{
    int bb = blockIdx.z;
    int m0 = blockIdx.y * 64;
    int n0 = blockIdx.x * 64;
    const float* ncs = g_ncs + (size_t)bb * kNC * kD;
    __shared__ float As[16][64 + 4];
    __shared__ float Bs[16][64 + 4];
    int tid = threadIdx.x;
    int ty = tid / 16, tx = tid % 16;
    float acc[4][4] = {};
    int lrow = tid / 4;
    int lk = (tid % 4) * 4;
    for (int k0 = 0; k0 < kD; k0 += 16) {
        float4 av = *(const float4*)&ncs[(size_t)(m0 + lrow) * kD + k0 + lk];
        float4 bv = *(const float4*)&ncs[(size_t)(n0 + lrow) * kD + k0 + lk];
        float4 wv = *(const float4*)&wpc[k0 + lk];
        As[lk + 0][lrow] = av.x * wv.x; As[lk + 1][lrow] = av.y * wv.y;
        As[lk + 2][lrow] = av.z * wv.z; As[lk + 3][lrow] = av.w * wv.w;
        Bs[lk + 0][lrow] = bv.x; Bs[lk + 1][lrow] = bv.y;
        Bs[lk + 2][lrow] = bv.z; Bs[lk + 3][lrow] = bv.w;
        __syncthreads();
        #pragma unroll
        for (int kk = 0; kk < 16; kk++) {
            float ar[4], br[4];
            #pragma unroll
            for (int i = 0; i < 4; i++) ar[i] = As[kk][ty * 4 + i];
            #pragma unroll
            for (int j = 0; j < 4; j++) br[j] = Bs[kk][tx * 4 + j];
            #pragma unroll
            for (int i = 0; i < 4; i++)
                #pragma unroll
                for (int j = 0; j < 4; j++)
                    acc[i][j] += ar[i] * br[j];
        }
        __syncthreads();
    }
    #pragma unroll
    for (int i = 0; i < 4; i++)
        #pragma unroll
        for (int j = 0; j < 4; j++)
            g_scmat[(size_t)bb * kNC * kNC + (size_t)(m0 + ty * 4 + i) * kNC + (n0 + tx * 4 + j)] =
                acc[i][j] * INV_SQRT_D;
}

// ---------------------------------------------------------------------------
// K4b: per-(b,n) top-4 (single-pass + warp merges), softmax, gather,
// tanh/LN finalize with warp-based bsum.
// ---------------------------------------------------------------------------
__global__ __launch_bounds__(256) void k4b_final(
    const float* __restrict__ ln_g_c, const float* __restrict__ ln_b_c,
    float* __restrict__ out)
{
    int bn = blockIdx.x;
    int bb = bn / kNC;
    int d = threadIdx.x;
    int wid = d >> 5, lane = d & 31;
    const float* sc = g_scmat + (size_t)bn * kNC;
    __shared__ float wvv[8][4]; __shared__ int wii[8][4];
    __shared__ float topw[4];   __shared__ int topidx[4];
    __shared__ float red[8];

    float lv[4] = {-INFINITY, -INFINITY, -INFINITY, -INFINITY};
    int   li[4] = {0x7fffffff, 0x7fffffff, 0x7fffffff, 0x7fffffff};
    ins4(sc[d], d, lv, li);
    ins4(sc[d + 256], d + 256, lv, li);
    warpmerge4(lv, li);
    if (lane == 0) {
        #pragma unroll
        for (int j = 0; j < 4; j++) { wvv[wid][j] = lv[j]; wii[wid][j] = li[j]; }
    }
    __syncthreads();
    if (wid == 0) {
        float v = wvv[lane >> 2][lane & 3];
        int  ix = wii[lane >> 2][lane & 3];
        #pragma unroll
        for (int r = 0; r < 4; r++) {
            float mv = v; int mi = ix;
            #pragma unroll
            for (int off = 16; off > 0; off >>= 1) {
                float ov = __shfl_xor_sync(0xffffffffu, mv, off);
                int   oi = __shfl_xor_sync(0xffffffffu, mi, off);
                if (bet(ov, oi, mv, mi)) { mv = ov; mi = oi; }
            }
            if (lane == 0) { topw[r] = mv; topidx[r] = mi; }
            if (ix == mi) v = -INFINITY;
        }
    }
    __syncthreads();

    float mx = topw[0];
    float e[4]; float esum = 0.0f;
    #pragma unroll
    for (int j = 0; j < 4; j++) { e[j] = expf(topw[j] - mx); esum += e[j]; }
    float inv = 1.0f / esum;

    const float* ncsB = g_ncs + (size_t)bb * kNC * kD;
    const float* ncvB = g_ncv + (size_t)bb * kNC * kD;
    float ds = 0.0f, dv = 0.0f;
    #pragma unroll
    for (int j = 0; j < 4; j++) {
        int m = topidx[j];
        float a = e[j] * inv;
        ds += a * ncsB[(size_t)m * kD + d];
        dv += a * ncvB[(size_t)m * kD + d];
    }
    float spre = g_ncs[(size_t)bn * kD + d];
    float vpre = g_ncv[(size_t)bn * kD + d];

    out[OFF_NCS + (size_t)bn * kD + d] = tanhf(spre + SC_B * ds);

    auto bsum = [&](float x) -> float {
        float w = warpsum(x);
        if (lane == 0) red[wid] = w;
        __syncthreads();
        float s = 0.0f;
        #pragma unroll
        for (int i = 0; i < 8; i++) s += red[i];
        __syncthreads();
        return s;
    };
    float x = vpre + SC_B * dv;
    float m = bsum(x) * (1.0f / kD);
    float xd = x - m;
    float var = bsum(xd * xd) * (1.0f / kD);
    out[OFF_NCV + (size_t)bn * kD + d] = xd * rsqrtf(var + EPSL) * ln_g_c[d] + ln_b_c[d];
}

// ---------------------------------------------------------------------------
extern "C" void kernel_launch(void* const* d_in, const int* in_sizes, int n_in,
                              void* d_out, int out_size) {
    const float* s_state  = (const float*)d_in[0];
    const float* s_val    = (const float*)d_in[1];
    const float* w_pair_s = (const float*)d_in[2];
    const float* w_pair_c = (const float*)d_in[4];
    const float* b_expand = (const float*)d_in[6];
    const float* b_b2s    = (const float*)d_in[8];
    const float* b_comp   = (const float*)d_in[10];
    const float* W_s2b    = (const float*)d_in[11];
    const float* b_s2b    = (const float*)d_in[12];
    const float* ln_g_s   = (const float*)d_in[13];
    const float* ln_b_s   = (const float*)d_in[14];
    const float* ln_g_e   = (const float*)d_in[15];
    const float* ln_b_e   = (const float*)d_in[16];
    const float* ln_g_c   = (const float*)d_in[17];
    const float* ln_b_c   = (const float*)d_in[18];
    float* out = (float*)d_out;

    static int smem_set = 0;
    if (!smem_set) {
        cudaFuncSetAttribute(k3a_gemm, cudaFuncAttributeMaxDynamicSharedMemorySize, K3_SMEM);
        smem_set = 1;
    }

    k0_prep<<<1, 256>>>(b_expand, b_b2s, b_comp, ln_b_c, ln_g_e, ln_b_e);
    k1_splitW<<<dim3(kNC / 32, kD / 32), dim3(32, 32)>>>(W_s2b);
    k2_window<<<kM / 8, 256>>>(s_state, s_val, w_pair_s, ln_g_s, ln_b_s, out);
    k3a_gemm<<<dim3(kNC / 64, kM / 128), 256, K3_SMEM>>>(b_s2b);
    k3b_rescore<<<kM / 8, 256>>>(out, b_s2b);
    k3c_gather<<<kB * kNC, 256>>>(out, ln_b_c);
    k4a_scores<<<dim3(kNC / 64, kNC / 64, kB), 256>>>(w_pair_c);
    k4b_final<<<kB * kNC, 256>>>(ln_g_c, ln_b_c, out);
}

// round 15
// speedup vs baseline: 1.2610x; 1.0052x over previous
#include <cuda_runtime.h>
#include <cuda_bf16.h>
#include <math.h>
#include <cstdint>

// ---------------------------------------------------------------------------
#define kD   256
#define kB   4
#define kS   8192
#define kNE  2048
#define kNC  512
#define kWIN 4
#define kM   (kB * kS)

#define S_SC       0.25f
#define SC_B       0.2f
#define SC_X       0.075f
#define EPSL       1e-5f
#define INV_SQRT_D 0.0625f
#define CAP        2048

#define OFF_SSTATE ((size_t)0)
#define OFF_SVAL   ((size_t)kB * kS * kD)
#define OFF_NCS    ((size_t)2 * kB * kS * kD)
#define OFF_NCV    (OFF_NCS + (size_t)kB * kNC * kD)

// ---------------------------------------------------------------------------
__device__ float g_scmat[(size_t)kB * kNC * kNC];
__device__ int   g_entR[(size_t)kB * kNC * CAP];
__device__ float g_entW[(size_t)kB * kNC * CAP];
__device__ int   g_cnt[kB * kNC];
__device__ float g_esum[kD];
__device__ int   g_is[4]; __device__ float g_ws[4];
__device__ int   g_ic[4]; __device__ float g_wc[4];
__device__ float g_ncs[(size_t)kB * kNC * kD];
__device__ float g_ncv[(size_t)kB * kNC * kD];

__device__ __nv_bfloat16 g_shi[(size_t)kM * kD];
__device__ __nv_bfloat16 g_wth[(size_t)kNC * kD];
__device__ float         g_wtf[(size_t)kNC * kD];
__device__ float g_candV[(size_t)kM * 32];
__device__ int   g_candI[(size_t)kM * 32];

__device__ __forceinline__ bool bet(float v, int i, float bv, int bi) {
    return (v > bv) || (v == bv && i < bi);
}

__device__ __forceinline__ float warpsum(float v) {
    #pragma unroll
    for (int off = 16; off > 0; off >>= 1) v += __shfl_xor_sync(0xffffffffu, v, off);
    return v;
}

__device__ __forceinline__ void ins4(float v, int i, float* tv, int* ti) {
    if (bet(v, i, tv[3], ti[3])) {
        tv[3] = v; ti[3] = i;
        #pragma unroll
        for (int q = 3; q > 0; q--) {
            if (bet(tv[q], ti[q], tv[q - 1], ti[q - 1])) {
                float fv = tv[q]; tv[q] = tv[q - 1]; tv[q - 1] = fv;
                int   fi = ti[q]; ti[q] = ti[q - 1]; ti[q - 1] = fi;
            } else break;
        }
    }
}

__device__ __forceinline__ void warpmerge4(float* tv, int* ti) {
    #pragma unroll
    for (int msk = 1; msk <= 16; msk <<= 1) {
        float pv[4]; int pi[4];
        #pragma unroll
        for (int j = 0; j < 4; j++) {
            pv[j] = __shfl_xor_sync(0xffffffffu, tv[j], msk);
            pi[j] = __shfl_xor_sync(0xffffffffu, ti[j], msk);
        }
        #pragma unroll
        for (int j = 0; j < 4; j++) ins4(pv[j], pi[j], tv, ti);
    }
}

__device__ __forceinline__ void mma16816(float* c, const unsigned* a, const unsigned* b) {
    asm volatile(
        "mma.sync.aligned.m16n8k16.row.col.f32.bf16.bf16.f32 "
        "{%0,%1,%2,%3}, {%4,%5,%6,%7}, {%8,%9}, {%0,%1,%2,%3};"
        : "+f"(c[0]), "+f"(c[1]), "+f"(c[2]), "+f"(c[3])
        : "r"(a[0]), "r"(a[1]), "r"(a[2]), "r"(a[3]), "r"(b[0]), "r"(b[1]));
}

__device__ __forceinline__ void ldsm4(unsigned* r, const void* p) {
    unsigned a = (unsigned)__cvta_generic_to_shared(p);
    asm volatile("ldmatrix.sync.aligned.m8n8.x4.shared.b16 {%0,%1,%2,%3}, [%4];"
        : "=r"(r[0]), "=r"(r[1]), "=r"(r[2]), "=r"(r[3]) : "r"(a));
}

__device__ __forceinline__ void cpasync16(void* dst, const void* src) {
    unsigned sd = (unsigned)__cvta_generic_to_shared(dst);
    asm volatile("cp.async.cg.shared.global [%0], [%1], 16;" :: "r"(sd), "l"(src));
}

// ---------------------------------------------------------------------------
// K0: prep (unchanged from R14)
// ---------------------------------------------------------------------------
__global__ __launch_bounds__(256) void k0_prep(
    const float* __restrict__ b_expand, const float* __restrict__ b_b2s,
    const float* __restrict__ b_comp,   const float* __restrict__ ln_b_c,
    const float* __restrict__ ln_g_e,   const float* __restrict__ ln_b_e)
{
    __shared__ float wvv[8][4]; __shared__ int wii[8][4];
    __shared__ float tv[4];     __shared__ int ti[4];
    __shared__ float we[4];     __shared__ int ie[4];
    __shared__ float red[8];
    int tid = threadIdx.x;
    int wid = tid >> 5, lane = tid & 31;

    for (int j = tid; j < kB * kNC; j += 256) g_cnt[j] = 0;

    auto top4 = [&](const float* x, int n) {
        float lv[4] = {-INFINITY, -INFINITY, -INFINITY, -INFINITY};
        int   li[4] = {0x7fffffff, 0x7fffffff, 0x7fffffff, 0x7fffffff};
        for (int j = tid; j < n; j += 256) ins4(x[j], j, lv, li);
        warpmerge4(lv, li);
        if (lane == 0) {
            #pragma unroll
            for (int j = 0; j < 4; j++) { wvv[wid][j] = lv[j]; wii[wid][j] = li[j]; }
        }
        __syncthreads();
        if (wid == 0) {
            float v = wvv[lane >> 2][lane & 3];
            int  ix = wii[lane >> 2][lane & 3];
            #pragma unroll
            for (int r = 0; r < 4; r++) {
                float mv = v; int mi = ix;
                #pragma unroll
                for (int off = 16; off > 0; off >>= 1) {
                    float ov = __shfl_xor_sync(0xffffffffu, mv, off);
                    int   oi = __shfl_xor_sync(0xffffffffu, mi, off);
                    if (bet(ov, oi, mv, mi)) { mv = ov; mi = oi; }
                }
                if (lane == 0) { tv[r] = mv; ti[r] = mi; }
                if (ix == mi) v = -INFINITY;
            }
        }
        __syncthreads();
    };
    auto softmax4 = [&](float* wout) {
        if (tid == 0) {
            float m = tv[0];
            float e0 = expf(tv[0] - m), e1 = expf(tv[1] - m);
            float e2 = expf(tv[2] - m), e3 = expf(tv[3] - m);
            float inv = 1.0f / (e0 + e1 + e2 + e3);
            wout[0] = e0 * inv; wout[1] = e1 * inv;
            wout[2] = e2 * inv; wout[3] = e3 * inv;
        }
        __syncthreads();
    };

    top4(b_expand, kNE); softmax4(we);
    if (tid < 4) ie[tid] = ti[tid];
    __syncthreads();
    top4(b_b2s, kS); softmax4(g_ws);
    if (tid < 4) g_is[tid] = ti[tid];
    __syncthreads();
    top4(b_comp, kNC); softmax4(g_wc);
    if (tid < 4) g_ic[tid] = ti[tid];
    __syncthreads();

    int d = tid;
    float cval = ln_b_c[d];
    float rowval[4];
    float dvE = 0.0f;
    #pragma unroll
    for (int j = 0; j < 4; j++) {
        rowval[j] = SC_B * (float)kNC * we[j] * cval;
        if (ie[j] < 4) dvE += rowval[j];
    }
    dvE *= 0.25f;
    float base = SC_B * dvE;

    auto bsum = [&](float x) -> float {
        float w = warpsum(x);
        if (lane == 0) red[wid] = w;
        __syncthreads();
        float s = 0.0f;
        #pragma unroll
        for (int i = 0; i < 8; i++) s += red[i];
        __syncthreads();
        return s;
    };
    float ge = ln_g_e[d], be = ln_b_e[d];
    auto LN_e = [&](float x) -> float {
        float m  = bsum(x) * (1.0f / kD);
        float dv = x - m;
        float var = bsum(dv * dv) * (1.0f / kD);
        return dv * rsqrtf(var + EPSL) * ge + be;
    };

    float other = LN_e(base);
    float esum = (float)(kNE - 4) * other;
    #pragma unroll
    for (int j = 0; j < 4; j++) esum += LN_e(rowval[j] + base);
    g_esum[d] = esum;
}

// ---------------------------------------------------------------------------
// K1: W_s2b -> transposed bf16 + fp32 copies (unchanged)
// ---------------------------------------------------------------------------
__global__ void k1_splitW(const float* __restrict__ W)
{
    __shared__ float tile[32][33];
    int n0 = blockIdx.x * 32, k0 = blockIdx.y * 32;
    int tx = threadIdx.x, ty = threadIdx.y;
    tile[ty][tx] = W[(size_t)(k0 + ty) * kNC + n0 + tx];
    __syncthreads();
    float x = tile[tx][ty];
    g_wth[(size_t)(n0 + ty) * kD + k0 + tx] = __float2bfloat16(x);
    g_wtf[(size_t)(n0 + ty) * kD + k0 + tx] = x;
}

// ---------------------------------------------------------------------------
// K2: smem-tiled window prop, 16 rows/block (24 slots), 512 threads.
// Read amplification 1.5x (was 2.0x). Warp w handles row row0+w.
// ---------------------------------------------------------------------------
__global__ __launch_bounds__(512) void k2_window(
    const float* __restrict__ s_state, const float* __restrict__ s_val,
    const float* __restrict__ w_pair_s,
    const float* __restrict__ ln_g_s, const float* __restrict__ ln_b_s,
    float* __restrict__ out)
{
    __shared__ float4 st_s[24][64];
    __shared__ float4 vl_s[24][64];

    int tid = threadIdx.x;
    int warp = tid >> 5, lane = tid & 31;
    int row0 = blockIdx.x * 16;
    int b = row0 >> 13, n0 = row0 & (kS - 1);
    const float4* st4 = (const float4*)(s_state + (size_t)b * kS * kD);
    const float4* vl4 = (const float4*)(s_val   + (size_t)b * kS * kD);

    // cooperative tile load: 2 arrays x 24 slots x 64 float4 = 3072
    #pragma unroll
    for (int t = 0; t < 6; t++) {
        int i = tid + t * 512;
        int arr = i / 1536, rem = i % 1536;
        int slot = rem >> 6, c = rem & 63;
        int gr = min(max(n0 - 4 + slot, 0), kS - 1);
        float4 v = (arr ? vl4 : st4)[(size_t)gr * 64 + c];
        if (arr) vl_s[slot][c] = v; else st_s[slot][c] = v;
    }
    __syncthreads();

    int n = n0 + warp;
    int row = row0 + warp;
    int c1 = lane, c2 = lane + 32;

    float4 w0 = ((const float4*)w_pair_s)[c1];
    float4 w1 = ((const float4*)w_pair_s)[c2];
    float4 s0a = st_s[warp + 4][c1];
    float4 s0b = st_s[warp + 4][c2];
    float4 q0, q1;
    q0.x = s0a.x * w0.x; q0.y = s0a.y * w0.y; q0.z = s0a.z * w0.z; q0.w = s0a.w * w0.w;
    q1.x = s0b.x * w1.x; q1.y = s0b.y * w1.y; q1.z = s0b.z * w1.z; q1.w = s0b.w * w1.w;

    float scw[9];
    #pragma unroll
    for (int k = 0; k < 9; k++) {
        int j = n + k - kWIN;
        bool valid = ((unsigned)j < (unsigned)kS);
        float4 na = st_s[warp + k][c1];
        float4 nb = st_s[warp + k][c2];
        float p = q0.x * na.x + q0.y * na.y + q0.z * na.z + q0.w * na.w
                + q1.x * nb.x + q1.y * nb.y + q1.z * nb.z + q1.w * nb.w;
        p = warpsum(p);
        scw[k] = valid ? p * INV_SQRT_D : -1e30f;
    }
    float mx = scw[0];
    #pragma unroll
    for (int k = 1; k < 9; k++) mx = fmaxf(mx, scw[k]);
    float asum = 0.0f;
    #pragma unroll
    for (int k = 0; k < 9; k++) { scw[k] = expf(scw[k] - mx); asum += scw[k]; }
    float ainv = 1.0f / asum;

    float4 ds0 = {0,0,0,0}, ds1 = {0,0,0,0}, dv0 = {0,0,0,0}, dv1 = {0,0,0,0};
    #pragma unroll
    for (int k = 0; k < 9; k++) {
        float a = scw[k] * ainv;
        float4 na = st_s[warp + k][c1];
        float4 nb = st_s[warp + k][c2];
        float4 va = vl_s[warp + k][c1];
        float4 vb = vl_s[warp + k][c2];
        ds0.x += a * na.x; ds0.y += a * na.y; ds0.z += a * na.z; ds0.w += a * na.w;
        ds1.x += a * nb.x; ds1.y += a * nb.y; ds1.z += a * nb.z; ds1.w += a * nb.w;
        dv0.x += a * va.x; dv0.y += a * va.y; dv0.z += a * va.z; dv0.w += a * va.w;
        dv1.x += a * vb.x; dv1.y += a * vb.y; dv1.z += a * vb.z; dv1.w += a * vb.w;
    }

    float sv0[8] = {s0a.x, s0a.y, s0a.z, s0a.w, s0b.x, s0b.y, s0b.z, s0b.w};
    float dss[8] = {ds0.x, ds0.y, ds0.z, ds0.w, ds1.x, ds1.y, ds1.z, ds1.w};
    float sq[8];
    #pragma unroll
    for (int i = 0; i < 8; i++) sq[i] = tanhf(tanhf(sv0[i] + S_SC * dss[i]));

    float4* outS = (float4*)(out + OFF_SSTATE);
    outS[(size_t)row * 64 + c1] = make_float4(sq[0], sq[1], sq[2], sq[3]);
    outS[(size_t)row * 64 + c2] = make_float4(sq[4], sq[5], sq[6], sq[7]);

    unsigned hw1[2], hw2[2];
    #pragma unroll
    for (int i = 0; i < 2; i++) {
        __nv_bfloat16 ha = __float2bfloat16(sq[2 * i]);
        __nv_bfloat16 hc = __float2bfloat16(sq[2 * i + 1]);
        hw1[i] = ((unsigned)__bfloat16_as_ushort(hc) << 16) | __bfloat16_as_ushort(ha);
        __nv_bfloat16 hb = __float2bfloat16(sq[4 + 2 * i]);
        __nv_bfloat16 hd = __float2bfloat16(sq[4 + 2 * i + 1]);
        hw2[i] = ((unsigned)__bfloat16_as_ushort(hd) << 16) | __bfloat16_as_ushort(hb);
    }
    *(uint2*)&g_shi[(size_t)row * kD + lane * 4]       = make_uint2(hw1[0], hw1[1]);
    *(uint2*)&g_shi[(size_t)row * kD + 128 + lane * 4] = make_uint2(hw2[0], hw2[1]);

    float4 va0 = vl_s[warp + 4][c1];
    float4 va1 = vl_s[warp + 4][c2];
    float v[8];
    v[0] = va0.x + S_SC * dv0.x; v[1] = va0.y + S_SC * dv0.y;
    v[2] = va0.z + S_SC * dv0.z; v[3] = va0.w + S_SC * dv0.w;
    v[4] = va1.x + S_SC * dv1.x; v[5] = va1.y + S_SC * dv1.y;
    v[6] = va1.z + S_SC * dv1.z; v[7] = va1.w + S_SC * dv1.w;

    float4 g0 = ((const float4*)ln_g_s)[c1], g1 = ((const float4*)ln_g_s)[c2];
    float4 b0v = ((const float4*)ln_b_s)[c1], b1v = ((const float4*)ln_b_s)[c2];
    float gs[8] = {g0.x, g0.y, g0.z, g0.w, g1.x, g1.y, g1.z, g1.w};
    float bs[8] = {b0v.x, b0v.y, b0v.z, b0v.w, b1v.x, b1v.y, b1v.z, b1v.w};

    float s8 = 0.0f;
    #pragma unroll
    for (int i = 0; i < 8; i++) s8 += v[i];
    float mean = warpsum(s8) * (1.0f / kD);
    float vs = 0.0f;
    #pragma unroll
    for (int i = 0; i < 8; i++) { v[i] -= mean; vs += v[i] * v[i]; }
    float rstd = rsqrtf(warpsum(vs) * (1.0f / kD) + EPSL);
    #pragma unroll
    for (int i = 0; i < 8; i++) v[i] = v[i] * rstd * gs[i] + bs[i];

    bool hit = false; float wj = 0.0f;
    #pragma unroll
    for (int j = 0; j < 4; j++)
        if (g_is[j] == n) { hit = true; wj = g_ws[j]; }
    if (hit) {
        float4 e0 = ((const float4*)g_esum)[c1], e1 = ((const float4*)g_esum)[c2];
        float es[8] = {e0.x, e0.y, e0.z, e0.w, e1.x, e1.y, e1.z, e1.w};
        #pragma unroll
        for (int i = 0; i < 8; i++) v[i] += SC_X * wj * es[i];
    }

    s8 = 0.0f;
    #pragma unroll
    for (int i = 0; i < 8; i++) s8 += v[i];
    mean = warpsum(s8) * (1.0f / kD);
    vs = 0.0f;
    #pragma unroll
    for (int i = 0; i < 8; i++) { v[i] -= mean; vs += v[i] * v[i]; }
    rstd = rsqrtf(warpsum(vs) * (1.0f / kD) + EPSL);
    float4* outV = (float4*)(out + OFF_SVAL);
    outV[(size_t)row * 64 + c1] =
        make_float4(v[0] * rstd * gs[0] + bs[0], v[1] * rstd * gs[1] + bs[1],
                    v[2] * rstd * gs[2] + bs[2], v[3] * rstd * gs[3] + bs[3]);
    outV[(size_t)row * 64 + c2] =
        make_float4(v[4] * rstd * gs[4] + bs[4], v[5] * rstd * gs[5] + bs[5],
                    v[6] * rstd * gs[6] + bs[6], v[7] * rstd * gs[7] + bs[7]);
}

// ---------------------------------------------------------------------------
// K3a: single-term bf16 GEMM + smem-scan epilogue (unchanged from R14)
// ---------------------------------------------------------------------------
#define KC3   64
#define SROW3 72
#define STG3  (192 * SROW3)
#define K3_SMEM (2 * STG3 * (int)sizeof(__nv_bfloat16))

__global__ __launch_bounds__(256, 3) void k3a_gemm(const float* __restrict__ bias)
{
    extern __shared__ __align__(16) __nv_bfloat16 sm3[];
    int tid = threadIdx.x;
    int warp = tid >> 5, lane = tid & 31;
    int mw = warp & 3, nw = warp >> 2;
    int g = lane >> 2, t = lane & 3;
    int m0 = blockIdx.y * 128, n0 = blockIdx.x * 64;

    int a_row = mw * 32 + (lane & 15);
    int a_kh  = ((lane >> 4) & 1) * 8;
    int b_row = 128 + nw * 32 + (lane & 7) + ((lane >> 4) & 1) * 8;
    int b_kh  = ((lane >> 3) & 1) * 8;

    float acc[2][4][4];
    #pragma unroll
    for (int i = 0; i < 2; i++)
        #pragma unroll
        for (int j = 0; j < 4; j++)
            #pragma unroll
            for (int q = 0; q < 4; q++) acc[i][j][q] = 0.0f;

    auto load_stage = [&](int st, int k0) {
        __nv_bfloat16* base = sm3 + st * STG3;
        #pragma unroll
        for (int tt = 0; tt < 6; tt++) {
            int i = tid + tt * 256;
            int r = i >> 3, c16 = i & 7;
            const __nv_bfloat16* src = (r < 128)
                ? g_shi + (size_t)(m0 + r) * kD + k0 + c16 * 8
                : g_wth + (size_t)(n0 + r - 128) * kD + k0 + c16 * 8;
            cpasync16(base + r * SROW3 + c16 * 8, src);
        }
        asm volatile("cp.async.commit_group;");
    };

    load_stage(0, 0);

    #pragma unroll
    for (int ks = 0; ks < kD / KC3; ks++) {
        int st = ks & 1;
        if (ks + 1 < kD / KC3) {
            load_stage(st ^ 1, (ks + 1) * KC3);
            asm volatile("cp.async.wait_group 1;");
        } else {
            asm volatile("cp.async.wait_group 0;");
        }
        __syncthreads();
        __nv_bfloat16* base = sm3 + st * STG3;

        #pragma unroll
        for (int kb = 0; kb < KC3; kb += 16) {
            unsigned ah[2][4];
            #pragma unroll
            for (int mt = 0; mt < 2; mt++)
                ldsm4(ah[mt], base + (a_row + mt * 16) * SROW3 + kb + a_kh);
            #pragma unroll
            for (int p = 0; p < 2; p++) {
                unsigned bh[4];
                ldsm4(bh, base + (b_row + p * 16) * SROW3 + kb + b_kh);
                #pragma unroll
                for (int half = 0; half < 2; half++) {
                    int nt = p * 2 + half;
                    unsigned* bhp = bh + half * 2;
                    #pragma unroll
                    for (int mt = 0; mt < 2; mt++)
                        mma16816(acc[mt][nt], ah[mt], bhp);
                }
            }
        }
        __syncthreads();
    }

    float bcol[8];
    #pragma unroll
    for (int nt = 0; nt < 4; nt++) {
        int c = n0 + nw * 32 + nt * 8 + 2 * t;
        bcol[nt * 2]     = bias[c];
        bcol[nt * 2 + 1] = bias[c + 1];
    }

    float* smf = (float*)&sm3[0];
    #pragma unroll
    for (int mt = 0; mt < 2; mt++) {
        #pragma unroll
        for (int h = 0; h < 2; h++) {
            int rloc = mw * 32 + mt * 16 + h * 8 + g;
            #pragma unroll
            for (int nt = 0; nt < 4; nt++) {
                int cloc = nw * 32 + nt * 8 + 2 * t;
                smf[rloc * 65 + cloc]     = acc[mt][nt][h * 2]     + bcol[nt * 2];
                smf[rloc * 65 + cloc + 1] = acc[mt][nt][h * 2 + 1] + bcol[nt * 2 + 1];
            }
        }
    }
    __syncthreads();

    {
        int rloc = tid >> 1, half = tid & 1;
        int cbase = half * 32;
        const float* rowp = smf + rloc * 65 + cbase;
        float tv[4] = {-INFINITY, -INFINITY, -INFINITY, -INFINITY};
        int   ti[4] = {0x7fffffff, 0x7fffffff, 0x7fffffff, 0x7fffffff};
        #pragma unroll 8
        for (int j = 0; j < 32; j++) ins4(rowp[j], cbase + j, tv, ti);
        float pv[4]; int pi[4];
        #pragma unroll
        for (int j = 0; j < 4; j++) {
            pv[j] = __shfl_xor_sync(0xffffffffu, tv[j], 1);
            pi[j] = __shfl_xor_sync(0xffffffffu, ti[j], 1);
        }
        #pragma unroll
        for (int j = 0; j < 4; j++) ins4(pv[j], pi[j], tv, ti);
        if (half == 0) {
            size_t basec = ((size_t)(m0 + rloc) * 8 + blockIdx.x) * 4;
            #pragma unroll
            for (int j = 0; j < 4; j++) {
                g_candV[basec + j] = tv[j];
                g_candI[basec + j] = n0 + ti[j];
            }
        }
    }
}

// ---------------------------------------------------------------------------
// K3b: rescore (unchanged from R14)
// ---------------------------------------------------------------------------
__global__ __launch_bounds__(256) void k3b_rescore(
    const float* __restrict__ out, const float* __restrict__ bias)
{
    int warp = threadIdx.x >> 5, lane = threadIdx.x & 31;
    int row = blockIdx.x * 8 + warp;
    int b = row >> 13;

    float v = g_candV[(size_t)row * 32 + lane];
    int  ix = g_candI[(size_t)row * 32 + lane];

    int cand8[8];
    #pragma unroll
    for (int r = 0; r < 8; r++) {
        float mv = v; int mi = ix;
        #pragma unroll
        for (int off = 16; off > 0; off >>= 1) {
            float ov = __shfl_xor_sync(0xffffffffu, mv, off);
            int   oi = __shfl_xor_sync(0xffffffffu, mi, off);
            if (bet(ov, oi, mv, mi)) { mv = ov; mi = oi; }
        }
        cand8[r] = mi;
        if (ix == mi) v = -INFINITY;
    }

    const float4* ar = (const float4*)(out + OFF_SSTATE + (size_t)row * kD);
    float4 a0 = ar[lane * 2], a1 = ar[lane * 2 + 1];

    float ex[8];
    #pragma unroll
    for (int r = 0; r < 8; r++) {
        const float4* wr = (const float4*)(g_wtf + (size_t)cand8[r] * kD);
        float4 w0 = wr[lane * 2], w1 = wr[lane * 2 + 1];
        float p = a0.x * w0.x + a0.y * w0.y + a0.z * w0.z + a0.w * w0.w
                + a1.x * w1.x + a1.y * w1.y + a1.z * w1.z + a1.w * w1.w;
        ex[r] = warpsum(p) + bias[cand8[r]];
    }

    float tv[4] = {-INFINITY, -INFINITY, -INFINITY, -INFINITY};
    int   ti[4] = {0x7fffffff, 0x7fffffff, 0x7fffffff, 0x7fffffff};
    #pragma unroll
    for (int r = 0; r < 8; r++) ins4(ex[r], cand8[r], tv, ti);

    float mx = tv[0];
    float e0 = expf(tv[0] - mx), e1 = expf(tv[1] - mx);
    float e2 = expf(tv[2] - mx), e3 = expf(tv[3] - mx);
    float inv = 1.0f / (e0 + e1 + e2 + e3);
    if (lane < 4) {
        float ej = (lane == 0) ? e0 : (lane == 1) ? e1 : (lane == 2) ? e2 : e3;
        float wgt = SC_X * ej * inv;
        int bt = b * kNC + ti[lane];
        int pos = atomicAdd(&g_cnt[bt], 1);
        if (pos < CAP) {
            g_entR[(size_t)bt * CAP + pos] = row;
            g_entW[(size_t)bt * CAP + pos] = wgt;
        }
    }
}

// ---------------------------------------------------------------------------
// K3c: per-(b,target) gather-sum with smem index prefetch (no dependent
// index->row chain: indices staged in smem first).
// ---------------------------------------------------------------------------
__global__ __launch_bounds__(256) void k3c_gather(
    const float* __restrict__ out, const float* __restrict__ ln_b_c)
{
    __shared__ int   sR[CAP];
    __shared__ float sW[CAP];
    int bt = blockIdx.x;
    int t = bt & (kNC - 1);
    int tid = threadIdx.x;
    int sub = tid >> 6, c = tid & 63;
    int n = min(g_cnt[bt], CAP);

    for (int i = tid; i < n; i += 256) {
        sR[i] = g_entR[(size_t)bt * CAP + i];
        sW[i] = g_entW[(size_t)bt * CAP + i];
    }
    __syncthreads();

    const float4* ssf = (const float4*)(out + OFF_SSTATE);
    const float4* svf = (const float4*)(out + OFF_SVAL);
    float4 aS = {0,0,0,0}, aV = {0,0,0,0};
    for (int i = sub; i < n; i += 4) {
        int r   = sR[i];
        float w = sW[i];
        float4 s = ssf[(size_t)r * 64 + c];
        float4 vv = svf[(size_t)r * 64 + c];
        aS.x += w * s.x;  aS.y += w * s.y;  aS.z += w * s.z;  aS.w += w * s.w;
        aV.x += w * vv.x; aV.y += w * vv.y; aV.z += w * vv.z; aV.w += w * vv.w;
    }
    __shared__ float4 shS[4][64], shV[4][64];
    shS[sub][c] = aS; shV[sub][c] = aV;
    __syncthreads();
    if (sub == 0) {
        float4 S = shS[0][c], V = shV[0][c];
        #pragma unroll
        for (int q = 1; q < 4; q++) {
            float4 s2 = shS[q][c], v2 = shV[q][c];
            S.x += s2.x; S.y += s2.y; S.z += s2.z; S.w += s2.w;
            V.x += v2.x; V.y += v2.y; V.z += v2.z; V.w += v2.w;
        }
        ((float4*)g_ncs)[(size_t)bt * 64 + c] = S;
        float4 nb = ((const float4*)ln_b_c)[c];
        V.x += nb.x; V.y += nb.y; V.z += nb.z; V.w += nb.w;
        #pragma unroll
        for (int j = 0; j < 4; j++)
            if (g_ic[j] == t) {
                float w = SC_B * g_wc[j];
                float4 es = ((const float4*)g_esum)[c];
                V.x += w * es.x; V.y += w * es.y; V.z += w * es.z; V.w += w * es.w;
            }
        ((float4*)g_ncv)[(size_t)bt * 64 + c] = V;
    }
}

// ---------------------------------------------------------------------------
// K4a: per-batch scores (unchanged)
// ---------------------------------------------------------------------------
__global__ __launch_bounds__(256) void k4a_scores(const float* __restrict__ wpc)
{
    int bb = blockIdx.z;
    int m0 = blockIdx.y * 64;
    int n0 = blockIdx.x * 64;
    const float* ncs = g_ncs + (size_t)bb * kNC * kD;
    __shared__ float As[16][64 + 4];
    __shared__ float Bs[16][64 + 4];
    int tid = threadIdx.x;
    int ty = tid / 16, tx = tid % 16;
    float acc[4][4] = {};
    int lrow = tid / 4;
    int lk = (tid % 4) * 4;
    for (int k0 = 0; k0 < kD; k0 += 16) {
        float4 av = *(const float4*)&ncs[(size_t)(m0 + lrow) * kD + k0 + lk];
        float4 bv = *(const float4*)&ncs[(size_t)(n0 + lrow) * kD + k0 + lk];
        float4 wv = *(const float4*)&wpc[k0 + lk];
        As[lk + 0][lrow] = av.x * wv.x; As[lk + 1][lrow] = av.y * wv.y;
        As[lk + 2][lrow] = av.z * wv.z; As[lk + 3][lrow] = av.w * wv.w;
        Bs[lk + 0][lrow] = bv.x; Bs[lk + 1][lrow] = bv.y;
        Bs[lk + 2][lrow] = bv.z; Bs[lk + 3][lrow] = bv.w;
        __syncthreads();
        #pragma unroll
        for (int kk = 0; kk < 16; kk++) {
            float ar[4], br[4];
            #pragma unroll
            for (int i = 0; i < 4; i++) ar[i] = As[kk][ty * 4 + i];
            #pragma unroll
            for (int j = 0; j < 4; j++) br[j] = Bs[kk][tx * 4 + j];
            #pragma unroll
            for (int i = 0; i < 4; i++)
                #pragma unroll
                for (int j = 0; j < 4; j++)
                    acc[i][j] += ar[i] * br[j];
        }
        __syncthreads();
    }
    #pragma unroll
    for (int i = 0; i < 4; i++)
        #pragma unroll
        for (int j = 0; j < 4; j++)
            g_scmat[(size_t)bb * kNC * kNC + (size_t)(m0 + ty * 4 + i) * kNC + (n0 + tx * 4 + j)] =
                acc[i][j] * INV_SQRT_D;
}

// ---------------------------------------------------------------------------
// K4b: per-(b,n) top-4 + tanh/LN finalize (unchanged)
// ---------------------------------------------------------------------------
__global__ __launch_bounds__(256) void k4b_final(
    const float* __restrict__ ln_g_c, const float* __restrict__ ln_b_c,
    float* __restrict__ out)
{
    int bn = blockIdx.x;
    int bb = bn / kNC;
    int d = threadIdx.x;
    int wid = d >> 5, lane = d & 31;
    const float* sc = g_scmat + (size_t)bn * kNC;
    __shared__ float wvv[8][4]; __shared__ int wii[8][4];
    __shared__ float topw[4];   __shared__ int topidx[4];
    __shared__ float red[8];

    float lv[4] = {-INFINITY, -INFINITY, -INFINITY, -INFINITY};
    int   li[4] = {0x7fffffff, 0x7fffffff, 0x7fffffff, 0x7fffffff};
    ins4(sc[d], d, lv, li);
    ins4(sc[d + 256], d + 256, lv, li);
    warpmerge4(lv, li);
    if (lane == 0) {
        #pragma unroll
        for (int j = 0; j < 4; j++) { wvv[wid][j] = lv[j]; wii[wid][j] = li[j]; }
    }
    __syncthreads();
    if (wid == 0) {
        float v = wvv[lane >> 2][lane & 3];
        int  ix = wii[lane >> 2][lane & 3];
        #pragma unroll
        for (int r = 0; r < 4; r++) {
            float mv = v; int mi = ix;
            #pragma unroll
            for (int off = 16; off > 0; off >>= 1) {
                float ov = __shfl_xor_sync(0xffffffffu, mv, off);
                int   oi = __shfl_xor_sync(0xffffffffu, mi, off);
                if (bet(ov, oi, mv, mi)) { mv = ov; mi = oi; }
            }
            if (lane == 0) { topw[r] = mv; topidx[r] = mi; }
            if (ix == mi) v = -INFINITY;
        }
    }
    __syncthreads();

    float mx = topw[0];
    float e[4]; float esum = 0.0f;
    #pragma unroll
    for (int j = 0; j < 4; j++) { e[j] = expf(topw[j] - mx); esum += e[j]; }
    float inv = 1.0f / esum;

    const float* ncsB = g_ncs + (size_t)bb * kNC * kD;
    const float* ncvB = g_ncv + (size_t)bb * kNC * kD;
    float ds = 0.0f, dv = 0.0f;
    #pragma unroll
    for (int j = 0; j < 4; j++) {
        int m = topidx[j];
        float a = e[j] * inv;
        ds += a * ncsB[(size_t)m * kD + d];
        dv += a * ncvB[(size_t)m * kD + d];
    }
    float spre = g_ncs[(size_t)bn * kD + d];
    float vpre = g_ncv[(size_t)bn * kD + d];

    out[OFF_NCS + (size_t)bn * kD + d] = tanhf(spre + SC_B * ds);

    auto bsum = [&](float x) -> float {
        float w = warpsum(x);
        if (lane == 0) red[wid] = w;
        __syncthreads();
        float s = 0.0f;
        #pragma unroll
        for (int i = 0; i < 8; i++) s += red[i];
        __syncthreads();
        return s;
    };
    float x = vpre + SC_B * dv;
    float m = bsum(x) * (1.0f / kD);
    float xd = x - m;
    float var = bsum(xd * xd) * (1.0f / kD);
    out[OFF_NCV + (size_t)bn * kD + d] = xd * rsqrtf(var + EPSL) * ln_g_c[d] + ln_b_c[d];
}

// ---------------------------------------------------------------------------
extern "C" void kernel_launch(void* const* d_in, const int* in_sizes, int n_in,
                              void* d_out, int out_size) {
    const float* s_state  = (const float*)d_in[0];
    const float* s_val    = (const float*)d_in[1];
    const float* w_pair_s = (const float*)d_in[2];
    const float* w_pair_c = (const float*)d_in[4];
    const float* b_expand = (const float*)d_in[6];
    const float* b_b2s    = (const float*)d_in[8];
    const float* b_comp   = (const float*)d_in[10];
    const float* W_s2b    = (const float*)d_in[11];
    const float* b_s2b    = (const float*)d_in[12];
    const float* ln_g_s   = (const float*)d_in[13];
    const float* ln_b_s   = (const float*)d_in[14];
    const float* ln_g_e   = (const float*)d_in[15];
    const float* ln_b_e   = (const float*)d_in[16];
    const float* ln_g_c   = (const float*)d_in[17];
    const float* ln_b_c   = (const float*)d_in[18];
    float* out = (float*)d_out;

    static int smem_set = 0;
    if (!smem_set) {
        cudaFuncSetAttribute(k3a_gemm, cudaFuncAttributeMaxDynamicSharedMemorySize, K3_SMEM);
        smem_set = 1;
    }

    k0_prep<<<1, 256>>>(b_expand, b_b2s, b_comp, ln_b_c, ln_g_e, ln_b_e);
    k1_splitW<<<dim3(kNC / 32, kD / 32), dim3(32, 32)>>>(W_s2b);
    k2_window<<<kM / 16, 512>>>(s_state, s_val, w_pair_s, ln_g_s, ln_b_s, out);
    k3a_gemm<<<dim3(kNC / 64, kM / 128), 256, K3_SMEM>>>(b_s2b);
    k3b_rescore<<<kM / 8, 256>>>(out, b_s2b);
    k3c_gather<<<kB * kNC, 256>>>(out, ln_b_c);
    k4a_scores<<<dim3(kNC / 64, kNC / 64, kB), 256>>>(w_pair_c);
    k4b_final<<<kB * kNC, 256>>>(ln_g_c, ln_b_c, out);
}